// round 6
// baseline (speedup 1.0000x reference)
#include <cuda_runtime.h>
#include <cuda_bf16.h>
#include <math.h>
#include <stdint.h>

#define T_STEPS 8
#define NN      10000
#define EE      200000
#define FIN     32
#define HID     128
#define OUTD    64
#define G4      256            // 4*OUT
#define MROWS   (T_STEPS*NN)   // 80000
#define EPSBN   1e-5f

// weight-plane offsets ([n][k] bf16 layout, packed)
#define WO0 0            // wg0^T   128x32
#define WO1 4096         // wg1^T   128x128
#define WO2 20480        // wg2^T   128x128
#define WO3 36864        // w_ih0   256x128
#define WO4 69632        // w_ih1   256x64
#define WO5 86016        // w_ih2   256x64
#define WH0 102400       // whh0    256x64
#define WH1 118784       // whh1    256x64
#define WH2 135168       // whh2    256x64
#define WTOT 151552
#define PREP_ELEMS (WTOT + 768)

// ===================== scratch (device globals) =====================
static __device__ float g_h  [MROWS*HID];      // GCN0/1 outputs (fp32, agg input)
static __device__ float g_pre[MROWS*G4];       // LSTM input projections
static __device__ __nv_bfloat16 g_aHi[MROWS*HID], g_aLo[MROWS*HID];   // agg out planes
static __device__ __nv_bfloat16 g_hHi[MROWS*HID], g_hLo[MROWS*HID];   // GCN2 out planes
static __device__ __nv_bfloat16 g_yAHi[MROWS*OUTD], g_yALo[MROWS*OUTD];
static __device__ __nv_bfloat16 g_yBHi[MROWS*OUTD], g_yBLo[MROWS*OUTD];
static __device__ __nv_bfloat16 g_wHi[WTOT], g_wLo[WTOT];
static __device__ float g_biasc[3*G4];
static __device__ float g_dis[NN];
static __device__ int   g_cnt[NN];
static __device__ int   g_rowptr[NN+1];
static __device__ int   g_cursor[NN];
static __device__ int   g_csr_src[EE];
static __device__ float g_csr_coef[EE];

// ===================== helpers =====================
__device__ __forceinline__ uint32_t smem_u32(const void* p) {
    uint32_t a;
    asm("{ .reg .u64 t; cvta.to.shared.u64 t, %1; cvt.u32.u64 %0, t; }" : "=r"(a) : "l"(p));
    return a;
}
__device__ __forceinline__ void cp16(uint32_t s, const void* g) {
    asm volatile("cp.async.cg.shared.global [%0], [%1], 16;" :: "r"(s), "l"(g));
}
__device__ __forceinline__ void cp_commit() {
    asm volatile("cp.async.commit_group;");
}
__device__ __forceinline__ void cp_wait0() {
    asm volatile("cp.async.wait_group 0;");
}
__device__ __forceinline__ void ldsm_x4(uint32_t* r, uint32_t addr) {
    asm volatile("ldmatrix.sync.aligned.m8n8.x4.shared.b16 {%0,%1,%2,%3}, [%4];"
                 : "=r"(r[0]), "=r"(r[1]), "=r"(r[2]), "=r"(r[3]) : "r"(addr));
}
__device__ __forceinline__ void mma16816(float* d, const uint32_t* a, const uint32_t* b) {
    asm volatile(
        "mma.sync.aligned.m16n8k16.row.col.f32.bf16.bf16.f32 "
        "{%0,%1,%2,%3}, {%4,%5,%6,%7}, {%8,%9}, {%0,%1,%2,%3};"
        : "+f"(d[0]), "+f"(d[1]), "+f"(d[2]), "+f"(d[3])
        : "r"(a[0]), "r"(a[1]), "r"(a[2]), "r"(a[3]), "r"(b[0]), "r"(b[1]));
}
__device__ __forceinline__ uint32_t pack_hi2(float x, float y) {
    __nv_bfloat162 h = __halves2bfloat162(__float2bfloat16(x), __float2bfloat16(y));
    return *(uint32_t*)&h;
}
__device__ __forceinline__ uint32_t pack_lo2(float x, float y) {
    float hx = __bfloat162float(__float2bfloat16(x));
    float hy = __bfloat162float(__float2bfloat16(y));
    __nv_bfloat162 l = __halves2bfloat162(__float2bfloat16(x - hx), __float2bfloat16(y - hy));
    return *(uint32_t*)&l;
}
__device__ __forceinline__ float sigmoidf_(float x) {
    return 1.0f / (1.0f + __expf(-x));
}
__device__ __forceinline__ float tanhf_(float x) {
    return 1.0f - 2.0f / (__expf(2.0f * x) + 1.0f);
}

// ===================== setup kernels =====================
__global__ void k_zero_cnt() {
    int i = blockIdx.x * blockDim.x + threadIdx.x;
    if (i < NN) g_cnt[i] = 0;
}
__global__ void k_hist(const int* __restrict__ dst) {
    int e = blockIdx.x * blockDim.x + threadIdx.x;
    if (e < EE) atomicAdd(&g_cnt[dst[e]], 1);
}
__global__ void k_scanfused() {
    const int TPB = 1024, PER = 10;
    __shared__ int sh[TPB];
    int tid = threadIdx.x;
    for (int i = tid; i < NN; i += TPB) g_dis[i] = rsqrtf((float)g_cnt[i] + 1.0f);
    int base = tid * PER;
    int loc[PER];
    int s = 0;
#pragma unroll
    for (int i = 0; i < PER; i++) {
        int idx = base + i;
        int v = (idx < NN) ? g_cnt[idx] : 0;
        loc[i] = s; s += v;
    }
    sh[tid] = s; __syncthreads();
    for (int off = 1; off < TPB; off <<= 1) {
        int v = (tid >= off) ? sh[tid - off] : 0;
        __syncthreads();
        sh[tid] += v;
        __syncthreads();
    }
    int excl = (tid == 0) ? 0 : sh[tid - 1];
#pragma unroll
    for (int i = 0; i < PER; i++) {
        int idx = base + i;
        if (idx <= NN) g_rowptr[idx] = excl + loc[i];
    }
    __syncthreads();
    for (int i = tid; i < NN; i += TPB) g_cursor[i] = g_rowptr[i];
}

#define FILL_BLOCKS ((EE + 255) / 256)
#define PREP_BLOCKS ((PREP_ELEMS + 255) / 256)
__global__ void k_fillprep(const int* __restrict__ src, const int* __restrict__ dst,
                           const float* __restrict__ wg0, const float* __restrict__ wg1,
                           const float* __restrict__ wg2,
                           const float* __restrict__ wih0, const float* __restrict__ wih1,
                           const float* __restrict__ wih2,
                           const float* __restrict__ whh0, const float* __restrict__ whh1,
                           const float* __restrict__ whh2,
                           const float* __restrict__ bih0, const float* __restrict__ bhh0,
                           const float* __restrict__ bih1, const float* __restrict__ bhh1,
                           const float* __restrict__ bih2, const float* __restrict__ bhh2) {
    int b = blockIdx.x;
    int tid = threadIdx.x;
    if (b < FILL_BLOCKS) {
        int e = b * 256 + tid;
        if (e < EE) {
            int s = src[e], d = dst[e];
            int p = atomicAdd(&g_cursor[d], 1);
            g_csr_src[p]  = s;
            g_csr_coef[p] = g_dis[s] * g_dis[d];
        }
        return;
    }
    int idx = (b - FILL_BLOCKS) * 256 + tid;
    if (idx >= PREP_ELEMS) return;
    if (idx < WTOT) {
        float v;
        if (idx < WO1)       { int r = idx - WO0; v = wg0[(r & 31)  * HID + (r >> 5)]; }
        else if (idx < WO2)  { int r = idx - WO1; v = wg1[(r & 127) * HID + (r >> 7)]; }
        else if (idx < WO3)  { int r = idx - WO2; v = wg2[(r & 127) * HID + (r >> 7)]; }
        else if (idx < WO4)  { v = wih0[idx - WO3]; }
        else if (idx < WO5)  { v = wih1[idx - WO4]; }
        else if (idx < WH0)  { v = wih2[idx - WO5]; }
        else if (idx < WH1)  { v = whh0[idx - WH0]; }
        else if (idx < WH2)  { v = whh1[idx - WH1]; }
        else                 { v = whh2[idx - WH2]; }
        __nv_bfloat16 h = __float2bfloat16(v);
        g_wHi[idx] = h;
        g_wLo[idx] = __float2bfloat16(v - __bfloat162float(h));
    } else {
        int r = idx - WTOT;
        int l = r >> 8, i = r & 255;
        const float* a = (l == 0) ? bih0 : (l == 1) ? bih1 : bih2;
        const float* c = (l == 0) ? bhh0 : (l == 1) ? bhh1 : bhh2;
        g_biasc[r] = a[i] + c[i];
    }
}

// ===================== GCN aggregation (emits bf16 hi/lo planes) =============
template <int F>
__global__ void k_agg(const float* __restrict__ in,
                      __nv_bfloat16* __restrict__ oHi, __nv_bfloat16* __restrict__ oLo) {
    int n = blockIdx.x;
    int t = threadIdx.x >> 5;
    int lane = threadIdx.x & 31;
    int p0 = g_rowptr[n], p1 = g_rowptr[n + 1];
    float d = g_dis[n];
    float sw = d * d;
    size_t m = (size_t)t * NN + n;
    if (F == 128) {
        int c0 = lane * 4;
        float4 acc = make_float4(0.f, 0.f, 0.f, 0.f);
        for (int p = p0; p < p1; p++) {
            int s = g_csr_src[p];
            float cf = g_csr_coef[p];
            float4 v = *(const float4*)(in + ((size_t)t * NN + s) * F + c0);
            acc.x += v.x * cf; acc.y += v.y * cf;
            acc.z += v.z * cf; acc.w += v.w * cf;
        }
        float4 hv = *(const float4*)(in + m * F + c0);
        float o0 = acc.x + hv.x * sw, o1 = acc.y + hv.y * sw;
        float o2 = acc.z + hv.z * sw, o3 = acc.w + hv.w * sw;
        uint2 hi = make_uint2(pack_hi2(o0, o1), pack_hi2(o2, o3));
        uint2 lo = make_uint2(pack_lo2(o0, o1), pack_lo2(o2, o3));
        *(uint2*)(oHi + m * F + c0) = hi;
        *(uint2*)(oLo + m * F + c0) = lo;
    } else {  // F == 32
        float acc = 0.0f;
        for (int p = p0; p < p1; p++) {
            int s = g_csr_src[p];
            acc += in[((size_t)t * NN + s) * F + lane] * g_csr_coef[p];
        }
        float r = acc + in[m * F + lane] * sw;
        __nv_bfloat16 h = __float2bfloat16(r);
        oHi[m * F + lane] = h;
        oLo[m * F + lane] = __float2bfloat16(r - __bfloat162float(h));
    }
}

// ===================== mma.sync bf16x3 GEMM (K-chunked, 2 CTA/SM) ===========
template <int K>
__global__ void __launch_bounds__(256, 2)
k_gemm_mma(const __nv_bfloat16* __restrict__ Ahi, const __nv_bfloat16* __restrict__ Alo,
           const __nv_bfloat16* __restrict__ Whi, const __nv_bfloat16* __restrict__ Wlo,
           const float* __restrict__ bias,
           const float* __restrict__ bng, const float* __restrict__ bnb,
           const float* __restrict__ bnm, const float* __restrict__ bnv,
           int mode, int Nout, float* __restrict__ outF,
           __nv_bfloat16* __restrict__ outHi, __nv_bfloat16* __restrict__ outLo) {
    constexpr int KC  = (K > 64) ? 64 : K;
    constexpr int NCH = K / KC;
    constexpr int P   = KC + 8;
    constexpr int P2  = P * 2;
    constexpr int S   = 128 * P2;
    constexpr int CH16 = KC / 8;
    extern __shared__ char sm[];
    uint32_t sA = smem_u32(sm);

    int tid = threadIdx.x, wid = tid >> 5, lane = tid & 31;
    int wm = wid & 1, wn = wid >> 1;
    int mBase = blockIdx.x * 128;
    int jBase = blockIdx.y * 128;

    float acc[4][4][4];
#pragma unroll
    for (int i = 0; i < 4; i++)
#pragma unroll
        for (int j = 0; j < 4; j++)
#pragma unroll
            for (int r = 0; r < 4; r++) acc[i][j][r] = 0.0f;

    uint32_t aOff = (uint32_t)((wm * 64 + (lane & 15)) * P2 + (lane >> 4) * 16);
    uint32_t bOff = (uint32_t)((wn * 32 + (lane & 7) + ((lane >> 4) << 3)) * P2 +
                               ((lane >> 3) & 1) * 16);

#pragma unroll
    for (int ch = 0; ch < NCH; ch++) {
        for (int idx = tid; idx < 128 * CH16; idx += 256) {
            int row = idx / CH16, c = idx % CH16;
            uint32_t d = sA + row * P2 + c * 16;
            size_t ga = (size_t)(mBase + row) * K + ch * KC + c * 8;
            size_t gw = (size_t)(jBase + row) * K + ch * KC + c * 8;
            cp16(d,         Ahi + ga);
            cp16(d + S,     Alo + ga);
            cp16(d + 2 * S, Whi + gw);
            cp16(d + 3 * S, Wlo + gw);
        }
        cp_commit(); cp_wait0();
        __syncthreads();

#pragma unroll
        for (int ks = 0; ks < KC / 16; ks++) {
            uint32_t ka = ks * 32;
            uint32_t bh[2][4], bl[2][4];
#pragma unroll
            for (int j2 = 0; j2 < 2; j2++) {
                ldsm_x4(bh[j2], sA + 2 * S + bOff + j2 * (16 * P2) + ka);
                ldsm_x4(bl[j2], sA + 3 * S + bOff + j2 * (16 * P2) + ka);
            }
#pragma unroll
            for (int i = 0; i < 4; i++) {
                uint32_t ah[4], al[4];
                ldsm_x4(ah, sA + aOff + i * (16 * P2) + ka);
                ldsm_x4(al, sA + S + aOff + i * (16 * P2) + ka);
#pragma unroll
                for (int j = 0; j < 4; j++) {
                    mma16816(acc[i][j], ah, &bh[j >> 1][(j & 1) * 2]);
                    mma16816(acc[i][j], ah, &bl[j >> 1][(j & 1) * 2]);
                    mma16816(acc[i][j], al, &bh[j >> 1][(j & 1) * 2]);
                }
            }
        }
        if (ch + 1 < NCH) __syncthreads();
    }

    float pb[4][2], psc[4][2], pmn[4][2], pbb[4][2];
#pragma unroll
    for (int j = 0; j < 4; j++) {
        int c = jBase + wn * 32 + j * 8 + (lane & 3) * 2;
#pragma unroll
        for (int q = 0; q < 2; q++) {
            pb[j][q] = bias ? bias[c + q] : 0.0f;
            if (mode == 2) {
                psc[j][q] = bng[c + q] * rsqrtf(bnv[c + q] + EPSBN);
                pmn[j][q] = bnm[c + q];
                pbb[j][q] = bnb[c + q];
            }
        }
    }
#pragma unroll
    for (int i = 0; i < 4; i++) {
        int r0 = mBase + wm * 64 + i * 16 + (lane >> 2);
#pragma unroll
        for (int j = 0; j < 4; j++) {
            int c = jBase + wn * 32 + j * 8 + (lane & 3) * 2;
            float v[4];
#pragma unroll
            for (int r = 0; r < 4; r++) {
                float x = acc[i][j][r] + pb[j][r & 1];
                if (mode >= 1) x = fmaxf(x, 0.0f);
                if (mode == 2) x = (x - pmn[j][r & 1]) * psc[j][r & 1] + pbb[j][r & 1];
                v[r] = x;
            }
            if (outF) {
                *(float2*)(outF + (size_t)r0 * Nout + c)       = make_float2(v[0], v[1]);
                *(float2*)(outF + (size_t)(r0 + 8) * Nout + c) = make_float2(v[2], v[3]);
            }
            if (outHi) {
                *(uint32_t*)(outHi + (size_t)r0 * Nout + c)       = pack_hi2(v[0], v[1]);
                *(uint32_t*)(outHi + (size_t)(r0 + 8) * Nout + c) = pack_hi2(v[2], v[3]);
                *(uint32_t*)(outLo + (size_t)r0 * Nout + c)       = pack_lo2(v[0], v[1]);
                *(uint32_t*)(outLo + (size_t)(r0 + 8) * Nout + c) = pack_lo2(v[2], v[3]);
            }
        }
    }
}

// ===================== tensor-core LSTM recurrence ===========================
// One block = 64 nodes, persistent over T. Per step: gates = pre + h @ Whh^T
// via bf16x3 mma.sync (M=64, N=256, K=64), gate nonlinearity, h back to smem.
#define LP2    144                      // h/whh smem pitch bytes (72 bf16)
#define GP     264                      // gates/pre pitch (floats)
#define S_WHH_HI 0
#define S_WHH_LO 36864
#define S_H_HI   73728
#define S_H_LO   82944
#define S_GATE   92160
#define S_PRE    (S_GATE + 64 * GP * 4) // 159744
#define LSTM_MMA_SMEM (S_PRE + 64 * GP * 4)   // 227328

__global__ void __launch_bounds__(256, 1)
k_lstm_mma(const float* __restrict__ pre,
           const __nv_bfloat16* __restrict__ whhHi, const __nv_bfloat16* __restrict__ whhLo,
           __nv_bfloat16* __restrict__ yHi, __nv_bfloat16* __restrict__ yLo,
           float* __restrict__ outFinal) {
    extern __shared__ char sm[];
    uint32_t sA = smem_u32(sm);
    int tid = threadIdx.x, wid = tid >> 5, lane = tid & 31;
    int wm = wid & 1, wn = wid >> 1;
    int nodeBase = blockIdx.x * 64;

    // load whh planes (256 rows x 64 k, pitch 72 bf16)
    for (int idx = tid; idx < 256 * 8; idx += 256) {
        int r = idx >> 3, c = idx & 7;
        cp16(sA + S_WHH_HI + r * LP2 + c * 16, whhHi + r * 64 + c * 8);
        cp16(sA + S_WHH_LO + r * LP2 + c * 16, whhLo + r * 64 + c * 8);
    }
    // zero h planes (hi+lo contiguous: 18432 B)
    for (int idx = tid; idx < 4608; idx += 256)
        ((uint32_t*)(sm + S_H_HI))[idx] = 0;
    cp_commit(); cp_wait0();
    __syncthreads();

    uint32_t aOff = (uint32_t)((wm * 32 + (lane & 15)) * LP2 + (lane >> 4) * 16);
    uint32_t bOff = (uint32_t)((wn * 64 + (lane & 7) + ((lane >> 4) << 3)) * LP2 +
                               ((lane >> 3) & 1) * 16);
    float cst[16];
#pragma unroll
    for (int w = 0; w < 16; w++) cst[w] = 0.0f;

    for (int t = 0; t < T_STEPS; t++) {
        // stage pre[t] for this block's 64 nodes (overlaps with MMA below)
        for (int idx = tid; idx < 64 * 64; idx += 256) {
            int r = idx >> 6, c = idx & 63;
            int n = nodeBase + r;
            if (n < NN)
                cp16(sA + S_PRE + r * (GP * 4) + c * 16,
                     pre + ((size_t)t * NN + n) * G4 + c * 4);
        }
        cp_commit();

        // MMA: gates_acc = h @ Whh^T (bf16x3)
        float acc[2][8][4];
#pragma unroll
        for (int i = 0; i < 2; i++)
#pragma unroll
            for (int j = 0; j < 8; j++)
#pragma unroll
                for (int r = 0; r < 4; r++) acc[i][j][r] = 0.0f;

#pragma unroll
        for (int ks = 0; ks < 4; ks++) {
            uint32_t ka = ks * 32;
            uint32_t bh[4][4], bl[4][4];
#pragma unroll
            for (int j2 = 0; j2 < 4; j2++) {
                ldsm_x4(bh[j2], sA + S_WHH_HI + bOff + j2 * (16 * LP2) + ka);
                ldsm_x4(bl[j2], sA + S_WHH_LO + bOff + j2 * (16 * LP2) + ka);
            }
#pragma unroll
            for (int i = 0; i < 2; i++) {
                uint32_t ah[4], al[4];
                ldsm_x4(ah, sA + S_H_HI + aOff + i * (16 * LP2) + ka);
                ldsm_x4(al, sA + S_H_LO + aOff + i * (16 * LP2) + ka);
#pragma unroll
                for (int j = 0; j < 8; j++) {
                    mma16816(acc[i][j], ah, &bh[j >> 1][(j & 1) * 2]);
                    mma16816(acc[i][j], ah, &bl[j >> 1][(j & 1) * 2]);
                    mma16816(acc[i][j], al, &bh[j >> 1][(j & 1) * 2]);
                }
            }
        }
        // acc -> gate smem
#pragma unroll
        for (int i = 0; i < 2; i++) {
            int r = wm * 32 + i * 16 + (lane >> 2);
#pragma unroll
            for (int j = 0; j < 8; j++) {
                int c = wn * 64 + j * 8 + (lane & 3) * 2;
                *(float2*)(sm + S_GATE + (r * GP + c) * 4) =
                    make_float2(acc[i][j][0], acc[i][j][1]);
                *(float2*)(sm + S_GATE + ((r + 8) * GP + c) * 4) =
                    make_float2(acc[i][j][2], acc[i][j][3]);
            }
        }
        cp_wait0();
        __syncthreads();

        // gate nonlinearity + state update; h back to smem planes
        const float* gate = (const float*)(sm + S_GATE);
        const float* prs  = (const float*)(sm + S_PRE);
#pragma unroll
        for (int w = 0; w < 16; w++) {
            int node = w * 4 + (tid >> 6);
            int u = tid & 63;
            int o = node * GP + u;
            float gi = gate[o]       + prs[o];
            float gf = gate[o + 64]  + prs[o + 64];
            float gg = gate[o + 128] + prs[o + 128];
            float go = gate[o + 192] + prs[o + 192];
            float ig = sigmoidf_(gi);
            float fg = sigmoidf_(gf);
            float gt = tanhf_(gg);
            float og = sigmoidf_(go);
            float cn = fg * cst[w] + ig * gt;
            cst[w] = cn;
            float hn = og * tanhf_(cn);
            __nv_bfloat16 hh = __float2bfloat16(hn);
            __nv_bfloat16 hl = __float2bfloat16(hn - __bfloat162float(hh));
            *(__nv_bfloat16*)(sm + S_H_HI + node * LP2 + u * 2) = hh;
            *(__nv_bfloat16*)(sm + S_H_LO + node * LP2 + u * 2) = hl;
            int n = nodeBase + node;
            if (n < NN) {
                if (yHi) {
                    size_t oo = ((size_t)t * NN + n) * OUTD + u;
                    yHi[oo] = hh;
                    yLo[oo] = hl;
                }
                if (outFinal && t == T_STEPS - 1)
                    outFinal[(size_t)n * OUTD + u] = hn;
            }
        }
        __syncthreads();
    }
}

// ===================== host =====================
extern "C" void kernel_launch(void* const* d_in, const int* in_sizes, int n_in,
                              void* d_out, int out_size) {
    const float* x   = (const float*)d_in[0];
    const int*   ei  = (const int*)d_in[1];
    const int*   src = ei;
    const int*   dst = ei + EE;
    const float* wg[3] = {(const float*)d_in[2], (const float*)d_in[4], (const float*)d_in[6]};
    const float* bg[3] = {(const float*)d_in[3], (const float*)d_in[5], (const float*)d_in[7]};
    const float* bnG[2] = {(const float*)d_in[8],  (const float*)d_in[12]};
    const float* bnB[2] = {(const float*)d_in[9],  (const float*)d_in[13]};
    const float* bnM[2] = {(const float*)d_in[10], (const float*)d_in[14]};
    const float* bnV[2] = {(const float*)d_in[11], (const float*)d_in[15]};
    const float* wih[3] = {(const float*)d_in[16], (const float*)d_in[20], (const float*)d_in[24]};
    const float* whh[3] = {(const float*)d_in[17], (const float*)d_in[21], (const float*)d_in[25]};
    const float* bih[3] = {(const float*)d_in[18], (const float*)d_in[22], (const float*)d_in[26]};
    const float* bhh[3] = {(const float*)d_in[19], (const float*)d_in[23], (const float*)d_in[27]};
    float* out = (float*)d_out;

    float *p_h, *p_pre, *p_bias;
    __nv_bfloat16 *p_aHi, *p_aLo, *p_hHi, *p_hLo, *p_yAHi, *p_yALo, *p_yBHi, *p_yBLo, *p_wHi, *p_wLo;
    cudaGetSymbolAddress((void**)&p_h,    g_h);
    cudaGetSymbolAddress((void**)&p_pre,  g_pre);
    cudaGetSymbolAddress((void**)&p_bias, g_biasc);
    cudaGetSymbolAddress((void**)&p_aHi,  g_aHi);
    cudaGetSymbolAddress((void**)&p_aLo,  g_aLo);
    cudaGetSymbolAddress((void**)&p_hHi,  g_hHi);
    cudaGetSymbolAddress((void**)&p_hLo,  g_hLo);
    cudaGetSymbolAddress((void**)&p_yAHi, g_yAHi);
    cudaGetSymbolAddress((void**)&p_yALo, g_yALo);
    cudaGetSymbolAddress((void**)&p_yBHi, g_yBHi);
    cudaGetSymbolAddress((void**)&p_yBLo, g_yBLo);
    cudaGetSymbolAddress((void**)&p_wHi,  g_wHi);
    cudaGetSymbolAddress((void**)&p_wLo,  g_wLo);

    const int SM32 = 4 * 128 * (32 + 8) * 2;   // 40960
    const int SM64 = 4 * 128 * (64 + 8) * 2;   // 73728
    cudaFuncSetAttribute(k_gemm_mma<32>,  cudaFuncAttributeMaxDynamicSharedMemorySize, SM32);
    cudaFuncSetAttribute(k_gemm_mma<64>,  cudaFuncAttributeMaxDynamicSharedMemorySize, SM64);
    cudaFuncSetAttribute(k_gemm_mma<128>, cudaFuncAttributeMaxDynamicSharedMemorySize, SM64);
    cudaFuncSetAttribute(k_lstm_mma, cudaFuncAttributeMaxDynamicSharedMemorySize, LSTM_MMA_SMEM);

    // ---- setup ----
    k_zero_cnt<<<(NN + 255) / 256, 256>>>();
    k_hist<<<(EE + 255) / 256, 256>>>(dst);
    k_scanfused<<<1, 1024>>>();
    k_fillprep<<<FILL_BLOCKS + PREP_BLOCKS, 256>>>(
        src, dst, wg[0], wg[1], wg[2], wih[0], wih[1], wih[2],
        whh[0], whh[1], whh[2],
        bih[0], bhh[0], bih[1], bhh[1], bih[2], bhh[2]);

    const int MT = MROWS / 128;  // 625 M tiles

    // ---- GCN 0 ----
    k_agg<32><<<NN, 256>>>(x, p_aHi, p_aLo);
    k_gemm_mma<32><<<dim3(MT, 1), 256, SM32>>>(
        p_aHi, p_aLo, p_wHi + WO0, p_wLo + WO0, bg[0],
        bnG[0], bnB[0], bnM[0], bnV[0], 2, HID, p_h, nullptr, nullptr);
    // ---- GCN 1 ----
    k_agg<128><<<NN, 256>>>(p_h, p_aHi, p_aLo);
    k_gemm_mma<128><<<dim3(MT, 1), 256, SM64>>>(
        p_aHi, p_aLo, p_wHi + WO1, p_wLo + WO1, bg[1],
        bnG[1], bnB[1], bnM[1], bnV[1], 2, HID, p_h, nullptr, nullptr);
    // ---- GCN 2 (relu only, emit bf16 planes) ----
    k_agg<128><<<NN, 256>>>(p_h, p_aHi, p_aLo);
    k_gemm_mma<128><<<dim3(MT, 1), 256, SM64>>>(
        p_aHi, p_aLo, p_wHi + WO2, p_wLo + WO2, bg[2],
        nullptr, nullptr, nullptr, nullptr, 1, HID, nullptr, p_hHi, p_hLo);

    int lstmBlocks = (NN + 63) / 64;  // 157
    // ---- LSTM layer 0 ----
    k_gemm_mma<128><<<dim3(MT, 2), 256, SM64>>>(
        p_hHi, p_hLo, p_wHi + WO3, p_wLo + WO3, p_bias + 0 * G4,
        nullptr, nullptr, nullptr, nullptr, 0, G4, p_pre, nullptr, nullptr);
    k_lstm_mma<<<lstmBlocks, 256, LSTM_MMA_SMEM>>>(
        p_pre, p_wHi + WH0, p_wLo + WH0, p_yAHi, p_yALo, nullptr);
    // ---- LSTM layer 1 ----
    k_gemm_mma<64><<<dim3(MT, 2), 256, SM64>>>(
        p_yAHi, p_yALo, p_wHi + WO4, p_wLo + WO4, p_bias + 1 * G4,
        nullptr, nullptr, nullptr, nullptr, 0, G4, p_pre, nullptr, nullptr);
    k_lstm_mma<<<lstmBlocks, 256, LSTM_MMA_SMEM>>>(
        p_pre, p_wHi + WH1, p_wLo + WH1, p_yBHi, p_yBLo, nullptr);
    // ---- LSTM layer 2 ----
    k_gemm_mma<64><<<dim3(MT, 2), 256, SM64>>>(
        p_yBHi, p_yBLo, p_wHi + WO5, p_wLo + WO5, p_bias + 2 * G4,
        nullptr, nullptr, nullptr, nullptr, 0, G4, p_pre, nullptr, nullptr);
    k_lstm_mma<<<lstmBlocks, 256, LSTM_MMA_SMEM>>>(
        p_pre, p_wHi + WH2, p_wLo + WH2, nullptr, nullptr, out);
}

// round 7
// speedup vs baseline: 1.0667x; 1.0667x over previous
#include <cuda_runtime.h>
#include <cuda_bf16.h>
#include <math.h>
#include <stdint.h>

#define T_STEPS 8
#define NN      10000
#define EE      200000
#define FIN     32
#define HID     128
#define OUTD    64
#define G4      256            // 4*OUT
#define MROWS   (T_STEPS*NN)   // 80000
#define EPSBN   1e-5f

// weight-plane offsets ([n][k] bf16 layout, packed)
#define WO0 0            // wg0^T   128x32
#define WO1 4096         // wg1^T   128x128
#define WO2 20480        // wg2^T   128x128
#define WO3 36864        // w_ih0   256x128
#define WO4 69632        // w_ih1   256x64
#define WO5 86016        // w_ih2   256x64
#define WTOT 102400
#define PREP_ELEMS (WTOT + 768)

// ===================== scratch (device globals) =====================
static __device__ float g_h  [MROWS*HID];      // GCN0/1 outputs (fp32, agg input)
static __device__ float g_pre[MROWS*G4];       // LSTM input projections
static __device__ __nv_bfloat16 g_aHi[MROWS*HID], g_aLo[MROWS*HID];   // agg out planes
static __device__ __nv_bfloat16 g_hHi[MROWS*HID], g_hLo[MROWS*HID];   // GCN2 out planes
static __device__ __nv_bfloat16 g_yAHi[MROWS*OUTD], g_yALo[MROWS*OUTD];
static __device__ __nv_bfloat16 g_yBHi[MROWS*OUTD], g_yBLo[MROWS*OUTD];
static __device__ __nv_bfloat16 g_wHi[WTOT], g_wLo[WTOT];
static __device__ float g_biasc[3*G4];
static __device__ float g_dis[NN];
static __device__ int   g_cnt[NN];
static __device__ int   g_rowptr[NN+1];
static __device__ int   g_cursor[NN];
static __device__ int   g_csr_src[EE];
static __device__ float g_csr_coef[EE];

// ===================== helpers =====================
__device__ __forceinline__ uint32_t smem_u32(const void* p) {
    uint32_t a;
    asm("{ .reg .u64 t; cvta.to.shared.u64 t, %1; cvt.u32.u64 %0, t; }" : "=r"(a) : "l"(p));
    return a;
}
__device__ __forceinline__ void cp16(uint32_t s, const void* g) {
    asm volatile("cp.async.cg.shared.global [%0], [%1], 16;" :: "r"(s), "l"(g));
}
__device__ __forceinline__ void cp_commit() {
    asm volatile("cp.async.commit_group;");
}
__device__ __forceinline__ void cp_wait0() {
    asm volatile("cp.async.wait_group 0;");
}
__device__ __forceinline__ void cp_wait1() {
    asm volatile("cp.async.wait_group 1;");
}
__device__ __forceinline__ void ldsm_x4(uint32_t* r, uint32_t addr) {
    asm volatile("ldmatrix.sync.aligned.m8n8.x4.shared.b16 {%0,%1,%2,%3}, [%4];"
                 : "=r"(r[0]), "=r"(r[1]), "=r"(r[2]), "=r"(r[3]) : "r"(addr));
}
__device__ __forceinline__ void mma16816(float* d, const uint32_t* a, const uint32_t* b) {
    asm volatile(
        "mma.sync.aligned.m16n8k16.row.col.f32.bf16.bf16.f32 "
        "{%0,%1,%2,%3}, {%4,%5,%6,%7}, {%8,%9}, {%0,%1,%2,%3};"
        : "+f"(d[0]), "+f"(d[1]), "+f"(d[2]), "+f"(d[3])
        : "r"(a[0]), "r"(a[1]), "r"(a[2]), "r"(a[3]), "r"(b[0]), "r"(b[1]));
}
__device__ __forceinline__ uint32_t pack_hi2(float x, float y) {
    __nv_bfloat162 h = __halves2bfloat162(__float2bfloat16(x), __float2bfloat16(y));
    return *(uint32_t*)&h;
}
__device__ __forceinline__ uint32_t pack_lo2(float x, float y) {
    float hx = __bfloat162float(__float2bfloat16(x));
    float hy = __bfloat162float(__float2bfloat16(y));
    __nv_bfloat162 l = __halves2bfloat162(__float2bfloat16(x - hx), __float2bfloat16(y - hy));
    return *(uint32_t*)&l;
}
__device__ __forceinline__ float sigmoidf_(float x) {
    return 1.0f / (1.0f + __expf(-x));
}
__device__ __forceinline__ float tanhf_(float x) {
    return 1.0f - 2.0f / (__expf(2.0f * x) + 1.0f);
}

// ===================== setup kernels =====================
__global__ void k_zero_cnt() {
    int i = blockIdx.x * blockDim.x + threadIdx.x;
    if (i < NN) g_cnt[i] = 0;
}
__global__ void k_hist(const int* __restrict__ dst) {
    int e = blockIdx.x * blockDim.x + threadIdx.x;
    if (e < EE) atomicAdd(&g_cnt[dst[e]], 1);
}
__global__ void k_scanfused() {
    const int TPB = 1024, PER = 10;
    __shared__ int sh[TPB];
    int tid = threadIdx.x;
    for (int i = tid; i < NN; i += TPB) g_dis[i] = rsqrtf((float)g_cnt[i] + 1.0f);
    int base = tid * PER;
    int loc[PER];
    int s = 0;
#pragma unroll
    for (int i = 0; i < PER; i++) {
        int idx = base + i;
        int v = (idx < NN) ? g_cnt[idx] : 0;
        loc[i] = s; s += v;
    }
    sh[tid] = s; __syncthreads();
    for (int off = 1; off < TPB; off <<= 1) {
        int v = (tid >= off) ? sh[tid - off] : 0;
        __syncthreads();
        sh[tid] += v;
        __syncthreads();
    }
    int excl = (tid == 0) ? 0 : sh[tid - 1];
#pragma unroll
    for (int i = 0; i < PER; i++) {
        int idx = base + i;
        if (idx <= NN) g_rowptr[idx] = excl + loc[i];
    }
    __syncthreads();
    for (int i = tid; i < NN; i += TPB) g_cursor[i] = g_rowptr[i];
}

#define FILL_BLOCKS ((EE + 255) / 256)
#define PREP_BLOCKS ((PREP_ELEMS + 255) / 256)
__global__ void k_fillprep(const int* __restrict__ src, const int* __restrict__ dst,
                           const float* __restrict__ wg0, const float* __restrict__ wg1,
                           const float* __restrict__ wg2,
                           const float* __restrict__ wih0, const float* __restrict__ wih1,
                           const float* __restrict__ wih2,
                           const float* __restrict__ bih0, const float* __restrict__ bhh0,
                           const float* __restrict__ bih1, const float* __restrict__ bhh1,
                           const float* __restrict__ bih2, const float* __restrict__ bhh2) {
    int b = blockIdx.x;
    int tid = threadIdx.x;
    if (b < FILL_BLOCKS) {
        int e = b * 256 + tid;
        if (e < EE) {
            int s = src[e], d = dst[e];
            int p = atomicAdd(&g_cursor[d], 1);
            g_csr_src[p]  = s;
            g_csr_coef[p] = g_dis[s] * g_dis[d];
        }
        return;
    }
    int idx = (b - FILL_BLOCKS) * 256 + tid;
    if (idx >= PREP_ELEMS) return;
    if (idx < WTOT) {
        float v;
        if (idx < WO1)       { int r = idx - WO0; v = wg0[(r & 31)  * HID + (r >> 5)]; }
        else if (idx < WO2)  { int r = idx - WO1; v = wg1[(r & 127) * HID + (r >> 7)]; }
        else if (idx < WO3)  { int r = idx - WO2; v = wg2[(r & 127) * HID + (r >> 7)]; }
        else if (idx < WO4)  { v = wih0[idx - WO3]; }
        else if (idx < WO5)  { v = wih1[idx - WO4]; }
        else                 { v = wih2[idx - WO5]; }
        __nv_bfloat16 h = __float2bfloat16(v);
        g_wHi[idx] = h;
        g_wLo[idx] = __float2bfloat16(v - __bfloat162float(h));
    } else {
        int r = idx - WTOT;
        int l = r >> 8, i = r & 255;
        const float* a = (l == 0) ? bih0 : (l == 1) ? bih1 : bih2;
        const float* c = (l == 0) ? bhh0 : (l == 1) ? bhh1 : bhh2;
        g_biasc[r] = a[i] + c[i];
    }
}

// ===================== GCN aggregation (emits bf16 hi/lo planes) =============
template <int F>
__global__ void k_agg(const float* __restrict__ in,
                      __nv_bfloat16* __restrict__ oHi, __nv_bfloat16* __restrict__ oLo) {
    int n = blockIdx.x;
    int t = threadIdx.x >> 5;
    int lane = threadIdx.x & 31;
    int p0 = g_rowptr[n], p1 = g_rowptr[n + 1];
    float d = g_dis[n];
    float sw = d * d;
    size_t m = (size_t)t * NN + n;
    if (F == 128) {
        int c0 = lane * 4;
        float4 acc = make_float4(0.f, 0.f, 0.f, 0.f);
        for (int p = p0; p < p1; p++) {
            int s = g_csr_src[p];
            float cf = g_csr_coef[p];
            float4 v = *(const float4*)(in + ((size_t)t * NN + s) * F + c0);
            acc.x += v.x * cf; acc.y += v.y * cf;
            acc.z += v.z * cf; acc.w += v.w * cf;
        }
        float4 hv = *(const float4*)(in + m * F + c0);
        float o0 = acc.x + hv.x * sw, o1 = acc.y + hv.y * sw;
        float o2 = acc.z + hv.z * sw, o3 = acc.w + hv.w * sw;
        uint2 hi = make_uint2(pack_hi2(o0, o1), pack_hi2(o2, o3));
        uint2 lo = make_uint2(pack_lo2(o0, o1), pack_lo2(o2, o3));
        *(uint2*)(oHi + m * F + c0) = hi;
        *(uint2*)(oLo + m * F + c0) = lo;
    } else {  // F == 32
        float acc = 0.0f;
        for (int p = p0; p < p1; p++) {
            int s = g_csr_src[p];
            acc += in[((size_t)t * NN + s) * F + lane] * g_csr_coef[p];
        }
        float r = acc + in[m * F + lane] * sw;
        __nv_bfloat16 h = __float2bfloat16(r);
        oHi[m * F + lane] = h;
        oLo[m * F + lane] = __float2bfloat16(r - __bfloat162float(h));
    }
}

// ===================== mma.sync bf16x3 GEMM (double-buffered, 2 CTA/SM) =====
// C = A @ W^T. A: bf16 hi/lo planes [M][K]; W: bf16 hi/lo planes [Nout][K].
// CTA tile 128x128, 256 threads (2(M)x4(N) warps), warp tile 64x32.
// K staged in KC=32 chunks, 2-buffer cp.async pipeline (stage c+1 || MMA c).
// mode: 0 = +bias ; 1 = relu(.+bias) ; 2 = bn(relu(.+bias))
template <int K>
__global__ void __launch_bounds__(256, 2)
k_gemm_mma(const __nv_bfloat16* __restrict__ Ahi, const __nv_bfloat16* __restrict__ Alo,
           const __nv_bfloat16* __restrict__ Whi, const __nv_bfloat16* __restrict__ Wlo,
           const float* __restrict__ bias,
           const float* __restrict__ bng, const float* __restrict__ bnb,
           const float* __restrict__ bnm, const float* __restrict__ bnv,
           int mode, int Nout, float* __restrict__ outF,
           __nv_bfloat16* __restrict__ outHi, __nv_bfloat16* __restrict__ outLo) {
    constexpr int KC   = 32;
    constexpr int NCH  = K / KC;           // 1, 2, 4
    constexpr int NBUF = (NCH > 1) ? 2 : 1;
    constexpr int P    = KC + 8;           // 40 bf16
    constexpr int P2   = P * 2;            // 80 bytes
    constexpr int S    = 128 * P2;         // 10240 per plane
    constexpr int BUF  = 4 * S;            // 40960 per buffer
    extern __shared__ char sm[];
    uint32_t sA = smem_u32(sm);

    int tid = threadIdx.x, wid = tid >> 5, lane = tid & 31;
    int wm = wid & 1, wn = wid >> 1;
    int mBase = blockIdx.x * 128;
    int jBase = blockIdx.y * 128;

    float acc[4][4][4];
#pragma unroll
    for (int i = 0; i < 4; i++)
#pragma unroll
        for (int j = 0; j < 4; j++)
#pragma unroll
            for (int r = 0; r < 4; r++) acc[i][j][r] = 0.0f;

    uint32_t aOff = (uint32_t)((wm * 64 + (lane & 15)) * P2 + (lane >> 4) * 16);
    uint32_t bOff = (uint32_t)((wn * 32 + (lane & 7) + ((lane >> 4) << 3)) * P2 +
                               ((lane >> 3) & 1) * 16);

    auto stage = [&](int ch) {
        uint32_t b = sA + (uint32_t)(ch % NBUF) * BUF;
        // 128 rows x 4 16B-chunks per plane; 512 slots / 256 threads = 2 each
#pragma unroll
        for (int s2 = 0; s2 < 2; s2++) {
            int idx = tid + s2 * 256;
            int row = idx >> 2, c = idx & 3;
            uint32_t d = b + row * P2 + c * 16;
            size_t ga = (size_t)(mBase + row) * K + ch * KC + c * 8;
            size_t gw = (size_t)(jBase + row) * K + ch * KC + c * 8;
            cp16(d,         Ahi + ga);
            cp16(d + S,     Alo + ga);
            cp16(d + 2 * S, Whi + gw);
            cp16(d + 3 * S, Wlo + gw);
        }
        cp_commit();
    };

    stage(0);
#pragma unroll
    for (int ch = 0; ch < NCH; ch++) {
        if (ch + 1 < NCH) { stage(ch + 1); cp_wait1(); } else { cp_wait0(); }
        __syncthreads();
        uint32_t b = sA + (uint32_t)(ch % NBUF) * BUF;
#pragma unroll
        for (int ks = 0; ks < KC / 16; ks++) {
            uint32_t ka = ks * 32;
            uint32_t bh[2][4], bl[2][4];
#pragma unroll
            for (int j2 = 0; j2 < 2; j2++) {
                ldsm_x4(bh[j2], b + 2 * S + bOff + j2 * (16 * P2) + ka);
                ldsm_x4(bl[j2], b + 3 * S + bOff + j2 * (16 * P2) + ka);
            }
#pragma unroll
            for (int i = 0; i < 4; i++) {
                uint32_t ah[4], al[4];
                ldsm_x4(ah, b + aOff + i * (16 * P2) + ka);
                ldsm_x4(al, b + S + aOff + i * (16 * P2) + ka);
#pragma unroll
                for (int j = 0; j < 4; j++) {
                    mma16816(acc[i][j], ah, &bh[j >> 1][(j & 1) * 2]);
                    mma16816(acc[i][j], ah, &bl[j >> 1][(j & 1) * 2]);
                    mma16816(acc[i][j], al, &bh[j >> 1][(j & 1) * 2]);
                }
            }
        }
        if (ch + 1 < NCH) __syncthreads();
    }

    float pb[4][2], psc[4][2], pmn[4][2], pbb[4][2];
#pragma unroll
    for (int j = 0; j < 4; j++) {
        int c = jBase + wn * 32 + j * 8 + (lane & 3) * 2;
#pragma unroll
        for (int q = 0; q < 2; q++) {
            pb[j][q] = bias ? bias[c + q] : 0.0f;
            if (mode == 2) {
                psc[j][q] = bng[c + q] * rsqrtf(bnv[c + q] + EPSBN);
                pmn[j][q] = bnm[c + q];
                pbb[j][q] = bnb[c + q];
            }
        }
    }
#pragma unroll
    for (int i = 0; i < 4; i++) {
        int r0 = mBase + wm * 64 + i * 16 + (lane >> 2);
#pragma unroll
        for (int j = 0; j < 4; j++) {
            int c = jBase + wn * 32 + j * 8 + (lane & 3) * 2;
            float v[4];
#pragma unroll
            for (int r = 0; r < 4; r++) {
                float x = acc[i][j][r] + pb[j][r & 1];
                if (mode >= 1) x = fmaxf(x, 0.0f);
                if (mode == 2) x = (x - pmn[j][r & 1]) * psc[j][r & 1] + pbb[j][r & 1];
                v[r] = x;
            }
            if (outF) {
                *(float2*)(outF + (size_t)r0 * Nout + c)       = make_float2(v[0], v[1]);
                *(float2*)(outF + (size_t)(r0 + 8) * Nout + c) = make_float2(v[2], v[3]);
            }
            if (outHi) {
                *(uint32_t*)(outHi + (size_t)r0 * Nout + c)       = pack_hi2(v[0], v[1]);
                *(uint32_t*)(outHi + (size_t)(r0 + 8) * Nout + c) = pack_hi2(v[2], v[3]);
                *(uint32_t*)(outLo + (size_t)r0 * Nout + c)       = pack_lo2(v[0], v[1]);
                *(uint32_t*)(outLo + (size_t)(r0 + 8) * Nout + c) = pack_lo2(v[2], v[3]);
            }
        }
    }
}

// ===================== LSTM recurrence (4 nodes / warp, scalar) ==============
#define LSTM_SMEM ((64*257 + 32*64) * 4)

__global__ void k_lstm(const float* __restrict__ pre, const float* __restrict__ whh,
                       __nv_bfloat16* __restrict__ yHi, __nv_bfloat16* __restrict__ yLo,
                       float* __restrict__ outFinal) {
    extern __shared__ float smf[];
    float* ws = smf;               // [64][257] transposed whh (padded)
    float* hs = smf + 64 * 257;    // [32 nodes][64]

    int tid  = threadIdx.x;
    int warp = tid >> 5, lane = tid & 31;
    int nodeBase = blockIdx.x * 32 + warp * 4;

    for (int idx = tid; idx < G4 * OUTD; idx += 256) {
        int j = idx >> 6, k = idx & 63;
        ws[k * 257 + j] = whh[idx];
    }
#pragma unroll
    for (int q = 0; q < 4; q++) {
        hs[(warp * 4 + q) * 64 + lane]      = 0.0f;
        hs[(warp * 4 + q) * 64 + lane + 32] = 0.0f;
    }
    float c[4][2];
#pragma unroll
    for (int q = 0; q < 4; q++) { c[q][0] = 0.0f; c[q][1] = 0.0f; }
    __syncthreads();

    for (int t = 0; t < T_STEPS; t++) {
        float g[4][8];
#pragma unroll
        for (int q = 0; q < 4; q++) {
            int n = nodeBase + q;
            if (n < NN) {
                const float* pb = pre + ((size_t)t * NN + n) * G4;
#pragma unroll
                for (int i = 0; i < 8; i++) g[q][i] = pb[i * 32 + lane];
            } else {
#pragma unroll
                for (int i = 0; i < 8; i++) g[q][i] = 0.0f;
            }
        }
#pragma unroll 4
        for (int k = 0; k < 64; k++) {
            float w[8];
#pragma unroll
            for (int i = 0; i < 8; i++) w[i] = ws[k * 257 + i * 32 + lane];
#pragma unroll
            for (int q = 0; q < 4; q++) {
                float hk = hs[(warp * 4 + q) * 64 + k];
#pragma unroll
                for (int i = 0; i < 8; i++) g[q][i] += hk * w[i];
            }
        }
        __syncwarp();
#pragma unroll
        for (int q = 0; q < 4; q++) {
            int n = nodeBase + q;
#pragma unroll
            for (int h2 = 0; h2 < 2; h2++) {
                float ig = sigmoidf_(g[q][0 + h2]);
                float fg = sigmoidf_(g[q][2 + h2]);
                float gg = tanhf_(g[q][4 + h2]);
                float og = sigmoidf_(g[q][6 + h2]);
                float cn = fg * c[q][h2] + ig * gg;
                c[q][h2] = cn;
                float hn = og * tanhf_(cn);
                int u = lane + 32 * h2;
                hs[(warp * 4 + q) * 64 + u] = hn;
                if (n < NN) {
                    if (yHi) {
                        size_t o = ((size_t)t * NN + n) * OUTD + u;
                        __nv_bfloat16 hh = __float2bfloat16(hn);
                        yHi[o] = hh;
                        yLo[o] = __float2bfloat16(hn - __bfloat162float(hh));
                    }
                    if (outFinal && t == T_STEPS - 1)
                        outFinal[(size_t)n * OUTD + u] = hn;
                }
            }
        }
        __syncwarp();
    }
}

// ===================== host =====================
extern "C" void kernel_launch(void* const* d_in, const int* in_sizes, int n_in,
                              void* d_out, int out_size) {
    const float* x   = (const float*)d_in[0];
    const int*   ei  = (const int*)d_in[1];
    const int*   src = ei;
    const int*   dst = ei + EE;
    const float* wg[3] = {(const float*)d_in[2], (const float*)d_in[4], (const float*)d_in[6]};
    const float* bg[3] = {(const float*)d_in[3], (const float*)d_in[5], (const float*)d_in[7]};
    const float* bnG[2] = {(const float*)d_in[8],  (const float*)d_in[12]};
    const float* bnB[2] = {(const float*)d_in[9],  (const float*)d_in[13]};
    const float* bnM[2] = {(const float*)d_in[10], (const float*)d_in[14]};
    const float* bnV[2] = {(const float*)d_in[11], (const float*)d_in[15]};
    const float* wih[3] = {(const float*)d_in[16], (const float*)d_in[20], (const float*)d_in[24]};
    const float* whh[3] = {(const float*)d_in[17], (const float*)d_in[21], (const float*)d_in[25]};
    const float* bih[3] = {(const float*)d_in[18], (const float*)d_in[22], (const float*)d_in[26]};
    const float* bhh[3] = {(const float*)d_in[19], (const float*)d_in[23], (const float*)d_in[27]};
    float* out = (float*)d_out;

    float *p_h, *p_pre, *p_bias;
    __nv_bfloat16 *p_aHi, *p_aLo, *p_hHi, *p_hLo, *p_yAHi, *p_yALo, *p_yBHi, *p_yBLo, *p_wHi, *p_wLo;
    cudaGetSymbolAddress((void**)&p_h,    g_h);
    cudaGetSymbolAddress((void**)&p_pre,  g_pre);
    cudaGetSymbolAddress((void**)&p_bias, g_biasc);
    cudaGetSymbolAddress((void**)&p_aHi,  g_aHi);
    cudaGetSymbolAddress((void**)&p_aLo,  g_aLo);
    cudaGetSymbolAddress((void**)&p_hHi,  g_hHi);
    cudaGetSymbolAddress((void**)&p_hLo,  g_hLo);
    cudaGetSymbolAddress((void**)&p_yAHi, g_yAHi);
    cudaGetSymbolAddress((void**)&p_yALo, g_yALo);
    cudaGetSymbolAddress((void**)&p_yBHi, g_yBHi);
    cudaGetSymbolAddress((void**)&p_yBLo, g_yBLo);
    cudaGetSymbolAddress((void**)&p_wHi,  g_wHi);
    cudaGetSymbolAddress((void**)&p_wLo,  g_wLo);

    const int SM1 = 40960;   // K=32: single buffer
    const int SM2 = 81920;   // K=64/128: double buffer
    cudaFuncSetAttribute(k_gemm_mma<32>,  cudaFuncAttributeMaxDynamicSharedMemorySize, SM1);
    cudaFuncSetAttribute(k_gemm_mma<64>,  cudaFuncAttributeMaxDynamicSharedMemorySize, SM2);
    cudaFuncSetAttribute(k_gemm_mma<128>, cudaFuncAttributeMaxDynamicSharedMemorySize, SM2);
    cudaFuncSetAttribute(k_lstm, cudaFuncAttributeMaxDynamicSharedMemorySize, LSTM_SMEM);

    // ---- setup ----
    k_zero_cnt<<<(NN + 255) / 256, 256>>>();
    k_hist<<<(EE + 255) / 256, 256>>>(dst);
    k_scanfused<<<1, 1024>>>();
    k_fillprep<<<FILL_BLOCKS + PREP_BLOCKS, 256>>>(
        src, dst, wg[0], wg[1], wg[2], wih[0], wih[1], wih[2],
        bih[0], bhh[0], bih[1], bhh[1], bih[2], bhh[2]);

    const int MT = MROWS / 128;  // 625 M tiles

    // ---- GCN 0 ----
    k_agg<32><<<NN, 256>>>(x, p_aHi, p_aLo);
    k_gemm_mma<32><<<dim3(MT, 1), 256, SM1>>>(
        p_aHi, p_aLo, p_wHi + WO0, p_wLo + WO0, bg[0],
        bnG[0], bnB[0], bnM[0], bnV[0], 2, HID, p_h, nullptr, nullptr);
    // ---- GCN 1 ----
    k_agg<128><<<NN, 256>>>(p_h, p_aHi, p_aLo);
    k_gemm_mma<128><<<dim3(MT, 1), 256, SM2>>>(
        p_aHi, p_aLo, p_wHi + WO1, p_wLo + WO1, bg[1],
        bnG[1], bnB[1], bnM[1], bnV[1], 2, HID, p_h, nullptr, nullptr);
    // ---- GCN 2 (relu only, emit bf16 planes) ----
    k_agg<128><<<NN, 256>>>(p_h, p_aHi, p_aLo);
    k_gemm_mma<128><<<dim3(MT, 1), 256, SM2>>>(
        p_aHi, p_aLo, p_wHi + WO2, p_wLo + WO2, bg[2],
        nullptr, nullptr, nullptr, nullptr, 1, HID, nullptr, p_hHi, p_hLo);

    int lstmBlocks = (NN + 31) / 32;  // 313
    // ---- LSTM layer 0 ----
    k_gemm_mma<128><<<dim3(MT, 2), 256, SM2>>>(
        p_hHi, p_hLo, p_wHi + WO3, p_wLo + WO3, p_bias + 0 * G4,
        nullptr, nullptr, nullptr, nullptr, 0, G4, p_pre, nullptr, nullptr);
    k_lstm<<<lstmBlocks, 256, LSTM_SMEM>>>(p_pre, whh[0], p_yAHi, p_yALo, nullptr);
    // ---- LSTM layer 1 ----
    k_gemm_mma<64><<<dim3(MT, 2), 256, SM2>>>(
        p_yAHi, p_yALo, p_wHi + WO4, p_wLo + WO4, p_bias + 1 * G4,
        nullptr, nullptr, nullptr, nullptr, 0, G4, p_pre, nullptr, nullptr);
    k_lstm<<<lstmBlocks, 256, LSTM_SMEM>>>(p_pre, whh[1], p_yBHi, p_yBLo, nullptr);
    // ---- LSTM layer 2 ----
    k_gemm_mma<64><<<dim3(MT, 2), 256, SM2>>>(
        p_yBHi, p_yBLo, p_wHi + WO5, p_wLo + WO5, p_bias + 2 * G4,
        nullptr, nullptr, nullptr, nullptr, 0, G4, p_pre, nullptr, nullptr);
    k_lstm<<<lstmBlocks, 256, LSTM_SMEM>>>(p_pre, whh[2], nullptr, nullptr, out);
}

// round 8
// speedup vs baseline: 1.0824x; 1.0148x over previous
#include <cuda_runtime.h>
#include <cuda_bf16.h>
#include <math.h>
#include <stdint.h>

#define T_STEPS 8
#define NN      10000
#define EE      200000
#define FIN     32
#define HID     128
#define OUTD    64
#define G4      256            // 4*OUT
#define MROWS   (T_STEPS*NN)   // 80000
#define EPSBN   1e-5f

// weight-plane offsets ([n][k] bf16 layout, packed)
// LSTM planes (WO3.., WH..) use gate-interleaved row permutation:
//   plane row j = g*32 + q*8 + v  <->  torch row = q*64 + g*8 + v
#define WO0 0            // wg0^T   128x32
#define WO1 4096         // wg1^T   128x128
#define WO2 20480        // wg2^T   128x128
#define WO3 36864        // w_ih0   256x128 (perm)
#define WO4 69632        // w_ih1   256x64  (perm)
#define WO5 86016        // w_ih2   256x64  (perm)
#define WH0 102400       // whh0    256x64  (perm)
#define WH1 118784       // whh1    256x64  (perm)
#define WH2 135168       // whh2    256x64  (perm)
#define WTOT 151552
#define PREP_ELEMS (WTOT + 768)

// ===================== scratch (device globals) =====================
static __device__ float g_h  [MROWS*HID];      // GCN0/1 outputs (fp32, agg input)
static __device__ float g_pre[MROWS*G4];       // LSTM input projections (permuted cols)
static __device__ __nv_bfloat16 g_aHi[MROWS*HID], g_aLo[MROWS*HID];   // agg out planes
static __device__ __nv_bfloat16 g_hHi[MROWS*HID], g_hLo[MROWS*HID];   // GCN2 out planes
static __device__ __nv_bfloat16 g_yAHi[MROWS*OUTD], g_yALo[MROWS*OUTD];
static __device__ __nv_bfloat16 g_yBHi[MROWS*OUTD], g_yBLo[MROWS*OUTD];
static __device__ __nv_bfloat16 g_wHi[WTOT], g_wLo[WTOT];
static __device__ float g_biasc[3*G4];         // permuted
static __device__ float g_dis[NN];
static __device__ int   g_cnt[NN];
static __device__ int   g_rowptr[NN+1];
static __device__ int   g_cursor[NN];
static __device__ int   g_csr_src[EE];
static __device__ float g_csr_coef[EE];

// ===================== helpers =====================
__device__ __forceinline__ uint32_t smem_u32(const void* p) {
    uint32_t a;
    asm("{ .reg .u64 t; cvta.to.shared.u64 t, %1; cvt.u32.u64 %0, t; }" : "=r"(a) : "l"(p));
    return a;
}
__device__ __forceinline__ void cp16(uint32_t s, const void* g) {
    asm volatile("cp.async.cg.shared.global [%0], [%1], 16;" :: "r"(s), "l"(g));
}
__device__ __forceinline__ void cp_commit() {
    asm volatile("cp.async.commit_group;");
}
__device__ __forceinline__ void cp_wait0() {
    asm volatile("cp.async.wait_group 0;");
}
__device__ __forceinline__ void cp_wait1() {
    asm volatile("cp.async.wait_group 1;");
}
__device__ __forceinline__ void ldsm_x4(uint32_t* r, uint32_t addr) {
    asm volatile("ldmatrix.sync.aligned.m8n8.x4.shared.b16 {%0,%1,%2,%3}, [%4];"
                 : "=r"(r[0]), "=r"(r[1]), "=r"(r[2]), "=r"(r[3]) : "r"(addr));
}
__device__ __forceinline__ void mma16816(float* d, const uint32_t* a, const uint32_t* b) {
    asm volatile(
        "mma.sync.aligned.m16n8k16.row.col.f32.bf16.bf16.f32 "
        "{%0,%1,%2,%3}, {%4,%5,%6,%7}, {%8,%9}, {%0,%1,%2,%3};"
        : "+f"(d[0]), "+f"(d[1]), "+f"(d[2]), "+f"(d[3])
        : "r"(a[0]), "r"(a[1]), "r"(a[2]), "r"(a[3]), "r"(b[0]), "r"(b[1]));
}
__device__ __forceinline__ uint32_t pack_hi2(float x, float y) {
    __nv_bfloat162 h = __halves2bfloat162(__float2bfloat16(x), __float2bfloat16(y));
    return *(uint32_t*)&h;
}
__device__ __forceinline__ uint32_t pack_lo2(float x, float y) {
    float hx = __bfloat162float(__float2bfloat16(x));
    float hy = __bfloat162float(__float2bfloat16(y));
    __nv_bfloat162 l = __halves2bfloat162(__float2bfloat16(x - hx), __float2bfloat16(y - hy));
    return *(uint32_t*)&l;
}
__device__ __forceinline__ float sigmoidf_(float x) {
    return 1.0f / (1.0f + __expf(-x));
}
__device__ __forceinline__ float tanhf_(float x) {
    return 1.0f - 2.0f / (__expf(2.0f * x) + 1.0f);
}

// ===================== setup kernels =====================
__global__ void k_zero_cnt() {
    int i = blockIdx.x * blockDim.x + threadIdx.x;
    if (i < NN) g_cnt[i] = 0;
}
__global__ void k_hist(const int* __restrict__ dst) {
    int e = blockIdx.x * blockDim.x + threadIdx.x;
    if (e < EE) atomicAdd(&g_cnt[dst[e]], 1);
}
__global__ void k_scanfused() {
    const int TPB = 1024, PER = 10;
    __shared__ int sh[TPB];
    int tid = threadIdx.x;
    for (int i = tid; i < NN; i += TPB) g_dis[i] = rsqrtf((float)g_cnt[i] + 1.0f);
    int base = tid * PER;
    int loc[PER];
    int s = 0;
#pragma unroll
    for (int i = 0; i < PER; i++) {
        int idx = base + i;
        int v = (idx < NN) ? g_cnt[idx] : 0;
        loc[i] = s; s += v;
    }
    sh[tid] = s; __syncthreads();
    for (int off = 1; off < TPB; off <<= 1) {
        int v = (tid >= off) ? sh[tid - off] : 0;
        __syncthreads();
        sh[tid] += v;
        __syncthreads();
    }
    int excl = (tid == 0) ? 0 : sh[tid - 1];
#pragma unroll
    for (int i = 0; i < PER; i++) {
        int idx = base + i;
        if (idx <= NN) g_rowptr[idx] = excl + loc[i];
    }
    __syncthreads();
    for (int i = tid; i < NN; i += TPB) g_cursor[i] = g_rowptr[i];
}

// gate-interleave permutation: plane row j -> torch row
__device__ __forceinline__ int gate_perm(int j) {
    return ((j >> 3) & 3) * 64 + (j >> 5) * 8 + (j & 7);
}

#define FILL_BLOCKS ((EE + 255) / 256)
#define PREP_BLOCKS ((PREP_ELEMS + 255) / 256)
__global__ void k_fillprep(const int* __restrict__ src, const int* __restrict__ dst,
                           const float* __restrict__ wg0, const float* __restrict__ wg1,
                           const float* __restrict__ wg2,
                           const float* __restrict__ wih0, const float* __restrict__ wih1,
                           const float* __restrict__ wih2,
                           const float* __restrict__ whh0, const float* __restrict__ whh1,
                           const float* __restrict__ whh2,
                           const float* __restrict__ bih0, const float* __restrict__ bhh0,
                           const float* __restrict__ bih1, const float* __restrict__ bhh1,
                           const float* __restrict__ bih2, const float* __restrict__ bhh2) {
    int b = blockIdx.x;
    int tid = threadIdx.x;
    if (b < FILL_BLOCKS) {
        int e = b * 256 + tid;
        if (e < EE) {
            int s = src[e], d = dst[e];
            int p = atomicAdd(&g_cursor[d], 1);
            g_csr_src[p]  = s;
            g_csr_coef[p] = g_dis[s] * g_dis[d];
        }
        return;
    }
    int idx = (b - FILL_BLOCKS) * 256 + tid;
    if (idx >= PREP_ELEMS) return;
    if (idx < WTOT) {
        float v;
        if (idx < WO1)       { int r = idx - WO0; v = wg0[(r & 31)  * HID + (r >> 5)]; }
        else if (idx < WO2)  { int r = idx - WO1; v = wg1[(r & 127) * HID + (r >> 7)]; }
        else if (idx < WO3)  { int r = idx - WO2; v = wg2[(r & 127) * HID + (r >> 7)]; }
        else if (idx < WO4)  { int l = idx - WO3; v = wih0[gate_perm(l >> 7) * 128 + (l & 127)]; }
        else if (idx < WO5)  { int l = idx - WO4; v = wih1[gate_perm(l >> 6) * 64 + (l & 63)]; }
        else if (idx < WH0)  { int l = idx - WO5; v = wih2[gate_perm(l >> 6) * 64 + (l & 63)]; }
        else if (idx < WH1)  { int l = idx - WH0; v = whh0[gate_perm(l >> 6) * 64 + (l & 63)]; }
        else if (idx < WH2)  { int l = idx - WH1; v = whh1[gate_perm(l >> 6) * 64 + (l & 63)]; }
        else                 { int l = idx - WH2; v = whh2[gate_perm(l >> 6) * 64 + (l & 63)]; }
        __nv_bfloat16 h = __float2bfloat16(v);
        g_wHi[idx] = h;
        g_wLo[idx] = __float2bfloat16(v - __bfloat162float(h));
    } else {
        int r = idx - WTOT;
        int l = r >> 8, j = r & 255;
        int orig = gate_perm(j);
        const float* a = (l == 0) ? bih0 : (l == 1) ? bih1 : bih2;
        const float* c = (l == 0) ? bhh0 : (l == 1) ? bhh1 : bhh2;
        g_biasc[r] = a[orig] + c[orig];
    }
}

// ===================== GCN aggregation (emits bf16 hi/lo planes) =============
template <int F>
__global__ void k_agg(const float* __restrict__ in,
                      __nv_bfloat16* __restrict__ oHi, __nv_bfloat16* __restrict__ oLo) {
    int n = blockIdx.x;
    int t = threadIdx.x >> 5;
    int lane = threadIdx.x & 31;
    int p0 = g_rowptr[n], p1 = g_rowptr[n + 1];
    float d = g_dis[n];
    float sw = d * d;
    size_t m = (size_t)t * NN + n;
    if (F == 128) {
        int c0 = lane * 4;
        float4 acc = make_float4(0.f, 0.f, 0.f, 0.f);
        for (int p = p0; p < p1; p++) {
            int s = g_csr_src[p];
            float cf = g_csr_coef[p];
            float4 v = *(const float4*)(in + ((size_t)t * NN + s) * F + c0);
            acc.x += v.x * cf; acc.y += v.y * cf;
            acc.z += v.z * cf; acc.w += v.w * cf;
        }
        float4 hv = *(const float4*)(in + m * F + c0);
        float o0 = acc.x + hv.x * sw, o1 = acc.y + hv.y * sw;
        float o2 = acc.z + hv.z * sw, o3 = acc.w + hv.w * sw;
        uint2 hi = make_uint2(pack_hi2(o0, o1), pack_hi2(o2, o3));
        uint2 lo = make_uint2(pack_lo2(o0, o1), pack_lo2(o2, o3));
        *(uint2*)(oHi + m * F + c0) = hi;
        *(uint2*)(oLo + m * F + c0) = lo;
    } else {  // F == 32
        float acc = 0.0f;
        for (int p = p0; p < p1; p++) {
            int s = g_csr_src[p];
            acc += in[((size_t)t * NN + s) * F + lane] * g_csr_coef[p];
        }
        float r = acc + in[m * F + lane] * sw;
        __nv_bfloat16 h = __float2bfloat16(r);
        oHi[m * F + lane] = h;
        oLo[m * F + lane] = __float2bfloat16(r - __bfloat162float(h));
    }
}

// ===================== mma.sync bf16x3 GEMM (double-buffered, 2 CTA/SM) =====
template <int K>
__global__ void __launch_bounds__(256, 2)
k_gemm_mma(const __nv_bfloat16* __restrict__ Ahi, const __nv_bfloat16* __restrict__ Alo,
           const __nv_bfloat16* __restrict__ Whi, const __nv_bfloat16* __restrict__ Wlo,
           const float* __restrict__ bias,
           const float* __restrict__ bng, const float* __restrict__ bnb,
           const float* __restrict__ bnm, const float* __restrict__ bnv,
           int mode, int Nout, float* __restrict__ outF,
           __nv_bfloat16* __restrict__ outHi, __nv_bfloat16* __restrict__ outLo) {
    constexpr int KC   = 32;
    constexpr int NCH  = K / KC;
    constexpr int NBUF = (NCH > 1) ? 2 : 1;
    constexpr int P    = KC + 8;
    constexpr int P2   = P * 2;
    constexpr int S    = 128 * P2;
    constexpr int BUF  = 4 * S;
    extern __shared__ char sm[];
    uint32_t sA = smem_u32(sm);

    int tid = threadIdx.x, wid = tid >> 5, lane = tid & 31;
    int wm = wid & 1, wn = wid >> 1;
    int mBase = blockIdx.x * 128;
    int jBase = blockIdx.y * 128;

    float acc[4][4][4];
#pragma unroll
    for (int i = 0; i < 4; i++)
#pragma unroll
        for (int j = 0; j < 4; j++)
#pragma unroll
            for (int r = 0; r < 4; r++) acc[i][j][r] = 0.0f;

    uint32_t aOff = (uint32_t)((wm * 64 + (lane & 15)) * P2 + (lane >> 4) * 16);
    uint32_t bOff = (uint32_t)((wn * 32 + (lane & 7) + ((lane >> 4) << 3)) * P2 +
                               ((lane >> 3) & 1) * 16);

    auto stage = [&](int ch) {
        uint32_t b = sA + (uint32_t)(ch % NBUF) * BUF;
#pragma unroll
        for (int s2 = 0; s2 < 2; s2++) {
            int idx = tid + s2 * 256;
            int row = idx >> 2, c = idx & 3;
            uint32_t d = b + row * P2 + c * 16;
            size_t ga = (size_t)(mBase + row) * K + ch * KC + c * 8;
            size_t gw = (size_t)(jBase + row) * K + ch * KC + c * 8;
            cp16(d,         Ahi + ga);
            cp16(d + S,     Alo + ga);
            cp16(d + 2 * S, Whi + gw);
            cp16(d + 3 * S, Wlo + gw);
        }
        cp_commit();
    };

    stage(0);
#pragma unroll
    for (int ch = 0; ch < NCH; ch++) {
        if (ch + 1 < NCH) { stage(ch + 1); cp_wait1(); } else { cp_wait0(); }
        __syncthreads();
        uint32_t b = sA + (uint32_t)(ch % NBUF) * BUF;
#pragma unroll
        for (int ks = 0; ks < KC / 16; ks++) {
            uint32_t ka = ks * 32;
            uint32_t bh[2][4], bl[2][4];
#pragma unroll
            for (int j2 = 0; j2 < 2; j2++) {
                ldsm_x4(bh[j2], b + 2 * S + bOff + j2 * (16 * P2) + ka);
                ldsm_x4(bl[j2], b + 3 * S + bOff + j2 * (16 * P2) + ka);
            }
#pragma unroll
            for (int i = 0; i < 4; i++) {
                uint32_t ah[4], al[4];
                ldsm_x4(ah, b + aOff + i * (16 * P2) + ka);
                ldsm_x4(al, b + S + aOff + i * (16 * P2) + ka);
#pragma unroll
                for (int j = 0; j < 4; j++) {
                    mma16816(acc[i][j], ah, &bh[j >> 1][(j & 1) * 2]);
                    mma16816(acc[i][j], ah, &bl[j >> 1][(j & 1) * 2]);
                    mma16816(acc[i][j], al, &bh[j >> 1][(j & 1) * 2]);
                }
            }
        }
        if (ch + 1 < NCH) __syncthreads();
    }

    float pb[4][2], psc[4][2], pmn[4][2], pbb[4][2];
#pragma unroll
    for (int j = 0; j < 4; j++) {
        int c = jBase + wn * 32 + j * 8 + (lane & 3) * 2;
#pragma unroll
        for (int q = 0; q < 2; q++) {
            pb[j][q] = bias ? bias[c + q] : 0.0f;
            if (mode == 2) {
                psc[j][q] = bng[c + q] * rsqrtf(bnv[c + q] + EPSBN);
                pmn[j][q] = bnm[c + q];
                pbb[j][q] = bnb[c + q];
            }
        }
    }
#pragma unroll
    for (int i = 0; i < 4; i++) {
        int r0 = mBase + wm * 64 + i * 16 + (lane >> 2);
#pragma unroll
        for (int j = 0; j < 4; j++) {
            int c = jBase + wn * 32 + j * 8 + (lane & 3) * 2;
            float v[4];
#pragma unroll
            for (int r = 0; r < 4; r++) {
                float x = acc[i][j][r] + pb[j][r & 1];
                if (mode >= 1) x = fmaxf(x, 0.0f);
                if (mode == 2) x = (x - pmn[j][r & 1]) * psc[j][r & 1] + pbb[j][r & 1];
                v[r] = x;
            }
            if (outF) {
                *(float2*)(outF + (size_t)r0 * Nout + c)       = make_float2(v[0], v[1]);
                *(float2*)(outF + (size_t)(r0 + 8) * Nout + c) = make_float2(v[2], v[3]);
            }
            if (outHi) {
                *(uint32_t*)(outHi + (size_t)r0 * Nout + c)       = pack_hi2(v[0], v[1]);
                *(uint32_t*)(outHi + (size_t)(r0 + 8) * Nout + c) = pack_hi2(v[2], v[3]);
                *(uint32_t*)(outLo + (size_t)r0 * Nout + c)       = pack_lo2(v[0], v[1]);
                *(uint32_t*)(outLo + (size_t)(r0 + 8) * Nout + c) = pack_lo2(v[2], v[3]);
            }
        }
    }
}

// ===================== tensor-core LSTM (gate-interleaved, 2 CTA/SM) =========
// Block = 64 nodes, 8 warps (wm: M half, wn: N quarter). Gates permuted so
// each thread owns i/f/g/o of its units in registers — no gate smem staging.
#define LP2 144                 // 72 bf16 pitch
#define S_WHH_HI 0
#define S_WHH_LO 36864
#define S_H_HI   73728
#define S_H_LO   82944
#define LSTM_MMA_SMEM 92160

__global__ void __launch_bounds__(256, 2)
k_lstm_mma(const float* __restrict__ pre,
           const __nv_bfloat16* __restrict__ whhHi, const __nv_bfloat16* __restrict__ whhLo,
           __nv_bfloat16* __restrict__ yHi, __nv_bfloat16* __restrict__ yLo,
           float* __restrict__ outFinal) {
    extern __shared__ char sm[];
    uint32_t sA = smem_u32(sm);
    int tid = threadIdx.x, wid = tid >> 5, lane = tid & 31;
    int wm = wid & 1, wn = wid >> 1;
    int nodeBase = blockIdx.x * 64;

    // load permuted whh planes (256 rows x 64 k)
    for (int idx = tid; idx < 2048; idx += 256) {
        int r = idx >> 3, c = idx & 7;
        cp16(sA + S_WHH_HI + r * LP2 + c * 16, whhHi + r * 64 + c * 8);
        cp16(sA + S_WHH_LO + r * LP2 + c * 16, whhLo + r * 64 + c * 8);
    }
    for (int idx = tid; idx < 4608; idx += 256)
        ((uint32_t*)(sm + S_H_HI))[idx] = 0;
    cp_commit(); cp_wait0();
    __syncthreads();

    uint32_t aOff = (uint32_t)((wm * 32 + (lane & 15)) * LP2 + (lane >> 4) * 16);
    uint32_t bOff = (uint32_t)((wn * 64 + (lane & 7) + ((lane >> 4) << 3)) * LP2 +
                               ((lane >> 3) & 1) * 16);
    float cst[16];
#pragma unroll
    for (int w = 0; w < 16; w++) cst[w] = 0.0f;

    for (int t = 0; t < T_STEPS; t++) {
        // ---- gates_acc = h @ Whh^T (bf16x3) ----
        float acc[2][8][4];
#pragma unroll
        for (int i = 0; i < 2; i++)
#pragma unroll
            for (int j = 0; j < 8; j++)
#pragma unroll
                for (int r = 0; r < 4; r++) acc[i][j][r] = 0.0f;

#pragma unroll
        for (int ks = 0; ks < 4; ks++) {
            uint32_t ka = ks * 32;
            uint32_t bh[4][4], bl[4][4];
#pragma unroll
            for (int j2 = 0; j2 < 4; j2++) {
                ldsm_x4(bh[j2], sA + S_WHH_HI + bOff + j2 * (16 * LP2) + ka);
                ldsm_x4(bl[j2], sA + S_WHH_LO + bOff + j2 * (16 * LP2) + ka);
            }
#pragma unroll
            for (int i = 0; i < 2; i++) {
                uint32_t ah[4], al[4];
                ldsm_x4(ah, sA + S_H_HI + aOff + i * (16 * LP2) + ka);
                ldsm_x4(al, sA + S_H_LO + aOff + i * (16 * LP2) + ka);
#pragma unroll
                for (int j = 0; j < 8; j++) {
                    mma16816(acc[i][j], ah, &bh[j >> 1][(j & 1) * 2]);
                    mma16816(acc[i][j], ah, &bl[j >> 1][(j & 1) * 2]);
                    mma16816(acc[i][j], al, &bh[j >> 1][(j & 1) * 2]);
                }
            }
        }
        __syncthreads();   // all warps done reading h planes

        // ---- gate nonlinearity (all 4 gates in-register) ----
#pragma unroll
        for (int i = 0; i < 2; i++) {
            int rbase = wm * 32 + i * 16 + (lane >> 2);
#pragma unroll
            for (int rr = 0; rr < 2; rr++) {
                int row = rbase + rr * 8;
                int n = nodeBase + row;
                bool valid = n < NN;
                const float* pp = pre + ((size_t)t * NN + n) * G4;
#pragma unroll
                for (int gl = 0; gl < 2; gl++) {
                    int cb = wn * 64 + gl * 32 + (lane & 3) * 2;
                    float2 p0 = make_float2(0.f, 0.f), p1 = p0, p2 = p0, p3 = p0;
                    if (valid) {
                        p0 = *(const float2*)(pp + cb);
                        p1 = *(const float2*)(pp + cb + 8);
                        p2 = *(const float2*)(pp + cb + 16);
                        p3 = *(const float2*)(pp + cb + 24);
                    }
                    float hn2[2];
#pragma unroll
                    for (int vv = 0; vv < 2; vv++) {
                        int w = i * 8 + rr * 4 + gl * 2 + vv;
                        float gi = acc[i][gl * 4 + 0][rr * 2 + vv] + (vv ? p0.y : p0.x);
                        float gf = acc[i][gl * 4 + 1][rr * 2 + vv] + (vv ? p1.y : p1.x);
                        float gg = acc[i][gl * 4 + 2][rr * 2 + vv] + (vv ? p2.y : p2.x);
                        float go = acc[i][gl * 4 + 3][rr * 2 + vv] + (vv ? p3.y : p3.x);
                        float ig = sigmoidf_(gi);
                        float fg = sigmoidf_(gf);
                        float gt = tanhf_(gg);
                        float og = sigmoidf_(go);
                        float cn = fg * cst[w] + ig * gt;
                        cst[w] = cn;
                        hn2[vv] = og * tanhf_(cn);
                    }
                    int u = (wn * 2 + gl) * 8 + (lane & 3) * 2;   // even
                    uint32_t hi2 = pack_hi2(hn2[0], hn2[1]);
                    uint32_t lo2 = pack_lo2(hn2[0], hn2[1]);
                    *(uint32_t*)(sm + S_H_HI + row * LP2 + u * 2) = hi2;
                    *(uint32_t*)(sm + S_H_LO + row * LP2 + u * 2) = lo2;
                    if (valid) {
                        if (yHi) {
                            size_t o = ((size_t)t * NN + n) * OUTD + u;
                            *(uint32_t*)(yHi + o) = hi2;
                            *(uint32_t*)(yLo + o) = lo2;
                        }
                        if (outFinal && t == T_STEPS - 1)
                            *(float2*)(outFinal + (size_t)n * OUTD + u) =
                                make_float2(hn2[0], hn2[1]);
                    }
                }
            }
        }
        __syncthreads();   // h writes visible before next step's MMA
    }
}

// ===================== host =====================
extern "C" void kernel_launch(void* const* d_in, const int* in_sizes, int n_in,
                              void* d_out, int out_size) {
    const float* x   = (const float*)d_in[0];
    const int*   ei  = (const int*)d_in[1];
    const int*   src = ei;
    const int*   dst = ei + EE;
    const float* wg[3] = {(const float*)d_in[2], (const float*)d_in[4], (const float*)d_in[6]};
    const float* bg[3] = {(const float*)d_in[3], (const float*)d_in[5], (const float*)d_in[7]};
    const float* bnG[2] = {(const float*)d_in[8],  (const float*)d_in[12]};
    const float* bnB[2] = {(const float*)d_in[9],  (const float*)d_in[13]};
    const float* bnM[2] = {(const float*)d_in[10], (const float*)d_in[14]};
    const float* bnV[2] = {(const float*)d_in[11], (const float*)d_in[15]};
    const float* wih[3] = {(const float*)d_in[16], (const float*)d_in[20], (const float*)d_in[24]};
    const float* whh[3] = {(const float*)d_in[17], (const float*)d_in[21], (const float*)d_in[25]};
    const float* bih[3] = {(const float*)d_in[18], (const float*)d_in[22], (const float*)d_in[26]};
    const float* bhh[3] = {(const float*)d_in[19], (const float*)d_in[23], (const float*)d_in[27]};
    float* out = (float*)d_out;

    float *p_h, *p_pre, *p_bias;
    __nv_bfloat16 *p_aHi, *p_aLo, *p_hHi, *p_hLo, *p_yAHi, *p_yALo, *p_yBHi, *p_yBLo, *p_wHi, *p_wLo;
    cudaGetSymbolAddress((void**)&p_h,    g_h);
    cudaGetSymbolAddress((void**)&p_pre,  g_pre);
    cudaGetSymbolAddress((void**)&p_bias, g_biasc);
    cudaGetSymbolAddress((void**)&p_aHi,  g_aHi);
    cudaGetSymbolAddress((void**)&p_aLo,  g_aLo);
    cudaGetSymbolAddress((void**)&p_hHi,  g_hHi);
    cudaGetSymbolAddress((void**)&p_hLo,  g_hLo);
    cudaGetSymbolAddress((void**)&p_yAHi, g_yAHi);
    cudaGetSymbolAddress((void**)&p_yALo, g_yALo);
    cudaGetSymbolAddress((void**)&p_yBHi, g_yBHi);
    cudaGetSymbolAddress((void**)&p_yBLo, g_yBLo);
    cudaGetSymbolAddress((void**)&p_wHi,  g_wHi);
    cudaGetSymbolAddress((void**)&p_wLo,  g_wLo);

    const int SM1 = 40960;   // K=32: single buffer
    const int SM2 = 81920;   // K=64/128: double buffer
    cudaFuncSetAttribute(k_gemm_mma<32>,  cudaFuncAttributeMaxDynamicSharedMemorySize, SM1);
    cudaFuncSetAttribute(k_gemm_mma<64>,  cudaFuncAttributeMaxDynamicSharedMemorySize, SM2);
    cudaFuncSetAttribute(k_gemm_mma<128>, cudaFuncAttributeMaxDynamicSharedMemorySize, SM2);
    cudaFuncSetAttribute(k_lstm_mma, cudaFuncAttributeMaxDynamicSharedMemorySize, LSTM_MMA_SMEM);

    // ---- setup ----
    k_zero_cnt<<<(NN + 255) / 256, 256>>>();
    k_hist<<<(EE + 255) / 256, 256>>>(dst);
    k_scanfused<<<1, 1024>>>();
    k_fillprep<<<FILL_BLOCKS + PREP_BLOCKS, 256>>>(
        src, dst, wg[0], wg[1], wg[2], wih[0], wih[1], wih[2],
        whh[0], whh[1], whh[2],
        bih[0], bhh[0], bih[1], bhh[1], bih[2], bhh[2]);

    const int MT = MROWS / 128;  // 625 M tiles

    // ---- GCN 0 ----
    k_agg<32><<<NN, 256>>>(x, p_aHi, p_aLo);
    k_gemm_mma<32><<<dim3(MT, 1), 256, SM1>>>(
        p_aHi, p_aLo, p_wHi + WO0, p_wLo + WO0, bg[0],
        bnG[0], bnB[0], bnM[0], bnV[0], 2, HID, p_h, nullptr, nullptr);
    // ---- GCN 1 ----
    k_agg<128><<<NN, 256>>>(p_h, p_aHi, p_aLo);
    k_gemm_mma<128><<<dim3(MT, 1), 256, SM2>>>(
        p_aHi, p_aLo, p_wHi + WO1, p_wLo + WO1, bg[1],
        bnG[1], bnB[1], bnM[1], bnV[1], 2, HID, p_h, nullptr, nullptr);
    // ---- GCN 2 (relu only, emit bf16 planes) ----
    k_agg<128><<<NN, 256>>>(p_h, p_aHi, p_aLo);
    k_gemm_mma<128><<<dim3(MT, 1), 256, SM2>>>(
        p_aHi, p_aLo, p_wHi + WO2, p_wLo + WO2, bg[2],
        nullptr, nullptr, nullptr, nullptr, 1, HID, nullptr, p_hHi, p_hLo);

    int lstmBlocks = (NN + 63) / 64;  // 157
    // ---- LSTM layer 0 ----
    k_gemm_mma<128><<<dim3(MT, 2), 256, SM2>>>(
        p_hHi, p_hLo, p_wHi + WO3, p_wLo + WO3, p_bias + 0 * G4,
        nullptr, nullptr, nullptr, nullptr, 0, G4, p_pre, nullptr, nullptr);
    k_lstm_mma<<<lstmBlocks, 256, LSTM_MMA_SMEM>>>(
        p_pre, p_wHi + WH0, p_wLo + WH0, p_yAHi, p_yALo, nullptr);
    // ---- LSTM layer 1 ----
    k_gemm_mma<64><<<dim3(MT, 2), 256, SM2>>>(
        p_yAHi, p_yALo, p_wHi + WO4, p_wLo + WO4, p_bias + 1 * G4,
        nullptr, nullptr, nullptr, nullptr, 0, G4, p_pre, nullptr, nullptr);
    k_lstm_mma<<<lstmBlocks, 256, LSTM_MMA_SMEM>>>(
        p_pre, p_wHi + WH1, p_wLo + WH1, p_yBHi, p_yBLo, nullptr);
    // ---- LSTM layer 2 ----
    k_gemm_mma<64><<<dim3(MT, 2), 256, SM2>>>(
        p_yBHi, p_yBLo, p_wHi + WO5, p_wLo + WO5, p_bias + 2 * G4,
        nullptr, nullptr, nullptr, nullptr, 0, G4, p_pre, nullptr, nullptr);
    k_lstm_mma<<<lstmBlocks, 256, LSTM_MMA_SMEM>>>(
        p_pre, p_wHi + WH2, p_wLo + WH2, nullptr, nullptr, out);
}

// round 9
// speedup vs baseline: 1.3204x; 1.2199x over previous
#include <cuda_runtime.h>
#include <cuda_fp16.h>
#include <math.h>
#include <stdint.h>

#define T_STEPS 8
#define NN      10000
#define EE      200000
#define FIN     32
#define HID     128
#define OUTD    64
#define G4      256            // 4*OUT
#define MROWS   (T_STEPS*NN)   // 80000
#define EPSBN   1e-5f

// weight-plane offsets ([n][k] fp16 layout, packed)
// LSTM planes (WO3.., WH..) use gate-interleaved row permutation:
//   plane row j = g*32 + q*8 + v  <->  torch row = q*64 + g*8 + v
#define WO0 0            // wg0^T   128x32
#define WO1 4096         // wg1^T   128x128
#define WO2 20480        // wg2^T   128x128
#define WO3 36864        // w_ih0   256x128 (perm)
#define WO4 69632        // w_ih1   256x64  (perm)
#define WO5 86016        // w_ih2   256x64  (perm)
#define WH0 102400       // whh0    256x64  (perm)
#define WH1 118784       // whh1    256x64  (perm)
#define WH2 135168       // whh2    256x64  (perm)
#define WTOT 151552
#define PREP_ELEMS (WTOT + 768)

// ===================== scratch (device globals) =====================
static __device__ float g_h  [MROWS*HID];      // GCN0/1 outputs (fp32, agg input)
static __device__ float g_pre[MROWS*G4];       // LSTM input projections (permuted cols)
static __device__ __half g_aH[MROWS*HID];      // agg out (fp16, single plane)
static __device__ __half g_hH[MROWS*HID];      // GCN2 out
static __device__ __half g_yA[MROWS*OUTD];
static __device__ __half g_yB[MROWS*OUTD];
static __device__ __half g_wHi[WTOT], g_wLo[WTOT];
static __device__ float g_biasc[3*G4];         // permuted
static __device__ float g_dis[NN];
static __device__ int   g_cnt[NN];
static __device__ int   g_rowptr[NN+1];
static __device__ int   g_cursor[NN];
static __device__ int   g_csr_src[EE];
static __device__ float g_csr_coef[EE];

// ===================== helpers =====================
__device__ __forceinline__ uint32_t smem_u32(const void* p) {
    uint32_t a;
    asm("{ .reg .u64 t; cvta.to.shared.u64 t, %1; cvt.u32.u64 %0, t; }" : "=r"(a) : "l"(p));
    return a;
}
__device__ __forceinline__ void cp16(uint32_t s, const void* g) {
    asm volatile("cp.async.cg.shared.global [%0], [%1], 16;" :: "r"(s), "l"(g));
}
__device__ __forceinline__ void cp_commit() {
    asm volatile("cp.async.commit_group;");
}
__device__ __forceinline__ void cp_wait0() {
    asm volatile("cp.async.wait_group 0;");
}
__device__ __forceinline__ void cp_wait1() {
    asm volatile("cp.async.wait_group 1;");
}
__device__ __forceinline__ void ldsm_x4(uint32_t* r, uint32_t addr) {
    asm volatile("ldmatrix.sync.aligned.m8n8.x4.shared.b16 {%0,%1,%2,%3}, [%4];"
                 : "=r"(r[0]), "=r"(r[1]), "=r"(r[2]), "=r"(r[3]) : "r"(addr));
}
__device__ __forceinline__ void mma16816(float* d, const uint32_t* a, const uint32_t* b) {
    asm volatile(
        "mma.sync.aligned.m16n8k16.row.col.f32.f16.f16.f32 "
        "{%0,%1,%2,%3}, {%4,%5,%6,%7}, {%8,%9}, {%0,%1,%2,%3};"
        : "+f"(d[0]), "+f"(d[1]), "+f"(d[2]), "+f"(d[3])
        : "r"(a[0]), "r"(a[1]), "r"(a[2]), "r"(a[3]), "r"(b[0]), "r"(b[1]));
}
__device__ __forceinline__ uint32_t pack_h2(float x, float y) {
    __half2 h = __floats2half2_rn(x, y);
    return *(uint32_t*)&h;
}
__device__ __forceinline__ float sigmoidf_(float x) {
    return 1.0f / (1.0f + __expf(-x));
}
__device__ __forceinline__ float tanhf_(float x) {
    return 1.0f - 2.0f / (__expf(2.0f * x) + 1.0f);
}

// ===================== setup kernels =====================
__global__ void k_zero_cnt() {
    int i = blockIdx.x * blockDim.x + threadIdx.x;
    if (i < NN) g_cnt[i] = 0;
}
__global__ void k_hist(const int* __restrict__ dst) {
    int e = blockIdx.x * blockDim.x + threadIdx.x;
    if (e < EE) atomicAdd(&g_cnt[dst[e]], 1);
}
__global__ void k_scanfused() {
    const int TPB = 1024, PER = 10;
    __shared__ int sh[TPB];
    int tid = threadIdx.x;
    for (int i = tid; i < NN; i += TPB) g_dis[i] = rsqrtf((float)g_cnt[i] + 1.0f);
    int base = tid * PER;
    int loc[PER];
    int s = 0;
#pragma unroll
    for (int i = 0; i < PER; i++) {
        int idx = base + i;
        int v = (idx < NN) ? g_cnt[idx] : 0;
        loc[i] = s; s += v;
    }
    sh[tid] = s; __syncthreads();
    for (int off = 1; off < TPB; off <<= 1) {
        int v = (tid >= off) ? sh[tid - off] : 0;
        __syncthreads();
        sh[tid] += v;
        __syncthreads();
    }
    int excl = (tid == 0) ? 0 : sh[tid - 1];
#pragma unroll
    for (int i = 0; i < PER; i++) {
        int idx = base + i;
        if (idx <= NN) g_rowptr[idx] = excl + loc[i];
    }
    __syncthreads();
    for (int i = tid; i < NN; i += TPB) g_cursor[i] = g_rowptr[i];
}

// gate-interleave permutation: plane row j -> torch row
__device__ __forceinline__ int gate_perm(int j) {
    return ((j >> 3) & 3) * 64 + (j >> 5) * 8 + (j & 7);
}

#define FILL_BLOCKS ((EE + 255) / 256)
#define PREP_BLOCKS ((PREP_ELEMS + 255) / 256)
__global__ void k_fillprep(const int* __restrict__ src, const int* __restrict__ dst,
                           const float* __restrict__ wg0, const float* __restrict__ wg1,
                           const float* __restrict__ wg2,
                           const float* __restrict__ wih0, const float* __restrict__ wih1,
                           const float* __restrict__ wih2,
                           const float* __restrict__ whh0, const float* __restrict__ whh1,
                           const float* __restrict__ whh2,
                           const float* __restrict__ bih0, const float* __restrict__ bhh0,
                           const float* __restrict__ bih1, const float* __restrict__ bhh1,
                           const float* __restrict__ bih2, const float* __restrict__ bhh2) {
    int b = blockIdx.x;
    int tid = threadIdx.x;
    if (b < FILL_BLOCKS) {
        int e = b * 256 + tid;
        if (e < EE) {
            int s = src[e], d = dst[e];
            int p = atomicAdd(&g_cursor[d], 1);
            g_csr_src[p]  = s;
            g_csr_coef[p] = g_dis[s] * g_dis[d];
        }
        return;
    }
    int idx = (b - FILL_BLOCKS) * 256 + tid;
    if (idx >= PREP_ELEMS) return;
    if (idx < WTOT) {
        float v;
        if (idx < WO1)       { int r = idx - WO0; v = wg0[(r & 31)  * HID + (r >> 5)]; }
        else if (idx < WO2)  { int r = idx - WO1; v = wg1[(r & 127) * HID + (r >> 7)]; }
        else if (idx < WO3)  { int r = idx - WO2; v = wg2[(r & 127) * HID + (r >> 7)]; }
        else if (idx < WO4)  { int l = idx - WO3; v = wih0[gate_perm(l >> 7) * 128 + (l & 127)]; }
        else if (idx < WO5)  { int l = idx - WO4; v = wih1[gate_perm(l >> 6) * 64 + (l & 63)]; }
        else if (idx < WH0)  { int l = idx - WO5; v = wih2[gate_perm(l >> 6) * 64 + (l & 63)]; }
        else if (idx < WH1)  { int l = idx - WH0; v = whh0[gate_perm(l >> 6) * 64 + (l & 63)]; }
        else if (idx < WH2)  { int l = idx - WH1; v = whh1[gate_perm(l >> 6) * 64 + (l & 63)]; }
        else                 { int l = idx - WH2; v = whh2[gate_perm(l >> 6) * 64 + (l & 63)]; }
        __half h = __float2half_rn(v);
        g_wHi[idx] = h;
        g_wLo[idx] = __float2half_rn(v - __half2float(h));
    } else {
        int r = idx - WTOT;
        int l = r >> 8, j = r & 255;
        int orig = gate_perm(j);
        const float* a = (l == 0) ? bih0 : (l == 1) ? bih1 : bih2;
        const float* c = (l == 0) ? bhh0 : (l == 1) ? bhh1 : bhh2;
        g_biasc[r] = a[orig] + c[orig];
    }
}

// ===================== GCN aggregation (emits fp16 plane) ====================
template <int F>
__global__ void k_agg(const float* __restrict__ in, __half* __restrict__ oH) {
    int n = blockIdx.x;
    int t = threadIdx.x >> 5;
    int lane = threadIdx.x & 31;
    int p0 = g_rowptr[n], p1 = g_rowptr[n + 1];
    float d = g_dis[n];
    float sw = d * d;
    size_t m = (size_t)t * NN + n;
    if (F == 128) {
        int c0 = lane * 4;
        float4 acc = make_float4(0.f, 0.f, 0.f, 0.f);
        for (int p = p0; p < p1; p++) {
            int s = g_csr_src[p];
            float cf = g_csr_coef[p];
            float4 v = *(const float4*)(in + ((size_t)t * NN + s) * F + c0);
            acc.x += v.x * cf; acc.y += v.y * cf;
            acc.z += v.z * cf; acc.w += v.w * cf;
        }
        float4 hv = *(const float4*)(in + m * F + c0);
        float o0 = acc.x + hv.x * sw, o1 = acc.y + hv.y * sw;
        float o2 = acc.z + hv.z * sw, o3 = acc.w + hv.w * sw;
        uint2 hi = make_uint2(pack_h2(o0, o1), pack_h2(o2, o3));
        *(uint2*)(oH + m * F + c0) = hi;
    } else {  // F == 32
        float acc = 0.0f;
        for (int p = p0; p < p1; p++) {
            int s = g_csr_src[p];
            acc += in[((size_t)t * NN + s) * F + lane] * g_csr_coef[p];
        }
        float r = acc + in[m * F + lane] * sw;
        oH[m * F + lane] = __float2half_rn(r);
    }
}

// ===================== mma.sync fp16x2 GEMM (double-buffered, 2 CTA/SM) =====
// C = A @ W^T. A: fp16 plane [M][K]; W: fp16 hi+lo planes [Nout][K].
// D = A*Whi + A*Wlo (W effectively fp32; A rounded to fp16).
// CTA tile 128x128, 256 threads (2(M)x4(N) warps), warp tile 64x32.
// K staged in KC=32 chunks, 2-buffer cp.async pipeline.
// mode: 0 = +bias ; 1 = relu(.+bias) ; 2 = bn(relu(.+bias))
template <int K>
__global__ void __launch_bounds__(256, 2)
k_gemm_mma(const __half* __restrict__ A,
           const __half* __restrict__ Whi, const __half* __restrict__ Wlo,
           const float* __restrict__ bias,
           const float* __restrict__ bng, const float* __restrict__ bnb,
           const float* __restrict__ bnm, const float* __restrict__ bnv,
           int mode, int Nout, float* __restrict__ outF,
           __half* __restrict__ outH) {
    constexpr int KC   = 32;
    constexpr int NCH  = K / KC;
    constexpr int NBUF = (NCH > 1) ? 2 : 1;
    constexpr int P    = KC + 8;           // 40 halfs
    constexpr int P2   = P * 2;            // 80 bytes
    constexpr int S    = 128 * P2;         // 10240 per plane
    constexpr int BUF  = 3 * S;            // 30720 per buffer
    extern __shared__ char sm[];
    uint32_t sA = smem_u32(sm);

    int tid = threadIdx.x, wid = tid >> 5, lane = tid & 31;
    int wm = wid & 1, wn = wid >> 1;
    int mBase = blockIdx.x * 128;
    int jBase = blockIdx.y * 128;

    float acc[4][4][4];
#pragma unroll
    for (int i = 0; i < 4; i++)
#pragma unroll
        for (int j = 0; j < 4; j++)
#pragma unroll
            for (int r = 0; r < 4; r++) acc[i][j][r] = 0.0f;

    uint32_t aOff = (uint32_t)((wm * 64 + (lane & 15)) * P2 + (lane >> 4) * 16);
    uint32_t bOff = (uint32_t)((wn * 32 + (lane & 7) + ((lane >> 4) << 3)) * P2 +
                               ((lane >> 3) & 1) * 16);

    auto stage = [&](int ch) {
        uint32_t b = sA + (uint32_t)(ch % NBUF) * BUF;
#pragma unroll
        for (int s2 = 0; s2 < 2; s2++) {
            int idx = tid + s2 * 256;
            int row = idx >> 2, c = idx & 3;
            uint32_t d = b + row * P2 + c * 16;
            size_t ga = (size_t)(mBase + row) * K + ch * KC + c * 8;
            size_t gw = (size_t)(jBase + row) * K + ch * KC + c * 8;
            cp16(d,         A + ga);
            cp16(d + S,     Whi + gw);
            cp16(d + 2 * S, Wlo + gw);
        }
        cp_commit();
    };

    stage(0);
#pragma unroll
    for (int ch = 0; ch < NCH; ch++) {
        if (ch + 1 < NCH) { stage(ch + 1); cp_wait1(); } else { cp_wait0(); }
        __syncthreads();
        uint32_t b = sA + (uint32_t)(ch % NBUF) * BUF;
#pragma unroll
        for (int ks = 0; ks < KC / 16; ks++) {
            uint32_t ka = ks * 32;
            uint32_t bh[2][4], bl[2][4];
#pragma unroll
            for (int j2 = 0; j2 < 2; j2++) {
                ldsm_x4(bh[j2], b + S + bOff + j2 * (16 * P2) + ka);
                ldsm_x4(bl[j2], b + 2 * S + bOff + j2 * (16 * P2) + ka);
            }
#pragma unroll
            for (int i = 0; i < 4; i++) {
                uint32_t ah[4];
                ldsm_x4(ah, b + aOff + i * (16 * P2) + ka);
#pragma unroll
                for (int j = 0; j < 4; j++) {
                    mma16816(acc[i][j], ah, &bh[j >> 1][(j & 1) * 2]);
                    mma16816(acc[i][j], ah, &bl[j >> 1][(j & 1) * 2]);
                }
            }
        }
        if (ch + 1 < NCH) __syncthreads();
    }

    float pb[4][2], psc[4][2], pmn[4][2], pbb[4][2];
#pragma unroll
    for (int j = 0; j < 4; j++) {
        int c = jBase + wn * 32 + j * 8 + (lane & 3) * 2;
#pragma unroll
        for (int q = 0; q < 2; q++) {
            pb[j][q] = bias ? bias[c + q] : 0.0f;
            if (mode == 2) {
                psc[j][q] = bng[c + q] * rsqrtf(bnv[c + q] + EPSBN);
                pmn[j][q] = bnm[c + q];
                pbb[j][q] = bnb[c + q];
            }
        }
    }
#pragma unroll
    for (int i = 0; i < 4; i++) {
        int r0 = mBase + wm * 64 + i * 16 + (lane >> 2);
#pragma unroll
        for (int j = 0; j < 4; j++) {
            int c = jBase + wn * 32 + j * 8 + (lane & 3) * 2;
            float v[4];
#pragma unroll
            for (int r = 0; r < 4; r++) {
                float x = acc[i][j][r] + pb[j][r & 1];
                if (mode >= 1) x = fmaxf(x, 0.0f);
                if (mode == 2) x = (x - pmn[j][r & 1]) * psc[j][r & 1] + pbb[j][r & 1];
                v[r] = x;
            }
            if (outF) {
                *(float2*)(outF + (size_t)r0 * Nout + c)       = make_float2(v[0], v[1]);
                *(float2*)(outF + (size_t)(r0 + 8) * Nout + c) = make_float2(v[2], v[3]);
            }
            if (outH) {
                *(uint32_t*)(outH + (size_t)r0 * Nout + c)       = pack_h2(v[0], v[1]);
                *(uint32_t*)(outH + (size_t)(r0 + 8) * Nout + c) = pack_h2(v[2], v[3]);
            }
        }
    }
}

// ===================== tensor-core LSTM (gate-interleaved, fp16x2) ==========
// Block = 64 nodes, 8 warps. Whh: fp16 hi+lo planes; h: single fp16 plane.
#define LP2 144                 // 72 halfs pitch
#define S_WHH_HI 0
#define S_WHH_LO 36864
#define S_H      73728
#define LSTM_MMA_SMEM 82944

__global__ void __launch_bounds__(256, 2)
k_lstm_mma(const float* __restrict__ pre,
           const __half* __restrict__ whhHi, const __half* __restrict__ whhLo,
           __half* __restrict__ yH, float* __restrict__ outFinal) {
    extern __shared__ char sm[];
    uint32_t sA = smem_u32(sm);
    int tid = threadIdx.x, wid = tid >> 5, lane = tid & 31;
    int wm = wid & 1, wn = wid >> 1;
    int nodeBase = blockIdx.x * 64;

    // load permuted whh planes (256 rows x 64 k)
    for (int idx = tid; idx < 2048; idx += 256) {
        int r = idx >> 3, c = idx & 7;
        cp16(sA + S_WHH_HI + r * LP2 + c * 16, whhHi + r * 64 + c * 8);
        cp16(sA + S_WHH_LO + r * LP2 + c * 16, whhLo + r * 64 + c * 8);
    }
    for (int idx = tid; idx < 2304; idx += 256)
        ((uint32_t*)(sm + S_H))[idx] = 0;
    cp_commit(); cp_wait0();
    __syncthreads();

    uint32_t aOff = (uint32_t)((wm * 32 + (lane & 15)) * LP2 + (lane >> 4) * 16);
    uint32_t bOff = (uint32_t)((wn * 64 + (lane & 7) + ((lane >> 4) << 3)) * LP2 +
                               ((lane >> 3) & 1) * 16);
    float cst[16];
#pragma unroll
    for (int w = 0; w < 16; w++) cst[w] = 0.0f;

    for (int t = 0; t < T_STEPS; t++) {
        // ---- gates_acc = h @ Whh^T (fp16x2) ----
        float acc[2][8][4];
#pragma unroll
        for (int i = 0; i < 2; i++)
#pragma unroll
            for (int j = 0; j < 8; j++)
#pragma unroll
                for (int r = 0; r < 4; r++) acc[i][j][r] = 0.0f;

#pragma unroll
        for (int ks = 0; ks < 4; ks++) {
            uint32_t ka = ks * 32;
            uint32_t bh[4][4], bl[4][4];
#pragma unroll
            for (int j2 = 0; j2 < 4; j2++) {
                ldsm_x4(bh[j2], sA + S_WHH_HI + bOff + j2 * (16 * LP2) + ka);
                ldsm_x4(bl[j2], sA + S_WHH_LO + bOff + j2 * (16 * LP2) + ka);
            }
#pragma unroll
            for (int i = 0; i < 2; i++) {
                uint32_t ah[4];
                ldsm_x4(ah, sA + S_H + aOff + i * (16 * LP2) + ka);
#pragma unroll
                for (int j = 0; j < 8; j++) {
                    mma16816(acc[i][j], ah, &bh[j >> 1][(j & 1) * 2]);
                    mma16816(acc[i][j], ah, &bl[j >> 1][(j & 1) * 2]);
                }
            }
        }
        __syncthreads();   // all warps done reading h plane

        // ---- gate nonlinearity (all 4 gates in-register) ----
#pragma unroll
        for (int i = 0; i < 2; i++) {
            int rbase = wm * 32 + i * 16 + (lane >> 2);
#pragma unroll
            for (int rr = 0; rr < 2; rr++) {
                int row = rbase + rr * 8;
                int n = nodeBase + row;
                bool valid = n < NN;
                const float* pp = pre + ((size_t)t * NN + n) * G4;
#pragma unroll
                for (int gl = 0; gl < 2; gl++) {
                    int cb = wn * 64 + gl * 32 + (lane & 3) * 2;
                    float2 p0 = make_float2(0.f, 0.f), p1 = p0, p2 = p0, p3 = p0;
                    if (valid) {
                        p0 = *(const float2*)(pp + cb);
                        p1 = *(const float2*)(pp + cb + 8);
                        p2 = *(const float2*)(pp + cb + 16);
                        p3 = *(const float2*)(pp + cb + 24);
                    }
                    float hn2[2];
#pragma unroll
                    for (int vv = 0; vv < 2; vv++) {
                        int w = i * 8 + rr * 4 + gl * 2 + vv;
                        float gi = acc[i][gl * 4 + 0][rr * 2 + vv] + (vv ? p0.y : p0.x);
                        float gf = acc[i][gl * 4 + 1][rr * 2 + vv] + (vv ? p1.y : p1.x);
                        float gg = acc[i][gl * 4 + 2][rr * 2 + vv] + (vv ? p2.y : p2.x);
                        float go = acc[i][gl * 4 + 3][rr * 2 + vv] + (vv ? p3.y : p3.x);
                        float ig = sigmoidf_(gi);
                        float fg = sigmoidf_(gf);
                        float gt = tanhf_(gg);
                        float og = sigmoidf_(go);
                        float cn = fg * cst[w] + ig * gt;
                        cst[w] = cn;
                        hn2[vv] = og * tanhf_(cn);
                    }
                    int u = (wn * 2 + gl) * 8 + (lane & 3) * 2;   // even
                    uint32_t hi2 = pack_h2(hn2[0], hn2[1]);
                    *(uint32_t*)(sm + S_H + row * LP2 + u * 2) = hi2;
                    if (valid) {
                        if (yH) {
                            size_t o = ((size_t)t * NN + n) * OUTD + u;
                            *(uint32_t*)(yH + o) = hi2;
                        }
                        if (outFinal && t == T_STEPS - 1)
                            *(float2*)(outFinal + (size_t)n * OUTD + u) =
                                make_float2(hn2[0], hn2[1]);
                    }
                }
            }
        }
        __syncthreads();   // h writes visible before next step's MMA
    }
}

// ===================== host =====================
extern "C" void kernel_launch(void* const* d_in, const int* in_sizes, int n_in,
                              void* d_out, int out_size) {
    const float* x   = (const float*)d_in[0];
    const int*   ei  = (const int*)d_in[1];
    const int*   src = ei;
    const int*   dst = ei + EE;
    const float* wg[3] = {(const float*)d_in[2], (const float*)d_in[4], (const float*)d_in[6]};
    const float* bg[3] = {(const float*)d_in[3], (const float*)d_in[5], (const float*)d_in[7]};
    const float* bnG[2] = {(const float*)d_in[8],  (const float*)d_in[12]};
    const float* bnB[2] = {(const float*)d_in[9],  (const float*)d_in[13]};
    const float* bnM[2] = {(const float*)d_in[10], (const float*)d_in[14]};
    const float* bnV[2] = {(const float*)d_in[11], (const float*)d_in[15]};
    const float* wih[3] = {(const float*)d_in[16], (const float*)d_in[20], (const float*)d_in[24]};
    const float* whh[3] = {(const float*)d_in[17], (const float*)d_in[21], (const float*)d_in[25]};
    const float* bih[3] = {(const float*)d_in[18], (const float*)d_in[22], (const float*)d_in[26]};
    const float* bhh[3] = {(const float*)d_in[19], (const float*)d_in[23], (const float*)d_in[27]};
    float* out = (float*)d_out;

    float *p_h, *p_pre, *p_bias;
    __half *p_aH, *p_hH, *p_yA, *p_yB, *p_wHi, *p_wLo;
    cudaGetSymbolAddress((void**)&p_h,    g_h);
    cudaGetSymbolAddress((void**)&p_pre,  g_pre);
    cudaGetSymbolAddress((void**)&p_bias, g_biasc);
    cudaGetSymbolAddress((void**)&p_aH,   g_aH);
    cudaGetSymbolAddress((void**)&p_hH,   g_hH);
    cudaGetSymbolAddress((void**)&p_yA,   g_yA);
    cudaGetSymbolAddress((void**)&p_yB,   g_yB);
    cudaGetSymbolAddress((void**)&p_wHi,  g_wHi);
    cudaGetSymbolAddress((void**)&p_wLo,  g_wLo);

    const int SM1 = 30720;   // K=32: single buffer (3 planes)
    const int SM2 = 61440;   // K=64/128: double buffer
    cudaFuncSetAttribute(k_gemm_mma<32>,  cudaFuncAttributeMaxDynamicSharedMemorySize, SM1);
    cudaFuncSetAttribute(k_gemm_mma<64>,  cudaFuncAttributeMaxDynamicSharedMemorySize, SM2);
    cudaFuncSetAttribute(k_gemm_mma<128>, cudaFuncAttributeMaxDynamicSharedMemorySize, SM2);
    cudaFuncSetAttribute(k_lstm_mma, cudaFuncAttributeMaxDynamicSharedMemorySize, LSTM_MMA_SMEM);

    // ---- setup ----
    k_zero_cnt<<<(NN + 255) / 256, 256>>>();
    k_hist<<<(EE + 255) / 256, 256>>>(dst);
    k_scanfused<<<1, 1024>>>();
    k_fillprep<<<FILL_BLOCKS + PREP_BLOCKS, 256>>>(
        src, dst, wg[0], wg[1], wg[2], wih[0], wih[1], wih[2],
        whh[0], whh[1], whh[2],
        bih[0], bhh[0], bih[1], bhh[1], bih[2], bhh[2]);

    const int MT = MROWS / 128;  // 625 M tiles

    // ---- GCN 0 ----
    k_agg<32><<<NN, 256>>>(x, p_aH);
    k_gemm_mma<32><<<dim3(MT, 1), 256, SM1>>>(
        p_aH, p_wHi + WO0, p_wLo + WO0, bg[0],
        bnG[0], bnB[0], bnM[0], bnV[0], 2, HID, p_h, nullptr);
    // ---- GCN 1 ----
    k_agg<128><<<NN, 256>>>(p_h, p_aH);
    k_gemm_mma<128><<<dim3(MT, 1), 256, SM2>>>(
        p_aH, p_wHi + WO1, p_wLo + WO1, bg[1],
        bnG[1], bnB[1], bnM[1], bnV[1], 2, HID, p_h, nullptr);
    // ---- GCN 2 (relu only, emit fp16 plane) ----
    k_agg<128><<<NN, 256>>>(p_h, p_aH);
    k_gemm_mma<128><<<dim3(MT, 1), 256, SM2>>>(
        p_aH, p_wHi + WO2, p_wLo + WO2, bg[2],
        nullptr, nullptr, nullptr, nullptr, 1, HID, nullptr, p_hH);

    int lstmBlocks = (NN + 63) / 64;  // 157
    // ---- LSTM layer 0 ----
    k_gemm_mma<128><<<dim3(MT, 2), 256, SM2>>>(
        p_hH, p_wHi + WO3, p_wLo + WO3, p_bias + 0 * G4,
        nullptr, nullptr, nullptr, nullptr, 0, G4, p_pre, nullptr);
    k_lstm_mma<<<lstmBlocks, 256, LSTM_MMA_SMEM>>>(
        p_pre, p_wHi + WH0, p_wLo + WH0, p_yA, nullptr);
    // ---- LSTM layer 1 ----
    k_gemm_mma<64><<<dim3(MT, 2), 256, SM2>>>(
        p_yA, p_wHi + WO4, p_wLo + WO4, p_bias + 1 * G4,
        nullptr, nullptr, nullptr, nullptr, 0, G4, p_pre, nullptr);
    k_lstm_mma<<<lstmBlocks, 256, LSTM_MMA_SMEM>>>(
        p_pre, p_wHi + WH1, p_wLo + WH1, p_yB, nullptr);
    // ---- LSTM layer 2 ----
    k_gemm_mma<64><<<dim3(MT, 2), 256, SM2>>>(
        p_yB, p_wHi + WO5, p_wLo + WO5, p_bias + 2 * G4,
        nullptr, nullptr, nullptr, nullptr, 0, G4, p_pre, nullptr);
    k_lstm_mma<<<lstmBlocks, 256, LSTM_MMA_SMEM>>>(
        p_pre, p_wHi + WH2, p_wLo + WH2, nullptr, out);
}

// round 10
// speedup vs baseline: 1.5352x; 1.1627x over previous
#include <cuda_runtime.h>
#include <cuda_fp16.h>
#include <math.h>
#include <stdint.h>

#define T_STEPS 8
#define NN      10000
#define EE      200000
#define FIN     32
#define HID     128
#define OUTD    64
#define G4      256            // 4*OUT
#define MROWS   (T_STEPS*NN)   // 80000
#define EPSBN   1e-5f

// weight-plane offsets ([n][k] fp16 layout, packed)
// LSTM planes (WO3.., WH..) use gate-interleaved row permutation:
//   plane row j = g*32 + q*8 + v  <->  torch row = q*64 + g*8 + v
#define WO0 0            // wg0^T   128x32
#define WO1 4096         // wg1^T   128x128
#define WO2 20480        // wg2^T   128x128
#define WO3 36864        // w_ih0   256x128 (perm)
#define WO4 69632        // w_ih1   256x64  (perm)
#define WO5 86016        // w_ih2   256x64  (perm)
#define WH0 102400       // whh0    256x64  (perm)
#define WH1 118784       // whh1    256x64  (perm)
#define WH2 135168       // whh2    256x64  (perm)
#define WTOT 151552
#define PREP_ELEMS (WTOT + 768)

// ===================== scratch (device globals) =====================
static __device__ float g_pre[MROWS*G4];       // LSTM input projections (permuted cols)
static __device__ __half g_actA[MROWS*HID];    // ping (agg out)
static __device__ __half g_actB[MROWS*HID];    // pong (GCN out)
static __device__ __half g_yA[MROWS*OUTD];
static __device__ __half g_yB[MROWS*OUTD];
static __device__ __half g_wH[WTOT];
static __device__ float g_biasc[3*G4];         // permuted
static __device__ float g_dis[NN];
static __device__ int   g_cnt[NN];
static __device__ int   g_rowptr[NN+1];
static __device__ int   g_cursor[NN];
static __device__ int   g_csr_src[EE];
static __device__ float g_csr_coef[EE];

// ===================== helpers =====================
__device__ __forceinline__ uint32_t smem_u32(const void* p) {
    uint32_t a;
    asm("{ .reg .u64 t; cvta.to.shared.u64 t, %1; cvt.u32.u64 %0, t; }" : "=r"(a) : "l"(p));
    return a;
}
__device__ __forceinline__ void cp16(uint32_t s, const void* g) {
    asm volatile("cp.async.cg.shared.global [%0], [%1], 16;" :: "r"(s), "l"(g));
}
__device__ __forceinline__ void cp_commit() {
    asm volatile("cp.async.commit_group;");
}
__device__ __forceinline__ void cp_wait0() {
    asm volatile("cp.async.wait_group 0;");
}
__device__ __forceinline__ void cp_wait1() {
    asm volatile("cp.async.wait_group 1;");
}
__device__ __forceinline__ void ldsm_x4(uint32_t* r, uint32_t addr) {
    asm volatile("ldmatrix.sync.aligned.m8n8.x4.shared.b16 {%0,%1,%2,%3}, [%4];"
                 : "=r"(r[0]), "=r"(r[1]), "=r"(r[2]), "=r"(r[3]) : "r"(addr));
}
__device__ __forceinline__ void mma16816(float* d, const uint32_t* a, const uint32_t* b) {
    asm volatile(
        "mma.sync.aligned.m16n8k16.row.col.f32.f16.f16.f32 "
        "{%0,%1,%2,%3}, {%4,%5,%6,%7}, {%8,%9}, {%0,%1,%2,%3};"
        : "+f"(d[0]), "+f"(d[1]), "+f"(d[2]), "+f"(d[3])
        : "r"(a[0]), "r"(a[1]), "r"(a[2]), "r"(a[3]), "r"(b[0]), "r"(b[1]));
}
__device__ __forceinline__ uint32_t pack_h2(float x, float y) {
    __half2 h = __floats2half2_rn(x, y);
    return *(uint32_t*)&h;
}
__device__ __forceinline__ float sigmoidf_(float x) {
    return 1.0f / (1.0f + __expf(-x));
}
__device__ __forceinline__ float tanhf_(float x) {
    return 1.0f - 2.0f / (__expf(2.0f * x) + 1.0f);
}

// ===================== setup kernels =====================
__global__ void k_zero_cnt() {
    int i = blockIdx.x * blockDim.x + threadIdx.x;
    if (i < NN) g_cnt[i] = 0;
}
__global__ void k_hist(const int* __restrict__ dst) {
    int e = blockIdx.x * blockDim.x + threadIdx.x;
    if (e < EE) atomicAdd(&g_cnt[dst[e]], 1);
}
__global__ void k_scanfused() {
    const int TPB = 1024, PER = 10;
    __shared__ int sh[TPB];
    int tid = threadIdx.x;
    for (int i = tid; i < NN; i += TPB) g_dis[i] = rsqrtf((float)g_cnt[i] + 1.0f);
    int base = tid * PER;
    int loc[PER];
    int s = 0;
#pragma unroll
    for (int i = 0; i < PER; i++) {
        int idx = base + i;
        int v = (idx < NN) ? g_cnt[idx] : 0;
        loc[i] = s; s += v;
    }
    sh[tid] = s; __syncthreads();
    for (int off = 1; off < TPB; off <<= 1) {
        int v = (tid >= off) ? sh[tid - off] : 0;
        __syncthreads();
        sh[tid] += v;
        __syncthreads();
    }
    int excl = (tid == 0) ? 0 : sh[tid - 1];
#pragma unroll
    for (int i = 0; i < PER; i++) {
        int idx = base + i;
        if (idx <= NN) g_rowptr[idx] = excl + loc[i];
    }
    __syncthreads();
    for (int i = tid; i < NN; i += TPB) g_cursor[i] = g_rowptr[i];
}

// gate-interleave permutation: plane row j -> torch row
__device__ __forceinline__ int gate_perm(int j) {
    return ((j >> 3) & 3) * 64 + (j >> 5) * 8 + (j & 7);
}

#define FILL_BLOCKS ((EE + 255) / 256)
#define PREP_BLOCKS ((PREP_ELEMS + 255) / 256)
__global__ void k_fillprep(const int* __restrict__ src, const int* __restrict__ dst,
                           const float* __restrict__ wg0, const float* __restrict__ wg1,
                           const float* __restrict__ wg2,
                           const float* __restrict__ wih0, const float* __restrict__ wih1,
                           const float* __restrict__ wih2,
                           const float* __restrict__ whh0, const float* __restrict__ whh1,
                           const float* __restrict__ whh2,
                           const float* __restrict__ bih0, const float* __restrict__ bhh0,
                           const float* __restrict__ bih1, const float* __restrict__ bhh1,
                           const float* __restrict__ bih2, const float* __restrict__ bhh2) {
    int b = blockIdx.x;
    int tid = threadIdx.x;
    if (b < FILL_BLOCKS) {
        int e = b * 256 + tid;
        if (e < EE) {
            int s = src[e], d = dst[e];
            int p = atomicAdd(&g_cursor[d], 1);
            g_csr_src[p]  = s;
            g_csr_coef[p] = g_dis[s] * g_dis[d];
        }
        return;
    }
    int idx = (b - FILL_BLOCKS) * 256 + tid;
    if (idx >= PREP_ELEMS) return;
    if (idx < WTOT) {
        float v;
        if (idx < WO1)       { int r = idx - WO0; v = wg0[(r & 31)  * HID + (r >> 5)]; }
        else if (idx < WO2)  { int r = idx - WO1; v = wg1[(r & 127) * HID + (r >> 7)]; }
        else if (idx < WO3)  { int r = idx - WO2; v = wg2[(r & 127) * HID + (r >> 7)]; }
        else if (idx < WO4)  { int l = idx - WO3; v = wih0[gate_perm(l >> 7) * 128 + (l & 127)]; }
        else if (idx < WO5)  { int l = idx - WO4; v = wih1[gate_perm(l >> 6) * 64 + (l & 63)]; }
        else if (idx < WH0)  { int l = idx - WO5; v = wih2[gate_perm(l >> 6) * 64 + (l & 63)]; }
        else if (idx < WH1)  { int l = idx - WH0; v = whh0[gate_perm(l >> 6) * 64 + (l & 63)]; }
        else if (idx < WH2)  { int l = idx - WH1; v = whh1[gate_perm(l >> 6) * 64 + (l & 63)]; }
        else                 { int l = idx - WH2; v = whh2[gate_perm(l >> 6) * 64 + (l & 63)]; }
        g_wH[idx] = __float2half_rn(v);
    } else {
        int r = idx - WTOT;
        int l = r >> 8, j = r & 255;
        int orig = gate_perm(j);
        const float* a = (l == 0) ? bih0 : (l == 1) ? bih1 : bih2;
        const float* c = (l == 0) ? bhh0 : (l == 1) ? bhh1 : bhh2;
        g_biasc[r] = a[orig] + c[orig];
    }
}

// ===================== GCN aggregation =====================
// layer 0: fp32 x input -> fp16 out
__global__ void k_agg32(const float* __restrict__ in, __half* __restrict__ oH) {
    int n = blockIdx.x;
    int t = threadIdx.x >> 5;
    int lane = threadIdx.x & 31;
    int p0 = g_rowptr[n], p1 = g_rowptr[n + 1];
    float d = g_dis[n];
    float sw = d * d;
    size_t m = (size_t)t * NN + n;
    float acc = 0.0f;
    for (int p = p0; p < p1; p++) {
        int s = g_csr_src[p];
        acc += in[((size_t)t * NN + s) * FIN + lane] * g_csr_coef[p];
    }
    float r = acc + in[m * FIN + lane] * sw;
    oH[m * FIN + lane] = __float2half_rn(r);
}

// layers 1/2: fp16 input gather -> fp16 out (half the L2 bytes)
__global__ void k_aggh(const __half* __restrict__ in, __half* __restrict__ oH) {
    int n = blockIdx.x;
    int t = threadIdx.x >> 5;
    int lane = threadIdx.x & 31;
    int p0 = g_rowptr[n], p1 = g_rowptr[n + 1];
    float d = g_dis[n];
    float sw = d * d;
    size_t m = (size_t)t * NN + n;
    int c0 = lane * 4;
    float acc0 = 0.f, acc1 = 0.f, acc2 = 0.f, acc3 = 0.f;
    for (int p = p0; p < p1; p++) {
        int s = g_csr_src[p];
        float cf = g_csr_coef[p];
        uint2 v = *(const uint2*)(in + ((size_t)t * NN + s) * HID + c0);
        float2 a = __half22float2(*(__half2*)&v.x);
        float2 b = __half22float2(*(__half2*)&v.y);
        acc0 += a.x * cf; acc1 += a.y * cf;
        acc2 += b.x * cf; acc3 += b.y * cf;
    }
    uint2 hv = *(const uint2*)(in + m * HID + c0);
    float2 ha = __half22float2(*(__half2*)&hv.x);
    float2 hb = __half22float2(*(__half2*)&hv.y);
    acc0 += ha.x * sw; acc1 += ha.y * sw;
    acc2 += hb.x * sw; acc3 += hb.y * sw;
    uint2 o = make_uint2(pack_h2(acc0, acc1), pack_h2(acc2, acc3));
    *(uint2*)(oH + m * HID + c0) = o;
}

// ===================== mma.sync fp16 GEMM (double-buffered, 2 CTA/SM) =======
// C = A @ W^T. A: fp16 [M][K]; W: fp16 [Nout][K]. Single MMA pass.
// CTA tile 128x128, 256 threads (2(M)x4(N) warps), warp tile 64x32.
// K staged in KC=32 chunks, 2-buffer cp.async pipeline.
// mode: 0 = +bias ; 1 = relu(.+bias) ; 2 = bn(relu(.+bias))
template <int K>
__global__ void __launch_bounds__(256, 2)
k_gemm_mma(const __half* __restrict__ A, const __half* __restrict__ W,
           const float* __restrict__ bias,
           const float* __restrict__ bng, const float* __restrict__ bnb,
           const float* __restrict__ bnm, const float* __restrict__ bnv,
           int mode, int Nout, float* __restrict__ outF,
           __half* __restrict__ outH) {
    constexpr int KC   = 32;
    constexpr int NCH  = K / KC;
    constexpr int NBUF = (NCH > 1) ? 2 : 1;
    constexpr int P    = KC + 8;           // 40 halfs
    constexpr int P2   = P * 2;            // 80 bytes
    constexpr int S    = 128 * P2;         // 10240 per plane
    constexpr int BUF  = 2 * S;            // 20480 per buffer
    extern __shared__ char sm[];
    uint32_t sA = smem_u32(sm);

    int tid = threadIdx.x, wid = tid >> 5, lane = tid & 31;
    int wm = wid & 1, wn = wid >> 1;
    int mBase = blockIdx.x * 128;
    int jBase = blockIdx.y * 128;

    float acc[4][4][4];
#pragma unroll
    for (int i = 0; i < 4; i++)
#pragma unroll
        for (int j = 0; j < 4; j++)
#pragma unroll
            for (int r = 0; r < 4; r++) acc[i][j][r] = 0.0f;

    uint32_t aOff = (uint32_t)((wm * 64 + (lane & 15)) * P2 + (lane >> 4) * 16);
    uint32_t bOff = (uint32_t)((wn * 32 + (lane & 7) + ((lane >> 4) << 3)) * P2 +
                               ((lane >> 3) & 1) * 16);

    auto stage = [&](int ch) {
        uint32_t b = sA + (uint32_t)(ch % NBUF) * BUF;
#pragma unroll
        for (int s2 = 0; s2 < 2; s2++) {
            int idx = tid + s2 * 256;
            int row = idx >> 2, c = idx & 3;
            uint32_t d = b + row * P2 + c * 16;
            size_t ga = (size_t)(mBase + row) * K + ch * KC + c * 8;
            size_t gw = (size_t)(jBase + row) * K + ch * KC + c * 8;
            cp16(d,     A + ga);
            cp16(d + S, W + gw);
        }
        cp_commit();
    };

    stage(0);
#pragma unroll
    for (int ch = 0; ch < NCH; ch++) {
        if (ch + 1 < NCH) { stage(ch + 1); cp_wait1(); } else { cp_wait0(); }
        __syncthreads();
        uint32_t b = sA + (uint32_t)(ch % NBUF) * BUF;
#pragma unroll
        for (int ks = 0; ks < KC / 16; ks++) {
            uint32_t ka = ks * 32;
            uint32_t bh[2][4];
#pragma unroll
            for (int j2 = 0; j2 < 2; j2++)
                ldsm_x4(bh[j2], b + S + bOff + j2 * (16 * P2) + ka);
#pragma unroll
            for (int i = 0; i < 4; i++) {
                uint32_t ah[4];
                ldsm_x4(ah, b + aOff + i * (16 * P2) + ka);
#pragma unroll
                for (int j = 0; j < 4; j++)
                    mma16816(acc[i][j], ah, &bh[j >> 1][(j & 1) * 2]);
            }
        }
        if (ch + 1 < NCH) __syncthreads();
    }

    float pb[4][2], psc[4][2], pmn[4][2], pbb[4][2];
#pragma unroll
    for (int j = 0; j < 4; j++) {
        int c = jBase + wn * 32 + j * 8 + (lane & 3) * 2;
#pragma unroll
        for (int q = 0; q < 2; q++) {
            pb[j][q] = bias ? bias[c + q] : 0.0f;
            if (mode == 2) {
                psc[j][q] = bng[c + q] * rsqrtf(bnv[c + q] + EPSBN);
                pmn[j][q] = bnm[c + q];
                pbb[j][q] = bnb[c + q];
            }
        }
    }
#pragma unroll
    for (int i = 0; i < 4; i++) {
        int r0 = mBase + wm * 64 + i * 16 + (lane >> 2);
#pragma unroll
        for (int j = 0; j < 4; j++) {
            int c = jBase + wn * 32 + j * 8 + (lane & 3) * 2;
            float v[4];
#pragma unroll
            for (int r = 0; r < 4; r++) {
                float x = acc[i][j][r] + pb[j][r & 1];
                if (mode >= 1) x = fmaxf(x, 0.0f);
                if (mode == 2) x = (x - pmn[j][r & 1]) * psc[j][r & 1] + pbb[j][r & 1];
                v[r] = x;
            }
            if (outF) {
                *(float2*)(outF + (size_t)r0 * Nout + c)       = make_float2(v[0], v[1]);
                *(float2*)(outF + (size_t)(r0 + 8) * Nout + c) = make_float2(v[2], v[3]);
            }
            if (outH) {
                *(uint32_t*)(outH + (size_t)r0 * Nout + c)       = pack_h2(v[0], v[1]);
                *(uint32_t*)(outH + (size_t)(r0 + 8) * Nout + c) = pack_h2(v[2], v[3]);
            }
        }
    }
}

// ===================== tensor-core LSTM (gate-interleaved, fp16) ============
// Block = 64 nodes, 8 warps. Whh: fp16 plane; h: fp16 plane. Single MMA pass.
#define LP2 144                 // 72 halfs pitch
#define S_WHH 0
#define S_H   36864
#define LSTM_MMA_SMEM 46080

__global__ void __launch_bounds__(256, 2)
k_lstm_mma(const float* __restrict__ pre, const __half* __restrict__ whh,
           __half* __restrict__ yH, float* __restrict__ outFinal) {
    extern __shared__ char sm[];
    uint32_t sA = smem_u32(sm);
    int tid = threadIdx.x, wid = tid >> 5, lane = tid & 31;
    int wm = wid & 1, wn = wid >> 1;
    int nodeBase = blockIdx.x * 64;

    // load permuted whh plane (256 rows x 64 k)
    for (int idx = tid; idx < 2048; idx += 256) {
        int r = idx >> 3, c = idx & 7;
        cp16(sA + S_WHH + r * LP2 + c * 16, whh + r * 64 + c * 8);
    }
    for (int idx = tid; idx < 2304; idx += 256)
        ((uint32_t*)(sm + S_H))[idx] = 0;
    cp_commit(); cp_wait0();
    __syncthreads();

    uint32_t aOff = (uint32_t)((wm * 32 + (lane & 15)) * LP2 + (lane >> 4) * 16);
    uint32_t bOff = (uint32_t)((wn * 64 + (lane & 7) + ((lane >> 4) << 3)) * LP2 +
                               ((lane >> 3) & 1) * 16);
    float cst[16];
#pragma unroll
    for (int w = 0; w < 16; w++) cst[w] = 0.0f;

    for (int t = 0; t < T_STEPS; t++) {
        // ---- gates_acc = h @ Whh^T (fp16, single pass) ----
        float acc[2][8][4];
#pragma unroll
        for (int i = 0; i < 2; i++)
#pragma unroll
            for (int j = 0; j < 8; j++)
#pragma unroll
                for (int r = 0; r < 4; r++) acc[i][j][r] = 0.0f;

#pragma unroll
        for (int ks = 0; ks < 4; ks++) {
            uint32_t ka = ks * 32;
            uint32_t bh[4][4];
#pragma unroll
            for (int j2 = 0; j2 < 4; j2++)
                ldsm_x4(bh[j2], sA + S_WHH + bOff + j2 * (16 * LP2) + ka);
#pragma unroll
            for (int i = 0; i < 2; i++) {
                uint32_t ah[4];
                ldsm_x4(ah, sA + S_H + aOff + i * (16 * LP2) + ka);
#pragma unroll
                for (int j = 0; j < 8; j++)
                    mma16816(acc[i][j], ah, &bh[j >> 1][(j & 1) * 2]);
            }
        }
        __syncthreads();   // all warps done reading h plane

        // ---- gate nonlinearity (all 4 gates in-register) ----
#pragma unroll
        for (int i = 0; i < 2; i++) {
            int rbase = wm * 32 + i * 16 + (lane >> 2);
#pragma unroll
            for (int rr = 0; rr < 2; rr++) {
                int row = rbase + rr * 8;
                int n = nodeBase + row;
                bool valid = n < NN;
                const float* pp = pre + ((size_t)t * NN + n) * G4;
#pragma unroll
                for (int gl = 0; gl < 2; gl++) {
                    int cb = wn * 64 + gl * 32 + (lane & 3) * 2;
                    float2 p0 = make_float2(0.f, 0.f), p1 = p0, p2 = p0, p3 = p0;
                    if (valid) {
                        p0 = *(const float2*)(pp + cb);
                        p1 = *(const float2*)(pp + cb + 8);
                        p2 = *(const float2*)(pp + cb + 16);
                        p3 = *(const float2*)(pp + cb + 24);
                    }
                    float hn2[2];
#pragma unroll
                    for (int vv = 0; vv < 2; vv++) {
                        int w = i * 8 + rr * 4 + gl * 2 + vv;
                        float gi = acc[i][gl * 4 + 0][rr * 2 + vv] + (vv ? p0.y : p0.x);
                        float gf = acc[i][gl * 4 + 1][rr * 2 + vv] + (vv ? p1.y : p1.x);
                        float gg = acc[i][gl * 4 + 2][rr * 2 + vv] + (vv ? p2.y : p2.x);
                        float go = acc[i][gl * 4 + 3][rr * 2 + vv] + (vv ? p3.y : p3.x);
                        float ig = sigmoidf_(gi);
                        float fg = sigmoidf_(gf);
                        float gt = tanhf_(gg);
                        float og = sigmoidf_(go);
                        float cn = fg * cst[w] + ig * gt;
                        cst[w] = cn;
                        hn2[vv] = og * tanhf_(cn);
                    }
                    int u = (wn * 2 + gl) * 8 + (lane & 3) * 2;   // even
                    uint32_t hi2 = pack_h2(hn2[0], hn2[1]);
                    *(uint32_t*)(sm + S_H + row * LP2 + u * 2) = hi2;
                    if (valid) {
                        if (yH) {
                            size_t o = ((size_t)t * NN + n) * OUTD + u;
                            *(uint32_t*)(yH + o) = hi2;
                        }
                        if (outFinal && t == T_STEPS - 1)
                            *(float2*)(outFinal + (size_t)n * OUTD + u) =
                                make_float2(hn2[0], hn2[1]);
                    }
                }
            }
        }
        __syncthreads();   // h writes visible before next step's MMA
    }
}

// ===================== host =====================
extern "C" void kernel_launch(void* const* d_in, const int* in_sizes, int n_in,
                              void* d_out, int out_size) {
    const float* x   = (const float*)d_in[0];
    const int*   ei  = (const int*)d_in[1];
    const int*   src = ei;
    const int*   dst = ei + EE;
    const float* wg[3] = {(const float*)d_in[2], (const float*)d_in[4], (const float*)d_in[6]};
    const float* bg[3] = {(const float*)d_in[3], (const float*)d_in[5], (const float*)d_in[7]};
    const float* bnG[2] = {(const float*)d_in[8],  (const float*)d_in[12]};
    const float* bnB[2] = {(const float*)d_in[9],  (const float*)d_in[13]};
    const float* bnM[2] = {(const float*)d_in[10], (const float*)d_in[14]};
    const float* bnV[2] = {(const float*)d_in[11], (const float*)d_in[15]};
    const float* wih[3] = {(const float*)d_in[16], (const float*)d_in[20], (const float*)d_in[24]};
    const float* whh[3] = {(const float*)d_in[17], (const float*)d_in[21], (const float*)d_in[25]};
    const float* bih[3] = {(const float*)d_in[18], (const float*)d_in[22], (const float*)d_in[26]};
    const float* bhh[3] = {(const float*)d_in[19], (const float*)d_in[23], (const float*)d_in[27]};
    float* out = (float*)d_out;

    float *p_pre, *p_bias;
    __half *p_actA, *p_actB, *p_yA, *p_yB, *p_wH;
    cudaGetSymbolAddress((void**)&p_pre,  g_pre);
    cudaGetSymbolAddress((void**)&p_bias, g_biasc);
    cudaGetSymbolAddress((void**)&p_actA, g_actA);
    cudaGetSymbolAddress((void**)&p_actB, g_actB);
    cudaGetSymbolAddress((void**)&p_yA,   g_yA);
    cudaGetSymbolAddress((void**)&p_yB,   g_yB);
    cudaGetSymbolAddress((void**)&p_wH,   g_wH);

    const int SM1 = 20480;   // K=32: single buffer (2 planes)
    const int SM2 = 40960;   // K=64/128: double buffer
    cudaFuncSetAttribute(k_gemm_mma<32>,  cudaFuncAttributeMaxDynamicSharedMemorySize, SM1);
    cudaFuncSetAttribute(k_gemm_mma<64>,  cudaFuncAttributeMaxDynamicSharedMemorySize, SM2);
    cudaFuncSetAttribute(k_gemm_mma<128>, cudaFuncAttributeMaxDynamicSharedMemorySize, SM2);
    cudaFuncSetAttribute(k_lstm_mma, cudaFuncAttributeMaxDynamicSharedMemorySize, LSTM_MMA_SMEM);

    // ---- setup ----
    k_zero_cnt<<<(NN + 255) / 256, 256>>>();
    k_hist<<<(EE + 255) / 256, 256>>>(dst);
    k_scanfused<<<1, 1024>>>();
    k_fillprep<<<FILL_BLOCKS + PREP_BLOCKS, 256>>>(
        src, dst, wg[0], wg[1], wg[2], wih[0], wih[1], wih[2],
        whh[0], whh[1], whh[2],
        bih[0], bhh[0], bih[1], bhh[1], bih[2], bhh[2]);

    const int MT = MROWS / 128;  // 625 M tiles

    // ---- GCN 0 ----
    k_agg32<<<NN, 256>>>(x, p_actA);
    k_gemm_mma<32><<<dim3(MT, 1), 256, SM1>>>(
        p_actA, p_wH + WO0, bg[0],
        bnG[0], bnB[0], bnM[0], bnV[0], 2, HID, nullptr, p_actB);
    // ---- GCN 1 ----
    k_aggh<<<NN, 256>>>(p_actB, p_actA);
    k_gemm_mma<128><<<dim3(MT, 1), 256, SM2>>>(
        p_actA, p_wH + WO1, bg[1],
        bnG[1], bnB[1], bnM[1], bnV[1], 2, HID, nullptr, p_actB);
    // ---- GCN 2 (relu only) ----
    k_aggh<<<NN, 256>>>(p_actB, p_actA);
    k_gemm_mma<128><<<dim3(MT, 1), 256, SM2>>>(
        p_actA, p_wH + WO2, bg[2],
        nullptr, nullptr, nullptr, nullptr, 1, HID, nullptr, p_actB);

    int lstmBlocks = (NN + 63) / 64;  // 157
    // ---- LSTM layer 0 ----
    k_gemm_mma<128><<<dim3(MT, 2), 256, SM2>>>(
        p_actB, p_wH + WO3, p_bias + 0 * G4,
        nullptr, nullptr, nullptr, nullptr, 0, G4, p_pre, nullptr);
    k_lstm_mma<<<lstmBlocks, 256, LSTM_MMA_SMEM>>>(
        p_pre, p_wH + WH0, p_yA, nullptr);
    // ---- LSTM layer 1 ----
    k_gemm_mma<64><<<dim3(MT, 2), 256, SM2>>>(
        p_yA, p_wH + WO4, p_bias + 1 * G4,
        nullptr, nullptr, nullptr, nullptr, 0, G4, p_pre, nullptr);
    k_lstm_mma<<<lstmBlocks, 256, LSTM_MMA_SMEM>>>(
        p_pre, p_wH + WH1, p_yB, nullptr);
    // ---- LSTM layer 2 ----
    k_gemm_mma<64><<<dim3(MT, 2), 256, SM2>>>(
        p_yB, p_wH + WO5, p_bias + 2 * G4,
        nullptr, nullptr, nullptr, nullptr, 0, G4, p_pre, nullptr);
    k_lstm_mma<<<lstmBlocks, 256, LSTM_MMA_SMEM>>>(
        p_pre, p_wH + WH2, nullptr, out);
}

// round 11
// speedup vs baseline: 1.7002x; 1.1075x over previous
#include <cuda_runtime.h>
#include <cuda_fp16.h>
#include <math.h>
#include <stdint.h>

#define T_STEPS 8
#define NN      10000
#define EE      200000
#define FIN     32
#define HID     128
#define OUTD    64
#define G4      256            // 4*OUT
#define MROWS   (T_STEPS*NN)   // 80000
#define EPSBN   1e-5f

// weight-plane offsets ([n][k] fp16 layout, packed)
// LSTM planes (WO3.., WH..) use gate-interleaved row permutation:
//   plane row j = g*32 + q*8 + v  <->  torch row = q*64 + g*8 + v
#define WO0 0            // wg0^T   128x32
#define WO1 4096         // wg1^T   128x128
#define WO2 20480        // wg2^T   128x128
#define WO3 36864        // w_ih0   256x128 (perm)
#define WO4 69632        // w_ih1   256x64  (perm)
#define WO5 86016        // w_ih2   256x64  (perm)
#define WH0 102400       // whh0    256x64  (perm)
#define WH1 118784       // whh1    256x64  (perm)
#define WH2 135168       // whh2    256x64  (perm)
#define WTOT 151552
#define PREP_ELEMS (WTOT + 768)

// ===================== scratch (device globals) =====================
static __device__ __half g_preH[MROWS*G4];     // LSTM input projections (fp16, permuted)
static __device__ __half g_xH  [MROWS*FIN];    // x converted to fp16
static __device__ __half g_actA[MROWS*HID];    // ping (agg out)
static __device__ __half g_actB[MROWS*HID];    // pong (GCN out)
static __device__ __half g_yA[MROWS*OUTD];
static __device__ __half g_yB[MROWS*OUTD];
static __device__ __half g_wH[WTOT];
static __device__ float g_biasc[3*G4];         // permuted
static __device__ float g_dis[NN];
static __device__ int   g_cnt[NN];
static __device__ int   g_rowptr[NN+1];
static __device__ int   g_cursor[NN];
static __device__ int   g_csr_src[EE];
static __device__ float g_csr_coef[EE];

// ===================== helpers =====================
__device__ __forceinline__ uint32_t smem_u32(const void* p) {
    uint32_t a;
    asm("{ .reg .u64 t; cvta.to.shared.u64 t, %1; cvt.u32.u64 %0, t; }" : "=r"(a) : "l"(p));
    return a;
}
__device__ __forceinline__ void cp16(uint32_t s, const void* g) {
    asm volatile("cp.async.cg.shared.global [%0], [%1], 16;" :: "r"(s), "l"(g));
}
__device__ __forceinline__ void cp_commit() {
    asm volatile("cp.async.commit_group;");
}
__device__ __forceinline__ void cp_wait0() {
    asm volatile("cp.async.wait_group 0;");
}
__device__ __forceinline__ void cp_wait1() {
    asm volatile("cp.async.wait_group 1;");
}
__device__ __forceinline__ void ldsm_x4(uint32_t* r, uint32_t addr) {
    asm volatile("ldmatrix.sync.aligned.m8n8.x4.shared.b16 {%0,%1,%2,%3}, [%4];"
                 : "=r"(r[0]), "=r"(r[1]), "=r"(r[2]), "=r"(r[3]) : "r"(addr));
}
__device__ __forceinline__ void mma16816(float* d, const uint32_t* a, const uint32_t* b) {
    asm volatile(
        "mma.sync.aligned.m16n8k16.row.col.f32.f16.f16.f32 "
        "{%0,%1,%2,%3}, {%4,%5,%6,%7}, {%8,%9}, {%0,%1,%2,%3};"
        : "+f"(d[0]), "+f"(d[1]), "+f"(d[2]), "+f"(d[3])
        : "r"(a[0]), "r"(a[1]), "r"(a[2]), "r"(a[3]), "r"(b[0]), "r"(b[1]));
}
__device__ __forceinline__ uint32_t pack_h2(float x, float y) {
    __half2 h = __floats2half2_rn(x, y);
    return *(uint32_t*)&h;
}
__device__ __forceinline__ float sigmoidf_(float x) {
    return 1.0f / (1.0f + __expf(-x));
}
__device__ __forceinline__ float tanhf_(float x) {
    return 1.0f - 2.0f / (__expf(2.0f * x) + 1.0f);
}

// ===================== setup kernels =====================
__global__ void k_zero_cnt() {
    int i = blockIdx.x * blockDim.x + threadIdx.x;
    if (i < NN) g_cnt[i] = 0;
}
__global__ void k_hist(const int* __restrict__ dst) {
    int e = blockIdx.x * blockDim.x + threadIdx.x;
    if (e < EE) atomicAdd(&g_cnt[dst[e]], 1);
}
__global__ void k_scanfused() {
    const int TPB = 1024, PER = 10;
    __shared__ int sh[TPB];
    int tid = threadIdx.x;
    for (int i = tid; i < NN; i += TPB) g_dis[i] = rsqrtf((float)g_cnt[i] + 1.0f);
    int base = tid * PER;
    int loc[PER];
    int s = 0;
#pragma unroll
    for (int i = 0; i < PER; i++) {
        int idx = base + i;
        int v = (idx < NN) ? g_cnt[idx] : 0;
        loc[i] = s; s += v;
    }
    sh[tid] = s; __syncthreads();
    for (int off = 1; off < TPB; off <<= 1) {
        int v = (tid >= off) ? sh[tid - off] : 0;
        __syncthreads();
        sh[tid] += v;
        __syncthreads();
    }
    int excl = (tid == 0) ? 0 : sh[tid - 1];
#pragma unroll
    for (int i = 0; i < PER; i++) {
        int idx = base + i;
        if (idx <= NN) g_rowptr[idx] = excl + loc[i];
    }
    __syncthreads();
    for (int i = tid; i < NN; i += TPB) g_cursor[i] = g_rowptr[i];
}

// gate-interleave permutation: plane row j -> torch row
__device__ __forceinline__ int gate_perm(int j) {
    return ((j >> 3) & 3) * 64 + (j >> 5) * 8 + (j & 7);
}

#define FILL_BLOCKS ((EE + 255) / 256)
#define PREP_BLOCKS ((PREP_ELEMS + 255) / 256)
#define XCONV_BLOCKS ((MROWS * FIN) / (256 * 4))   // 2500
__global__ void k_fillprep(const int* __restrict__ src, const int* __restrict__ dst,
                           const float* __restrict__ xin,
                           const float* __restrict__ wg0, const float* __restrict__ wg1,
                           const float* __restrict__ wg2,
                           const float* __restrict__ wih0, const float* __restrict__ wih1,
                           const float* __restrict__ wih2,
                           const float* __restrict__ whh0, const float* __restrict__ whh1,
                           const float* __restrict__ whh2,
                           const float* __restrict__ bih0, const float* __restrict__ bhh0,
                           const float* __restrict__ bih1, const float* __restrict__ bhh1,
                           const float* __restrict__ bih2, const float* __restrict__ bhh2) {
    int b = blockIdx.x;
    int tid = threadIdx.x;
    if (b < FILL_BLOCKS) {
        int e = b * 256 + tid;
        if (e < EE) {
            int s = src[e], d = dst[e];
            int p = atomicAdd(&g_cursor[d], 1);
            g_csr_src[p]  = s;
            g_csr_coef[p] = g_dis[s] * g_dis[d];
        }
        return;
    }
    if (b < FILL_BLOCKS + PREP_BLOCKS) {
        int idx = (b - FILL_BLOCKS) * 256 + tid;
        if (idx >= PREP_ELEMS) return;
        if (idx < WTOT) {
            float v;
            if (idx < WO1)       { int r = idx - WO0; v = wg0[(r & 31)  * HID + (r >> 5)]; }
            else if (idx < WO2)  { int r = idx - WO1; v = wg1[(r & 127) * HID + (r >> 7)]; }
            else if (idx < WO3)  { int r = idx - WO2; v = wg2[(r & 127) * HID + (r >> 7)]; }
            else if (idx < WO4)  { int l = idx - WO3; v = wih0[gate_perm(l >> 7) * 128 + (l & 127)]; }
            else if (idx < WO5)  { int l = idx - WO4; v = wih1[gate_perm(l >> 6) * 64 + (l & 63)]; }
            else if (idx < WH0)  { int l = idx - WO5; v = wih2[gate_perm(l >> 6) * 64 + (l & 63)]; }
            else if (idx < WH1)  { int l = idx - WH0; v = whh0[gate_perm(l >> 6) * 64 + (l & 63)]; }
            else if (idx < WH2)  { int l = idx - WH1; v = whh1[gate_perm(l >> 6) * 64 + (l & 63)]; }
            else                 { int l = idx - WH2; v = whh2[gate_perm(l >> 6) * 64 + (l & 63)]; }
            g_wH[idx] = __float2half_rn(v);
        } else {
            int r = idx - WTOT;
            int l = r >> 8, j = r & 255;
            int orig = gate_perm(j);
            const float* a = (l == 0) ? bih0 : (l == 1) ? bih1 : bih2;
            const float* c = (l == 0) ? bhh0 : (l == 1) ? bhh1 : bhh2;
            g_biasc[r] = a[orig] + c[orig];
        }
        return;
    }
    // x -> fp16 conversion: 4 floats per thread
    int idx = (b - FILL_BLOCKS - PREP_BLOCKS) * 256 + tid;
    int base = idx * 4;
    if (base < MROWS * FIN) {
        float4 v = *(const float4*)(xin + base);
        uint2 o = make_uint2(pack_h2(v.x, v.y), pack_h2(v.z, v.w));
        *(uint2*)(g_xH + base) = o;
    }
}

// ===================== GCN aggregation =====================
// layer 0: fp16 x gather -> fp16 out (F=32)
__global__ void k_agg32(const __half* __restrict__ in, __half* __restrict__ oH) {
    int n = blockIdx.x;
    int t = threadIdx.x >> 5;
    int lane = threadIdx.x & 31;
    int p0 = g_rowptr[n], p1 = g_rowptr[n + 1];
    float d = g_dis[n];
    float sw = d * d;
    size_t m = (size_t)t * NN + n;
    float acc = 0.0f;
    for (int p = p0; p < p1; p++) {
        int s = g_csr_src[p];
        acc += __half2float(in[((size_t)t * NN + s) * FIN + lane]) * g_csr_coef[p];
    }
    float r = acc + __half2float(in[m * FIN + lane]) * sw;
    oH[m * FIN + lane] = __float2half_rn(r);
}

// layers 1/2: fp16 input gather -> fp16 out
__global__ void k_aggh(const __half* __restrict__ in, __half* __restrict__ oH) {
    int n = blockIdx.x;
    int t = threadIdx.x >> 5;
    int lane = threadIdx.x & 31;
    int p0 = g_rowptr[n], p1 = g_rowptr[n + 1];
    float d = g_dis[n];
    float sw = d * d;
    size_t m = (size_t)t * NN + n;
    int c0 = lane * 4;
    float acc0 = 0.f, acc1 = 0.f, acc2 = 0.f, acc3 = 0.f;
    for (int p = p0; p < p1; p++) {
        int s = g_csr_src[p];
        float cf = g_csr_coef[p];
        uint2 v = *(const uint2*)(in + ((size_t)t * NN + s) * HID + c0);
        float2 a = __half22float2(*(__half2*)&v.x);
        float2 b = __half22float2(*(__half2*)&v.y);
        acc0 += a.x * cf; acc1 += a.y * cf;
        acc2 += b.x * cf; acc3 += b.y * cf;
    }
    uint2 hv = *(const uint2*)(in + m * HID + c0);
    float2 ha = __half22float2(*(__half2*)&hv.x);
    float2 hb = __half22float2(*(__half2*)&hv.y);
    acc0 += ha.x * sw; acc1 += ha.y * sw;
    acc2 += hb.x * sw; acc3 += hb.y * sw;
    uint2 o = make_uint2(pack_h2(acc0, acc1), pack_h2(acc2, acc3));
    *(uint2*)(oH + m * HID + c0) = o;
}

// ===================== mma.sync fp16 GEMM (double-buffered, 2 CTA/SM) =======
// C = A @ W^T. A: fp16 [M][K]; W: fp16 [Nout][K]. Single MMA pass.
// mode: 0 = +bias ; 1 = relu(.+bias) ; 2 = bn(relu(.+bias))
template <int K>
__global__ void __launch_bounds__(256, 2)
k_gemm_mma(const __half* __restrict__ A, const __half* __restrict__ W,
           const float* __restrict__ bias,
           const float* __restrict__ bng, const float* __restrict__ bnb,
           const float* __restrict__ bnm, const float* __restrict__ bnv,
           int mode, int Nout, __half* __restrict__ outH) {
    constexpr int KC   = 32;
    constexpr int NCH  = K / KC;
    constexpr int NBUF = (NCH > 1) ? 2 : 1;
    constexpr int P    = KC + 8;           // 40 halfs
    constexpr int P2   = P * 2;            // 80 bytes
    constexpr int S    = 128 * P2;         // 10240 per plane
    constexpr int BUF  = 2 * S;            // 20480 per buffer
    extern __shared__ char sm[];
    uint32_t sA = smem_u32(sm);

    int tid = threadIdx.x, wid = tid >> 5, lane = tid & 31;
    int wm = wid & 1, wn = wid >> 1;
    int mBase = blockIdx.x * 128;
    int jBase = blockIdx.y * 128;

    float acc[4][4][4];
#pragma unroll
    for (int i = 0; i < 4; i++)
#pragma unroll
        for (int j = 0; j < 4; j++)
#pragma unroll
            for (int r = 0; r < 4; r++) acc[i][j][r] = 0.0f;

    uint32_t aOff = (uint32_t)((wm * 64 + (lane & 15)) * P2 + (lane >> 4) * 16);
    uint32_t bOff = (uint32_t)((wn * 32 + (lane & 7) + ((lane >> 4) << 3)) * P2 +
                               ((lane >> 3) & 1) * 16);

    auto stage = [&](int ch) {
        uint32_t b = sA + (uint32_t)(ch % NBUF) * BUF;
#pragma unroll
        for (int s2 = 0; s2 < 2; s2++) {
            int idx = tid + s2 * 256;
            int row = idx >> 2, c = idx & 3;
            uint32_t d = b + row * P2 + c * 16;
            size_t ga = (size_t)(mBase + row) * K + ch * KC + c * 8;
            size_t gw = (size_t)(jBase + row) * K + ch * KC + c * 8;
            cp16(d,     A + ga);
            cp16(d + S, W + gw);
        }
        cp_commit();
    };

    stage(0);
#pragma unroll
    for (int ch = 0; ch < NCH; ch++) {
        if (ch + 1 < NCH) { stage(ch + 1); cp_wait1(); } else { cp_wait0(); }
        __syncthreads();
        uint32_t b = sA + (uint32_t)(ch % NBUF) * BUF;
#pragma unroll
        for (int ks = 0; ks < KC / 16; ks++) {
            uint32_t ka = ks * 32;
            uint32_t bh[2][4];
#pragma unroll
            for (int j2 = 0; j2 < 2; j2++)
                ldsm_x4(bh[j2], b + S + bOff + j2 * (16 * P2) + ka);
#pragma unroll
            for (int i = 0; i < 4; i++) {
                uint32_t ah[4];
                ldsm_x4(ah, b + aOff + i * (16 * P2) + ka);
#pragma unroll
                for (int j = 0; j < 4; j++)
                    mma16816(acc[i][j], ah, &bh[j >> 1][(j & 1) * 2]);
            }
        }
        if (ch + 1 < NCH) __syncthreads();
    }

    float pb[4][2], psc[4][2], pmn[4][2], pbb[4][2];
#pragma unroll
    for (int j = 0; j < 4; j++) {
        int c = jBase + wn * 32 + j * 8 + (lane & 3) * 2;
#pragma unroll
        for (int q = 0; q < 2; q++) {
            pb[j][q] = bias ? bias[c + q] : 0.0f;
            if (mode == 2) {
                psc[j][q] = bng[c + q] * rsqrtf(bnv[c + q] + EPSBN);
                pmn[j][q] = bnm[c + q];
                pbb[j][q] = bnb[c + q];
            }
        }
    }
#pragma unroll
    for (int i = 0; i < 4; i++) {
        int r0 = mBase + wm * 64 + i * 16 + (lane >> 2);
#pragma unroll
        for (int j = 0; j < 4; j++) {
            int c = jBase + wn * 32 + j * 8 + (lane & 3) * 2;
            float v[4];
#pragma unroll
            for (int r = 0; r < 4; r++) {
                float x = acc[i][j][r] + pb[j][r & 1];
                if (mode >= 1) x = fmaxf(x, 0.0f);
                if (mode == 2) x = (x - pmn[j][r & 1]) * psc[j][r & 1] + pbb[j][r & 1];
                v[r] = x;
            }
            *(uint32_t*)(outH + (size_t)r0 * Nout + c)       = pack_h2(v[0], v[1]);
            *(uint32_t*)(outH + (size_t)(r0 + 8) * Nout + c) = pack_h2(v[2], v[3]);
        }
    }
}

// ===================== tensor-core LSTM (gate-interleaved, fp16) ============
// Block = 64 nodes, 8 warps. Whh: fp16 plane; h: fp16 plane. Single MMA pass.
#define LP2 144                 // 72 halfs pitch
#define S_WHH 0
#define S_H   36864
#define LSTM_MMA_SMEM 46080

__global__ void __launch_bounds__(256, 2)
k_lstm_mma(const __half* __restrict__ pre, const __half* __restrict__ whh,
           __half* __restrict__ yH, float* __restrict__ outFinal) {
    extern __shared__ char sm[];
    uint32_t sA = smem_u32(sm);
    int tid = threadIdx.x, wid = tid >> 5, lane = tid & 31;
    int wm = wid & 1, wn = wid >> 1;
    int nodeBase = blockIdx.x * 64;

    // load permuted whh plane (256 rows x 64 k)
    for (int idx = tid; idx < 2048; idx += 256) {
        int r = idx >> 3, c = idx & 7;
        cp16(sA + S_WHH + r * LP2 + c * 16, whh + r * 64 + c * 8);
    }
    for (int idx = tid; idx < 2304; idx += 256)
        ((uint32_t*)(sm + S_H))[idx] = 0;
    cp_commit(); cp_wait0();
    __syncthreads();

    uint32_t aOff = (uint32_t)((wm * 32 + (lane & 15)) * LP2 + (lane >> 4) * 16);
    uint32_t bOff = (uint32_t)((wn * 64 + (lane & 7) + ((lane >> 4) << 3)) * LP2 +
                               ((lane >> 3) & 1) * 16);
    float cst[16];
#pragma unroll
    for (int w = 0; w < 16; w++) cst[w] = 0.0f;

    for (int t = 0; t < T_STEPS; t++) {
        // ---- gates_acc = h @ Whh^T (fp16, single pass) ----
        float acc[2][8][4];
#pragma unroll
        for (int i = 0; i < 2; i++)
#pragma unroll
            for (int j = 0; j < 8; j++)
#pragma unroll
                for (int r = 0; r < 4; r++) acc[i][j][r] = 0.0f;

#pragma unroll
        for (int ks = 0; ks < 4; ks++) {
            uint32_t ka = ks * 32;
            uint32_t bh[4][4];
#pragma unroll
            for (int j2 = 0; j2 < 4; j2++)
                ldsm_x4(bh[j2], sA + S_WHH + bOff + j2 * (16 * LP2) + ka);
#pragma unroll
            for (int i = 0; i < 2; i++) {
                uint32_t ah[4];
                ldsm_x4(ah, sA + S_H + aOff + i * (16 * LP2) + ka);
#pragma unroll
                for (int j = 0; j < 8; j++)
                    mma16816(acc[i][j], ah, &bh[j >> 1][(j & 1) * 2]);
            }
        }
        __syncthreads();   // all warps done reading h plane

        // ---- gate nonlinearity (all 4 gates in-register) ----
#pragma unroll
        for (int i = 0; i < 2; i++) {
            int rbase = wm * 32 + i * 16 + (lane >> 2);
#pragma unroll
            for (int rr = 0; rr < 2; rr++) {
                int row = rbase + rr * 8;
                int n = nodeBase + row;
                bool valid = n < NN;
                const __half* pp = pre + ((size_t)t * NN + n) * G4;
#pragma unroll
                for (int gl = 0; gl < 2; gl++) {
                    int cb = wn * 64 + gl * 32 + (lane & 3) * 2;
                    float2 p0 = make_float2(0.f, 0.f), p1 = p0, p2 = p0, p3 = p0;
                    if (valid) {
                        p0 = __half22float2(*(const __half2*)(pp + cb));
                        p1 = __half22float2(*(const __half2*)(pp + cb + 8));
                        p2 = __half22float2(*(const __half2*)(pp + cb + 16));
                        p3 = __half22float2(*(const __half2*)(pp + cb + 24));
                    }
                    float hn2[2];
#pragma unroll
                    for (int vv = 0; vv < 2; vv++) {
                        int w = i * 8 + rr * 4 + gl * 2 + vv;
                        float gi = acc[i][gl * 4 + 0][rr * 2 + vv] + (vv ? p0.y : p0.x);
                        float gf = acc[i][gl * 4 + 1][rr * 2 + vv] + (vv ? p1.y : p1.x);
                        float gg = acc[i][gl * 4 + 2][rr * 2 + vv] + (vv ? p2.y : p2.x);
                        float go = acc[i][gl * 4 + 3][rr * 2 + vv] + (vv ? p3.y : p3.x);
                        float ig = sigmoidf_(gi);
                        float fg = sigmoidf_(gf);
                        float gt = tanhf_(gg);
                        float og = sigmoidf_(go);
                        float cn = fg * cst[w] + ig * gt;
                        cst[w] = cn;
                        hn2[vv] = og * tanhf_(cn);
                    }
                    int u = (wn * 2 + gl) * 8 + (lane & 3) * 2;   // even
                    uint32_t hi2 = pack_h2(hn2[0], hn2[1]);
                    *(uint32_t*)(sm + S_H + row * LP2 + u * 2) = hi2;
                    if (valid) {
                        if (yH) {
                            size_t o = ((size_t)t * NN + n) * OUTD + u;
                            *(uint32_t*)(yH + o) = hi2;
                        }
                        if (outFinal && t == T_STEPS - 1)
                            *(float2*)(outFinal + (size_t)n * OUTD + u) =
                                make_float2(hn2[0], hn2[1]);
                    }
                }
            }
        }
        __syncthreads();   // h writes visible before next step's MMA
    }
}

// ===================== host =====================
extern "C" void kernel_launch(void* const* d_in, const int* in_sizes, int n_in,
                              void* d_out, int out_size) {
    const float* x   = (const float*)d_in[0];
    const int*   ei  = (const int*)d_in[1];
    const int*   src = ei;
    const int*   dst = ei + EE;
    const float* wg[3] = {(const float*)d_in[2], (const float*)d_in[4], (const float*)d_in[6]};
    const float* bg[3] = {(const float*)d_in[3], (const float*)d_in[5], (const float*)d_in[7]};
    const float* bnG[2] = {(const float*)d_in[8],  (const float*)d_in[12]};
    const float* bnB[2] = {(const float*)d_in[9],  (const float*)d_in[13]};
    const float* bnM[2] = {(const float*)d_in[10], (const float*)d_in[14]};
    const float* bnV[2] = {(const float*)d_in[11], (const float*)d_in[15]};
    const float* wih[3] = {(const float*)d_in[16], (const float*)d_in[20], (const float*)d_in[24]};
    const float* whh[3] = {(const float*)d_in[17], (const float*)d_in[21], (const float*)d_in[25]};
    const float* bih[3] = {(const float*)d_in[18], (const float*)d_in[22], (const float*)d_in[26]};
    const float* bhh[3] = {(const float*)d_in[19], (const float*)d_in[23], (const float*)d_in[27]};
    float* out = (float*)d_out;

    float* p_bias;
    __half *p_preH, *p_xH, *p_actA, *p_actB, *p_yA, *p_yB, *p_wH;
    cudaGetSymbolAddress((void**)&p_preH, g_preH);
    cudaGetSymbolAddress((void**)&p_xH,   g_xH);
    cudaGetSymbolAddress((void**)&p_bias, g_biasc);
    cudaGetSymbolAddress((void**)&p_actA, g_actA);
    cudaGetSymbolAddress((void**)&p_actB, g_actB);
    cudaGetSymbolAddress((void**)&p_yA,   g_yA);
    cudaGetSymbolAddress((void**)&p_yB,   g_yB);
    cudaGetSymbolAddress((void**)&p_wH,   g_wH);

    const int SM1 = 20480;   // K=32: single buffer (2 planes)
    const int SM2 = 40960;   // K=64/128: double buffer
    cudaFuncSetAttribute(k_gemm_mma<32>,  cudaFuncAttributeMaxDynamicSharedMemorySize, SM1);
    cudaFuncSetAttribute(k_gemm_mma<64>,  cudaFuncAttributeMaxDynamicSharedMemorySize, SM2);
    cudaFuncSetAttribute(k_gemm_mma<128>, cudaFuncAttributeMaxDynamicSharedMemorySize, SM2);
    cudaFuncSetAttribute(k_lstm_mma, cudaFuncAttributeMaxDynamicSharedMemorySize, LSTM_MMA_SMEM);

    // ---- setup ----
    k_zero_cnt<<<(NN + 255) / 256, 256>>>();
    k_hist<<<(EE + 255) / 256, 256>>>(dst);
    k_scanfused<<<1, 1024>>>();
    k_fillprep<<<FILL_BLOCKS + PREP_BLOCKS + XCONV_BLOCKS, 256>>>(
        src, dst, x, wg[0], wg[1], wg[2], wih[0], wih[1], wih[2],
        whh[0], whh[1], whh[2],
        bih[0], bhh[0], bih[1], bhh[1], bih[2], bhh[2]);

    const int MT = MROWS / 128;  // 625 M tiles

    // ---- GCN 0 ----
    k_agg32<<<NN, 256>>>(p_xH, p_actA);
    k_gemm_mma<32><<<dim3(MT, 1), 256, SM1>>>(
        p_actA, p_wH + WO0, bg[0],
        bnG[0], bnB[0], bnM[0], bnV[0], 2, HID, p_actB);
    // ---- GCN 1 ----
    k_aggh<<<NN, 256>>>(p_actB, p_actA);
    k_gemm_mma<128><<<dim3(MT, 1), 256, SM2>>>(
        p_actA, p_wH + WO1, bg[1],
        bnG[1], bnB[1], bnM[1], bnV[1], 2, HID, p_actB);
    // ---- GCN 2 (relu only) ----
    k_aggh<<<NN, 256>>>(p_actB, p_actA);
    k_gemm_mma<128><<<dim3(MT, 1), 256, SM2>>>(
        p_actA, p_wH + WO2, bg[2],
        nullptr, nullptr, nullptr, nullptr, 1, HID, p_actB);

    int lstmBlocks = (NN + 63) / 64;  // 157
    // ---- LSTM layer 0 ----
    k_gemm_mma<128><<<dim3(MT, 2), 256, SM2>>>(
        p_actB, p_wH + WO3, p_bias + 0 * G4,
        nullptr, nullptr, nullptr, nullptr, 0, G4, p_preH);
    k_lstm_mma<<<lstmBlocks, 256, LSTM_MMA_SMEM>>>(
        p_preH, p_wH + WH0, p_yA, nullptr);
    // ---- LSTM layer 1 ----
    k_gemm_mma<64><<<dim3(MT, 2), 256, SM2>>>(
        p_yA, p_wH + WO4, p_bias + 1 * G4,
        nullptr, nullptr, nullptr, nullptr, 0, G4, p_preH);
    k_lstm_mma<<<lstmBlocks, 256, LSTM_MMA_SMEM>>>(
        p_preH, p_wH + WH1, p_yB, nullptr);
    // ---- LSTM layer 2 ----
    k_gemm_mma<64><<<dim3(MT, 2), 256, SM2>>>(
        p_yB, p_wH + WO5, p_bias + 2 * G4,
        nullptr, nullptr, nullptr, nullptr, 0, G4, p_preH);
    k_lstm_mma<<<lstmBlocks, 256, LSTM_MMA_SMEM>>>(
        p_preH, p_wH + WH2, nullptr, out);
}

// round 12
// speedup vs baseline: 1.9246x; 1.1320x over previous
#include <cuda_runtime.h>
#include <cuda_fp16.h>
#include <math.h>
#include <stdint.h>

#define T_STEPS 8
#define NN      10000
#define EE      200000
#define FIN     32
#define HID     128
#define OUTD    64
#define G4      256            // 4*OUT
#define MROWS   (T_STEPS*NN)   // 80000
#define EPSBN   1e-5f

// weight-plane offsets ([n][k] fp16 layout, packed)
// LSTM planes (WO3.., WH..) use gate-interleaved row permutation:
//   plane row j = g*32 + q*8 + v  <->  torch row = q*64 + g*8 + v
#define WO0 0            // wg0^T   128x32
#define WO1 4096         // wg1^T   128x128
#define WO2 20480        // wg2^T   128x128
#define WO3 36864        // w_ih0   256x128 (perm)
#define WO4 69632        // w_ih1   256x64  (perm)
#define WO5 86016        // w_ih2   256x64  (perm)
#define WH0 102400       // whh0    256x64  (perm)
#define WH1 118784       // whh1    256x64  (perm)
#define WH2 135168       // whh2    256x64  (perm)
#define WTOT 151552
#define PREP_ELEMS (WTOT + 768)

// ===================== scratch (device globals) =====================
static __device__ __half g_preH[MROWS*G4];     // LSTM0 input projections (fp16, permuted)
static __device__ __half g_xH  [MROWS*FIN];    // x converted to fp16
static __device__ __half g_actA[MROWS*HID];    // ping (agg out)
static __device__ __half g_actB[MROWS*HID];    // pong (GCN out)
static __device__ __half g_yA[MROWS*OUTD];
static __device__ __half g_yB[MROWS*OUTD];
static __device__ __half g_wH[WTOT];
static __device__ float g_biasc[3*G4];         // permuted
static __device__ float g_dis[NN];
static __device__ int   g_cnt[NN];
static __device__ int   g_rowptr[NN+1];
static __device__ int   g_cursor[NN];
static __device__ int   g_csr_src[EE];
static __device__ float g_csr_coef[EE];

// ===================== helpers =====================
__device__ __forceinline__ uint32_t smem_u32(const void* p) {
    uint32_t a;
    asm("{ .reg .u64 t; cvta.to.shared.u64 t, %1; cvt.u32.u64 %0, t; }" : "=r"(a) : "l"(p));
    return a;
}
__device__ __forceinline__ void cp16(uint32_t s, const void* g) {
    asm volatile("cp.async.cg.shared.global [%0], [%1], 16;" :: "r"(s), "l"(g));
}
__device__ __forceinline__ void cp_commit() {
    asm volatile("cp.async.commit_group;");
}
__device__ __forceinline__ void cp_wait0() {
    asm volatile("cp.async.wait_group 0;");
}
__device__ __forceinline__ void cp_wait1() {
    asm volatile("cp.async.wait_group 1;");
}
__device__ __forceinline__ void ldsm_x4(uint32_t* r, uint32_t addr) {
    asm volatile("ldmatrix.sync.aligned.m8n8.x4.shared.b16 {%0,%1,%2,%3}, [%4];"
                 : "=r"(r[0]), "=r"(r[1]), "=r"(r[2]), "=r"(r[3]) : "r"(addr));
}
__device__ __forceinline__ void mma16816(float* d, const uint32_t* a, const uint32_t* b) {
    asm volatile(
        "mma.sync.aligned.m16n8k16.row.col.f32.f16.f16.f32 "
        "{%0,%1,%2,%3}, {%4,%5,%6,%7}, {%8,%9}, {%0,%1,%2,%3};"
        : "+f"(d[0]), "+f"(d[1]), "+f"(d[2]), "+f"(d[3])
        : "r"(a[0]), "r"(a[1]), "r"(a[2]), "r"(a[3]), "r"(b[0]), "r"(b[1]));
}
__device__ __forceinline__ uint32_t pack_h2(float x, float y) {
    __half2 h = __floats2half2_rn(x, y);
    return *(uint32_t*)&h;
}
__device__ __forceinline__ float sigmoidf_(float x) {
    return 1.0f / (1.0f + __expf(-x));
}
__device__ __forceinline__ float tanhf_(float x) {
    return 1.0f - 2.0f / (__expf(2.0f * x) + 1.0f);
}

// ===================== setup kernels =====================
__global__ void k_zero_cnt() {
    int i = blockIdx.x * blockDim.x + threadIdx.x;
    if (i < NN) g_cnt[i] = 0;
}
__global__ void k_hist(const int* __restrict__ dst) {
    int e = blockIdx.x * blockDim.x + threadIdx.x;
    if (e < EE) atomicAdd(&g_cnt[dst[e]], 1);
}
__global__ void k_scanfused() {
    const int TPB = 1024, PER = 10;
    __shared__ int sh[TPB];
    int tid = threadIdx.x;
    for (int i = tid; i < NN; i += TPB) g_dis[i] = rsqrtf((float)g_cnt[i] + 1.0f);
    int base = tid * PER;
    int loc[PER];
    int s = 0;
#pragma unroll
    for (int i = 0; i < PER; i++) {
        int idx = base + i;
        int v = (idx < NN) ? g_cnt[idx] : 0;
        loc[i] = s; s += v;
    }
    sh[tid] = s; __syncthreads();
    for (int off = 1; off < TPB; off <<= 1) {
        int v = (tid >= off) ? sh[tid - off] : 0;
        __syncthreads();
        sh[tid] += v;
        __syncthreads();
    }
    int excl = (tid == 0) ? 0 : sh[tid - 1];
#pragma unroll
    for (int i = 0; i < PER; i++) {
        int idx = base + i;
        if (idx <= NN) g_rowptr[idx] = excl + loc[i];
    }
    __syncthreads();
    for (int i = tid; i < NN; i += TPB) g_cursor[i] = g_rowptr[i];
}

// gate-interleave permutation: plane row j -> torch row
__device__ __forceinline__ int gate_perm(int j) {
    return ((j >> 3) & 3) * 64 + (j >> 5) * 8 + (j & 7);
}

#define FILL_BLOCKS ((EE + 255) / 256)
#define PREP_BLOCKS ((PREP_ELEMS + 255) / 256)
#define XCONV_BLOCKS ((MROWS * FIN) / (256 * 4))   // 2500
__global__ void k_fillprep(const int* __restrict__ src, const int* __restrict__ dst,
                           const float* __restrict__ xin,
                           const float* __restrict__ wg0, const float* __restrict__ wg1,
                           const float* __restrict__ wg2,
                           const float* __restrict__ wih0, const float* __restrict__ wih1,
                           const float* __restrict__ wih2,
                           const float* __restrict__ whh0, const float* __restrict__ whh1,
                           const float* __restrict__ whh2,
                           const float* __restrict__ bih0, const float* __restrict__ bhh0,
                           const float* __restrict__ bih1, const float* __restrict__ bhh1,
                           const float* __restrict__ bih2, const float* __restrict__ bhh2) {
    int b = blockIdx.x;
    int tid = threadIdx.x;
    if (b < FILL_BLOCKS) {
        int e = b * 256 + tid;
        if (e < EE) {
            int s = src[e], d = dst[e];
            int p = atomicAdd(&g_cursor[d], 1);
            g_csr_src[p]  = s;
            g_csr_coef[p] = g_dis[s] * g_dis[d];
        }
        return;
    }
    if (b < FILL_BLOCKS + PREP_BLOCKS) {
        int idx = (b - FILL_BLOCKS) * 256 + tid;
        if (idx >= PREP_ELEMS) return;
        if (idx < WTOT) {
            float v;
            if (idx < WO1)       { int r = idx - WO0; v = wg0[(r & 31)  * HID + (r >> 5)]; }
            else if (idx < WO2)  { int r = idx - WO1; v = wg1[(r & 127) * HID + (r >> 7)]; }
            else if (idx < WO3)  { int r = idx - WO2; v = wg2[(r & 127) * HID + (r >> 7)]; }
            else if (idx < WO4)  { int l = idx - WO3; v = wih0[gate_perm(l >> 7) * 128 + (l & 127)]; }
            else if (idx < WO5)  { int l = idx - WO4; v = wih1[gate_perm(l >> 6) * 64 + (l & 63)]; }
            else if (idx < WH0)  { int l = idx - WO5; v = wih2[gate_perm(l >> 6) * 64 + (l & 63)]; }
            else if (idx < WH1)  { int l = idx - WH0; v = whh0[gate_perm(l >> 6) * 64 + (l & 63)]; }
            else if (idx < WH2)  { int l = idx - WH1; v = whh1[gate_perm(l >> 6) * 64 + (l & 63)]; }
            else                 { int l = idx - WH2; v = whh2[gate_perm(l >> 6) * 64 + (l & 63)]; }
            g_wH[idx] = __float2half_rn(v);
        } else {
            int r = idx - WTOT;
            int l = r >> 8, j = r & 255;
            int orig = gate_perm(j);
            const float* a = (l == 0) ? bih0 : (l == 1) ? bih1 : bih2;
            const float* c = (l == 0) ? bhh0 : (l == 1) ? bhh1 : bhh2;
            g_biasc[r] = a[orig] + c[orig];
        }
        return;
    }
    // x -> fp16 conversion: 4 floats per thread
    int idx = (b - FILL_BLOCKS - PREP_BLOCKS) * 256 + tid;
    int base = idx * 4;
    if (base < MROWS * FIN) {
        float4 v = *(const float4*)(xin + base);
        uint2 o = make_uint2(pack_h2(v.x, v.y), pack_h2(v.z, v.w));
        *(uint2*)(g_xH + base) = o;
    }
}

// ===================== GCN aggregation =====================
__global__ void k_agg32(const __half* __restrict__ in, __half* __restrict__ oH) {
    int n = blockIdx.x;
    int t = threadIdx.x >> 5;
    int lane = threadIdx.x & 31;
    int p0 = g_rowptr[n], p1 = g_rowptr[n + 1];
    float d = g_dis[n];
    float sw = d * d;
    size_t m = (size_t)t * NN + n;
    float acc = 0.0f;
    for (int p = p0; p < p1; p++) {
        int s = g_csr_src[p];
        acc += __half2float(in[((size_t)t * NN + s) * FIN + lane]) * g_csr_coef[p];
    }
    float r = acc + __half2float(in[m * FIN + lane]) * sw;
    oH[m * FIN + lane] = __float2half_rn(r);
}

__global__ void k_aggh(const __half* __restrict__ in, __half* __restrict__ oH) {
    int n = blockIdx.x;
    int t = threadIdx.x >> 5;
    int lane = threadIdx.x & 31;
    int p0 = g_rowptr[n], p1 = g_rowptr[n + 1];
    float d = g_dis[n];
    float sw = d * d;
    size_t m = (size_t)t * NN + n;
    int c0 = lane * 4;
    float acc0 = 0.f, acc1 = 0.f, acc2 = 0.f, acc3 = 0.f;
    for (int p = p0; p < p1; p++) {
        int s = g_csr_src[p];
        float cf = g_csr_coef[p];
        uint2 v = *(const uint2*)(in + ((size_t)t * NN + s) * HID + c0);
        float2 a = __half22float2(*(__half2*)&v.x);
        float2 b = __half22float2(*(__half2*)&v.y);
        acc0 += a.x * cf; acc1 += a.y * cf;
        acc2 += b.x * cf; acc3 += b.y * cf;
    }
    uint2 hv = *(const uint2*)(in + m * HID + c0);
    float2 ha = __half22float2(*(__half2*)&hv.x);
    float2 hb = __half22float2(*(__half2*)&hv.y);
    acc0 += ha.x * sw; acc1 += ha.y * sw;
    acc2 += hb.x * sw; acc3 += hb.y * sw;
    uint2 o = make_uint2(pack_h2(acc0, acc1), pack_h2(acc2, acc3));
    *(uint2*)(oH + m * HID + c0) = o;
}

// ===================== mma.sync fp16 GEMM (double-buffered, 2 CTA/SM) =======
// C = A @ W^T. A: fp16 [M][K]; W: fp16 [Nout][K]. Single MMA pass.
// mode: 0 = +bias ; 1 = relu(.+bias) ; 2 = bn(relu(.+bias))
template <int K>
__global__ void __launch_bounds__(256, 2)
k_gemm_mma(const __half* __restrict__ A, const __half* __restrict__ W,
           const float* __restrict__ bias,
           const float* __restrict__ bng, const float* __restrict__ bnb,
           const float* __restrict__ bnm, const float* __restrict__ bnv,
           int mode, int Nout, __half* __restrict__ outH) {
    constexpr int KC   = 32;
    constexpr int NCH  = K / KC;
    constexpr int NBUF = (NCH > 1) ? 2 : 1;
    constexpr int P    = KC + 8;           // 40 halfs
    constexpr int P2   = P * 2;            // 80 bytes
    constexpr int S    = 128 * P2;         // 10240 per plane
    constexpr int BUF  = 2 * S;            // 20480 per buffer
    extern __shared__ char sm[];
    uint32_t sA = smem_u32(sm);

    int tid = threadIdx.x, wid = tid >> 5, lane = tid & 31;
    int wm = wid & 1, wn = wid >> 1;
    int mBase = blockIdx.x * 128;
    int jBase = blockIdx.y * 128;

    float acc[4][4][4];
#pragma unroll
    for (int i = 0; i < 4; i++)
#pragma unroll
        for (int j = 0; j < 4; j++)
#pragma unroll
            for (int r = 0; r < 4; r++) acc[i][j][r] = 0.0f;

    uint32_t aOff = (uint32_t)((wm * 64 + (lane & 15)) * P2 + (lane >> 4) * 16);
    uint32_t bOff = (uint32_t)((wn * 32 + (lane & 7) + ((lane >> 4) << 3)) * P2 +
                               ((lane >> 3) & 1) * 16);

    auto stage = [&](int ch) {
        uint32_t b = sA + (uint32_t)(ch % NBUF) * BUF;
#pragma unroll
        for (int s2 = 0; s2 < 2; s2++) {
            int idx = tid + s2 * 256;
            int row = idx >> 2, c = idx & 3;
            uint32_t d = b + row * P2 + c * 16;
            size_t ga = (size_t)(mBase + row) * K + ch * KC + c * 8;
            size_t gw = (size_t)(jBase + row) * K + ch * KC + c * 8;
            cp16(d,     A + ga);
            cp16(d + S, W + gw);
        }
        cp_commit();
    };

    stage(0);
#pragma unroll
    for (int ch = 0; ch < NCH; ch++) {
        if (ch + 1 < NCH) { stage(ch + 1); cp_wait1(); } else { cp_wait0(); }
        __syncthreads();
        uint32_t b = sA + (uint32_t)(ch % NBUF) * BUF;
#pragma unroll
        for (int ks = 0; ks < KC / 16; ks++) {
            uint32_t ka = ks * 32;
            uint32_t bh[2][4];
#pragma unroll
            for (int j2 = 0; j2 < 2; j2++)
                ldsm_x4(bh[j2], b + S + bOff + j2 * (16 * P2) + ka);
#pragma unroll
            for (int i = 0; i < 4; i++) {
                uint32_t ah[4];
                ldsm_x4(ah, b + aOff + i * (16 * P2) + ka);
#pragma unroll
                for (int j = 0; j < 4; j++)
                    mma16816(acc[i][j], ah, &bh[j >> 1][(j & 1) * 2]);
            }
        }
        if (ch + 1 < NCH) __syncthreads();
    }

    float pb[4][2], psc[4][2], pmn[4][2], pbb[4][2];
#pragma unroll
    for (int j = 0; j < 4; j++) {
        int c = jBase + wn * 32 + j * 8 + (lane & 3) * 2;
#pragma unroll
        for (int q = 0; q < 2; q++) {
            pb[j][q] = bias ? bias[c + q] : 0.0f;
            if (mode == 2) {
                psc[j][q] = bng[c + q] * rsqrtf(bnv[c + q] + EPSBN);
                pmn[j][q] = bnm[c + q];
                pbb[j][q] = bnb[c + q];
            }
        }
    }
#pragma unroll
    for (int i = 0; i < 4; i++) {
        int r0 = mBase + wm * 64 + i * 16 + (lane >> 2);
#pragma unroll
        for (int j = 0; j < 4; j++) {
            int c = jBase + wn * 32 + j * 8 + (lane & 3) * 2;
            float v[4];
#pragma unroll
            for (int r = 0; r < 4; r++) {
                float x = acc[i][j][r] + pb[j][r & 1];
                if (mode >= 1) x = fmaxf(x, 0.0f);
                if (mode == 2) x = (x - pmn[j][r & 1]) * psc[j][r & 1] + pbb[j][r & 1];
                v[r] = x;
            }
            *(uint32_t*)(outH + (size_t)r0 * Nout + c)       = pack_h2(v[0], v[1]);
            *(uint32_t*)(outH + (size_t)(r0 + 8) * Nout + c) = pack_h2(v[2], v[3]);
        }
    }
}

// ===================== tensor-core LSTM layer 0 (pre from GEMM) =============
#define LP2 144                 // 72 halfs pitch
#define S_WHH 0
#define S_H   36864
#define LSTM_MMA_SMEM 46080

__global__ void __launch_bounds__(256, 2)
k_lstm_mma(const __half* __restrict__ pre, const __half* __restrict__ whh,
           __half* __restrict__ yH) {
    extern __shared__ char sm[];
    uint32_t sA = smem_u32(sm);
    int tid = threadIdx.x, wid = tid >> 5, lane = tid & 31;
    int wm = wid & 1, wn = wid >> 1;
    int nodeBase = blockIdx.x * 64;

    for (int idx = tid; idx < 2048; idx += 256) {
        int r = idx >> 3, c = idx & 7;
        cp16(sA + S_WHH + r * LP2 + c * 16, whh + r * 64 + c * 8);
    }
    for (int idx = tid; idx < 2304; idx += 256)
        ((uint32_t*)(sm + S_H))[idx] = 0;
    cp_commit(); cp_wait0();
    __syncthreads();

    uint32_t aOff = (uint32_t)((wm * 32 + (lane & 15)) * LP2 + (lane >> 4) * 16);
    uint32_t bOff = (uint32_t)((wn * 64 + (lane & 7) + ((lane >> 4) << 3)) * LP2 +
                               ((lane >> 3) & 1) * 16);
    float cst[16];
#pragma unroll
    for (int w = 0; w < 16; w++) cst[w] = 0.0f;

    for (int t = 0; t < T_STEPS; t++) {
        float acc[2][8][4];
#pragma unroll
        for (int i = 0; i < 2; i++)
#pragma unroll
            for (int j = 0; j < 8; j++)
#pragma unroll
                for (int r = 0; r < 4; r++) acc[i][j][r] = 0.0f;

#pragma unroll
        for (int ks = 0; ks < 4; ks++) {
            uint32_t ka = ks * 32;
            uint32_t bh[4][4];
#pragma unroll
            for (int j2 = 0; j2 < 4; j2++)
                ldsm_x4(bh[j2], sA + S_WHH + bOff + j2 * (16 * LP2) + ka);
#pragma unroll
            for (int i = 0; i < 2; i++) {
                uint32_t ah[4];
                ldsm_x4(ah, sA + S_H + aOff + i * (16 * LP2) + ka);
#pragma unroll
                for (int j = 0; j < 8; j++)
                    mma16816(acc[i][j], ah, &bh[j >> 1][(j & 1) * 2]);
            }
        }
        __syncthreads();

#pragma unroll
        for (int i = 0; i < 2; i++) {
            int rbase = wm * 32 + i * 16 + (lane >> 2);
#pragma unroll
            for (int rr = 0; rr < 2; rr++) {
                int row = rbase + rr * 8;
                int n = nodeBase + row;
                bool valid = n < NN;
                const __half* pp = pre + ((size_t)t * NN + n) * G4;
#pragma unroll
                for (int gl = 0; gl < 2; gl++) {
                    int cb = wn * 64 + gl * 32 + (lane & 3) * 2;
                    float2 p0 = make_float2(0.f, 0.f), p1 = p0, p2 = p0, p3 = p0;
                    if (valid) {
                        p0 = __half22float2(*(const __half2*)(pp + cb));
                        p1 = __half22float2(*(const __half2*)(pp + cb + 8));
                        p2 = __half22float2(*(const __half2*)(pp + cb + 16));
                        p3 = __half22float2(*(const __half2*)(pp + cb + 24));
                    }
                    float hn2[2];
#pragma unroll
                    for (int vv = 0; vv < 2; vv++) {
                        int w = i * 8 + rr * 4 + gl * 2 + vv;
                        float gi = acc[i][gl * 4 + 0][rr * 2 + vv] + (vv ? p0.y : p0.x);
                        float gf = acc[i][gl * 4 + 1][rr * 2 + vv] + (vv ? p1.y : p1.x);
                        float gg = acc[i][gl * 4 + 2][rr * 2 + vv] + (vv ? p2.y : p2.x);
                        float go = acc[i][gl * 4 + 3][rr * 2 + vv] + (vv ? p3.y : p3.x);
                        float ig = sigmoidf_(gi);
                        float fg = sigmoidf_(gf);
                        float gt = tanhf_(gg);
                        float og = sigmoidf_(go);
                        float cn = fg * cst[w] + ig * gt;
                        cst[w] = cn;
                        hn2[vv] = og * tanhf_(cn);
                    }
                    int u = (wn * 2 + gl) * 8 + (lane & 3) * 2;
                    uint32_t hi2 = pack_h2(hn2[0], hn2[1]);
                    *(uint32_t*)(sm + S_H + row * LP2 + u * 2) = hi2;
                    if (valid) {
                        size_t o = ((size_t)t * NN + n) * OUTD + u;
                        *(uint32_t*)(yH + o) = hi2;
                    }
                }
            }
        }
        __syncthreads();
    }
}

// ===================== fused LSTM layers 1/2 (input projection in-kernel) ===
// gates = x_t @ Wih^T + h @ Whh^T + bias (all fp16 MMA, fp32 accum).
// x_t tile (64 nodes x 64) cp.async double-buffered; Wih/Whh planes resident.
#define F_WIH  0
#define F_WHH  36864
#define F_H    73728            // 9216
#define F_X    82944            // 2 x 9216
#define F_BIAS 101376           // 1024
#define LSTM_FUSED_SMEM 102400

__global__ void __launch_bounds__(256, 2)
k_lstm_fused(const __half* __restrict__ xin,
             const __half* __restrict__ wih, const __half* __restrict__ whh,
             const float* __restrict__ bias,
             __half* __restrict__ yH, float* __restrict__ outFinal) {
    extern __shared__ char sm[];
    uint32_t sA = smem_u32(sm);
    int tid = threadIdx.x, wid = tid >> 5, lane = tid & 31;
    int wm = wid & 1, wn = wid >> 1;
    int nodeBase = blockIdx.x * 64;

    // weights + bias + zero h
    for (int idx = tid; idx < 2048; idx += 256) {
        int r = idx >> 3, c = idx & 7;
        cp16(sA + F_WIH + r * LP2 + c * 16, wih + r * 64 + c * 8);
        cp16(sA + F_WHH + r * LP2 + c * 16, whh + r * 64 + c * 8);
    }
    ((float*)(sm + F_BIAS))[tid] = bias[tid];
    for (int idx = tid; idx < 2304; idx += 256)
        ((uint32_t*)(sm + F_H))[idx] = 0;

    auto stage_x = [&](int t) {
        uint32_t b = sA + F_X + (uint32_t)(t & 1) * 9216;
#pragma unroll
        for (int s2 = 0; s2 < 2; s2++) {
            int idx = tid + s2 * 256;
            int r = idx >> 3, c = idx & 7;
            int n = nodeBase + r;
            if (n >= NN) n = NN - 1;           // clamp (result masked later)
            cp16(b + r * LP2 + c * 16, xin + ((size_t)t * NN + n) * OUTD + c * 8);
        }
    };
    stage_x(0);
    cp_commit();

    uint32_t aOff = (uint32_t)((wm * 32 + (lane & 15)) * LP2 + (lane >> 4) * 16);
    uint32_t bOff = (uint32_t)((wn * 64 + (lane & 7) + ((lane >> 4) << 3)) * LP2 +
                               ((lane >> 3) & 1) * 16);
    float cst[16];
#pragma unroll
    for (int w = 0; w < 16; w++) cst[w] = 0.0f;

    for (int t = 0; t < T_STEPS; t++) {
        if (t + 1 < T_STEPS) { stage_x(t + 1); cp_commit(); cp_wait1(); }
        else                 { cp_wait0(); }
        __syncthreads();   // x[t] ready; prev-step h writes visible

        float acc[2][8][4];
#pragma unroll
        for (int i = 0; i < 2; i++)
#pragma unroll
            for (int j = 0; j < 8; j++)
#pragma unroll
                for (int r = 0; r < 4; r++) acc[i][j][r] = 0.0f;

        // pass 1: x_t @ Wih^T
        uint32_t xb = sA + F_X + (uint32_t)(t & 1) * 9216;
#pragma unroll
        for (int ks = 0; ks < 4; ks++) {
            uint32_t ka = ks * 32;
            uint32_t bh[4][4];
#pragma unroll
            for (int j2 = 0; j2 < 4; j2++)
                ldsm_x4(bh[j2], sA + F_WIH + bOff + j2 * (16 * LP2) + ka);
#pragma unroll
            for (int i = 0; i < 2; i++) {
                uint32_t ah[4];
                ldsm_x4(ah, xb + aOff + i * (16 * LP2) + ka);
#pragma unroll
                for (int j = 0; j < 8; j++)
                    mma16816(acc[i][j], ah, &bh[j >> 1][(j & 1) * 2]);
            }
        }
        // pass 2: h @ Whh^T
#pragma unroll
        for (int ks = 0; ks < 4; ks++) {
            uint32_t ka = ks * 32;
            uint32_t bh[4][4];
#pragma unroll
            for (int j2 = 0; j2 < 4; j2++)
                ldsm_x4(bh[j2], sA + F_WHH + bOff + j2 * (16 * LP2) + ka);
#pragma unroll
            for (int i = 0; i < 2; i++) {
                uint32_t ah[4];
                ldsm_x4(ah, sA + F_H + aOff + i * (16 * LP2) + ka);
#pragma unroll
                for (int j = 0; j < 8; j++)
                    mma16816(acc[i][j], ah, &bh[j >> 1][(j & 1) * 2]);
            }
        }
        __syncthreads();   // all warps done reading h plane

        const float* bsm = (const float*)(sm + F_BIAS);
#pragma unroll
        for (int i = 0; i < 2; i++) {
            int rbase = wm * 32 + i * 16 + (lane >> 2);
#pragma unroll
            for (int rr = 0; rr < 2; rr++) {
                int row = rbase + rr * 8;
                int n = nodeBase + row;
                bool valid = n < NN;
#pragma unroll
                for (int gl = 0; gl < 2; gl++) {
                    int cb = wn * 64 + gl * 32 + (lane & 3) * 2;
                    float2 b0 = *(const float2*)(bsm + cb);
                    float2 b1 = *(const float2*)(bsm + cb + 8);
                    float2 b2 = *(const float2*)(bsm + cb + 16);
                    float2 b3 = *(const float2*)(bsm + cb + 24);
                    float hn2[2];
#pragma unroll
                    for (int vv = 0; vv < 2; vv++) {
                        int w = i * 8 + rr * 4 + gl * 2 + vv;
                        float gi = acc[i][gl * 4 + 0][rr * 2 + vv] + (vv ? b0.y : b0.x);
                        float gf = acc[i][gl * 4 + 1][rr * 2 + vv] + (vv ? b1.y : b1.x);
                        float gg = acc[i][gl * 4 + 2][rr * 2 + vv] + (vv ? b2.y : b2.x);
                        float go = acc[i][gl * 4 + 3][rr * 2 + vv] + (vv ? b3.y : b3.x);
                        float ig = sigmoidf_(gi);
                        float fg = sigmoidf_(gf);
                        float gt = tanhf_(gg);
                        float og = sigmoidf_(go);
                        float cn = fg * cst[w] + ig * gt;
                        cst[w] = cn;
                        hn2[vv] = og * tanhf_(cn);
                    }
                    int u = (wn * 2 + gl) * 8 + (lane & 3) * 2;
                    uint32_t hi2 = pack_h2(hn2[0], hn2[1]);
                    *(uint32_t*)(sm + F_H + row * LP2 + u * 2) = hi2;
                    if (valid) {
                        if (yH) {
                            size_t o = ((size_t)t * NN + n) * OUTD + u;
                            *(uint32_t*)(yH + o) = hi2;
                        }
                        if (outFinal && t == T_STEPS - 1)
                            *(float2*)(outFinal + (size_t)n * OUTD + u) =
                                make_float2(hn2[0], hn2[1]);
                    }
                }
            }
        }
        __syncthreads();
    }
}

// ===================== host =====================
extern "C" void kernel_launch(void* const* d_in, const int* in_sizes, int n_in,
                              void* d_out, int out_size) {
    const float* x   = (const float*)d_in[0];
    const int*   ei  = (const int*)d_in[1];
    const int*   src = ei;
    const int*   dst = ei + EE;
    const float* wg[3] = {(const float*)d_in[2], (const float*)d_in[4], (const float*)d_in[6]};
    const float* bg[3] = {(const float*)d_in[3], (const float*)d_in[5], (const float*)d_in[7]};
    const float* bnG[2] = {(const float*)d_in[8],  (const float*)d_in[12]};
    const float* bnB[2] = {(const float*)d_in[9],  (const float*)d_in[13]};
    const float* bnM[2] = {(const float*)d_in[10], (const float*)d_in[14]};
    const float* bnV[2] = {(const float*)d_in[11], (const float*)d_in[15]};
    const float* wih[3] = {(const float*)d_in[16], (const float*)d_in[20], (const float*)d_in[24]};
    const float* whh[3] = {(const float*)d_in[17], (const float*)d_in[21], (const float*)d_in[25]};
    const float* bih[3] = {(const float*)d_in[18], (const float*)d_in[22], (const float*)d_in[26]};
    const float* bhh[3] = {(const float*)d_in[19], (const float*)d_in[23], (const float*)d_in[27]};
    float* out = (float*)d_out;

    float* p_bias;
    __half *p_preH, *p_xH, *p_actA, *p_actB, *p_yA, *p_yB, *p_wH;
    cudaGetSymbolAddress((void**)&p_preH, g_preH);
    cudaGetSymbolAddress((void**)&p_xH,   g_xH);
    cudaGetSymbolAddress((void**)&p_bias, g_biasc);
    cudaGetSymbolAddress((void**)&p_actA, g_actA);
    cudaGetSymbolAddress((void**)&p_actB, g_actB);
    cudaGetSymbolAddress((void**)&p_yA,   g_yA);
    cudaGetSymbolAddress((void**)&p_yB,   g_yB);
    cudaGetSymbolAddress((void**)&p_wH,   g_wH);

    const int SM1 = 20480;   // K=32: single buffer (2 planes)
    const int SM2 = 40960;   // K=64/128: double buffer
    cudaFuncSetAttribute(k_gemm_mma<32>,  cudaFuncAttributeMaxDynamicSharedMemorySize, SM1);
    cudaFuncSetAttribute(k_gemm_mma<128>, cudaFuncAttributeMaxDynamicSharedMemorySize, SM2);
    cudaFuncSetAttribute(k_lstm_mma,   cudaFuncAttributeMaxDynamicSharedMemorySize, LSTM_MMA_SMEM);
    cudaFuncSetAttribute(k_lstm_fused, cudaFuncAttributeMaxDynamicSharedMemorySize, LSTM_FUSED_SMEM);

    // ---- setup ----
    k_zero_cnt<<<(NN + 255) / 256, 256>>>();
    k_hist<<<(EE + 255) / 256, 256>>>(dst);
    k_scanfused<<<1, 1024>>>();
    k_fillprep<<<FILL_BLOCKS + PREP_BLOCKS + XCONV_BLOCKS, 256>>>(
        src, dst, x, wg[0], wg[1], wg[2], wih[0], wih[1], wih[2],
        whh[0], whh[1], whh[2],
        bih[0], bhh[0], bih[1], bhh[1], bih[2], bhh[2]);

    const int MT = MROWS / 128;  // 625 M tiles

    // ---- GCN 0 ----
    k_agg32<<<NN, 256>>>(p_xH, p_actA);
    k_gemm_mma<32><<<dim3(MT, 1), 256, SM1>>>(
        p_actA, p_wH + WO0, bg[0],
        bnG[0], bnB[0], bnM[0], bnV[0], 2, HID, p_actB);
    // ---- GCN 1 ----
    k_aggh<<<NN, 256>>>(p_actB, p_actA);
    k_gemm_mma<128><<<dim3(MT, 1), 256, SM2>>>(
        p_actA, p_wH + WO1, bg[1],
        bnG[1], bnB[1], bnM[1], bnV[1], 2, HID, p_actB);
    // ---- GCN 2 (relu only) ----
    k_aggh<<<NN, 256>>>(p_actB, p_actA);
    k_gemm_mma<128><<<dim3(MT, 1), 256, SM2>>>(
        p_actA, p_wH + WO2, bg[2],
        nullptr, nullptr, nullptr, nullptr, 1, HID, p_actB);

    int lstmBlocks = (NN + 63) / 64;  // 157
    // ---- LSTM layer 0 (input GEMM + recurrence) ----
    k_gemm_mma<128><<<dim3(MT, 2), 256, SM2>>>(
        p_actB, p_wH + WO3, p_bias + 0 * G4,
        nullptr, nullptr, nullptr, nullptr, 0, G4, p_preH);
    k_lstm_mma<<<lstmBlocks, 256, LSTM_MMA_SMEM>>>(p_preH, p_wH + WH0, p_yA);
    // ---- LSTM layers 1 & 2 (fully fused) ----
    k_lstm_fused<<<lstmBlocks, 256, LSTM_FUSED_SMEM>>>(
        p_yA, p_wH + WO4, p_wH + WH1, p_bias + 1 * G4, p_yB, nullptr);
    k_lstm_fused<<<lstmBlocks, 256, LSTM_FUSED_SMEM>>>(
        p_yB, p_wH + WO5, p_wH + WH2, p_bias + 2 * G4, nullptr, out);
}